// round 4
// baseline (speedup 1.0000x reference)
#include <cuda_runtime.h>
#include <cstdint>
#include <math.h>

#define D_DIM   1024
#define N_BATCH 8
#define N_SEQ   4096
#define M_FLAT  (N_BATCH * N_SEQ)   // 32768

// GEMM tile config
#define BM 128
#define BN 128
#define BK 32
#define LDROW 136                       // smem row pitch in words (conflict-free)
#define STAGE_WORDS (BK * LDROW)        // one operand, one stage
#define SMEM_WORDS  (4 * STAGE_WORDS)   // A0,A1,B0,B1
#define SMEM_BYTES  (SMEM_WORDS * 4)    // 69632 B

// ---------------- scratch (device globals: no allocation allowed) ----------
__device__ float g_Q  [(size_t)M_FLAT * D_DIM];           // 134 MB
__device__ float g_Kf [(size_t)M_FLAT * D_DIM];           // feature-mapped K
__device__ float g_V  [(size_t)M_FLAT * D_DIM];
__device__ float g_KV [(size_t)N_BATCH * D_DIM * D_DIM];  // K^T V  [d,e]
__device__ float g_M  [(size_t)N_BATCH * D_DIM * D_DIM];  // KV @ Wo^T  [d,f]
__device__ float g_Ksum[N_BATCH * D_DIM];
__device__ float g_Z[M_FLAT];

// ---------------- helpers ----------------
__device__ __forceinline__ uint32_t f2tf32(float f) {
    uint32_t u;
    asm("cvt.rna.tf32.f32 %0, %1;" : "=r"(u) : "f"(f));
    return u;
}

__device__ __forceinline__ uint32_t smem_u32(const void* p) {
    uint32_t a;
    asm("{ .reg .u64 t; cvta.to.shared.u64 t, %1; cvt.u32.u64 %0, t; }" : "=r"(a) : "l"(p));
    return a;
}

#define CP_ASYNC16(dst, src) \
    asm volatile("cp.async.cg.shared.global [%0], [%1], 16;" :: "r"(dst), "l"(src) : "memory")
#define CP_COMMIT() asm volatile("cp.async.commit_group;" ::: "memory")
#define CP_WAIT0()  asm volatile("cp.async.wait_group 0;" ::: "memory")

__device__ __forceinline__ void mma8(float c[4], const uint32_t a[4], const uint32_t b[2]) {
    asm volatile(
        "mma.sync.aligned.m16n8k8.row.col.f32.tf32.tf32.f32 "
        "{%0,%1,%2,%3}, {%4,%5,%6,%7}, {%8,%9}, {%0,%1,%2,%3};\n"
        : "+f"(c[0]), "+f"(c[1]), "+f"(c[2]), "+f"(c[3])
        : "r"(a[0]), "r"(a[1]), "r"(a[2]), "r"(a[3]), "r"(b[0]), "r"(b[1]));
}

// ---------------- generic tf32 GEMM ----------------
// C[M,N] = epi( sum_k A[m,k] * B[k,n] )
// AT==0: A[m,k] = A[m*lda + k]  (reg-transpose path, RNA cvt)
// AT==1: A[m,k] = A[k*lda + m]  (cp.async path, truncation)
// BT==0: B[k,n] = B[n*ldb + k]  (reg-transpose path)
// BT==1: B[k,n] = B[k*ldb + n]  (cp.async path)
// EPI: 0 none | 1 +biasN | 2 elu(+biasN)+1 | 4 v/zM + biasN
template<int AT, int BT, int EPI>
__global__ void __launch_bounds__(256, 1)
gemm_tf32(const float* __restrict__ Ag, const float* __restrict__ Bg,
          float* __restrict__ Cg,
          const float* __restrict__ auxM, const float* __restrict__ auxN,
          int K, int lda, int ldb, int ldc,
          long sA, long sB, long sC, long sAuxM)
{
    extern __shared__ uint32_t sm[];
    const int bz = blockIdx.z;
    const float* A = Ag + (size_t)bz * sA;
    const float* B = Bg + (size_t)bz * sB;
    float*       C = Cg + (size_t)bz * sC;
    const float* axm = auxM + (size_t)bz * sAuxM;

    const int tid  = threadIdx.x;
    const int lane = tid & 31;
    const int warp = tid >> 5;
    const int g    = lane >> 2;
    const int t    = lane & 3;
    const int wm   = warp & 1;          // 2 (m) x 4 (n) warp grid
    const int wn   = warp >> 1;
    const int m0   = blockIdx.y * BM;
    const int n0   = blockIdx.x * BN;

    const uint32_t smem0 = smem_u32(sm);

    float acc[4][4][4];
    #pragma unroll
    for (int i = 0; i < 4; ++i)
        #pragma unroll
        for (int j = 0; j < 4; ++j)
            #pragma unroll
            for (int l = 0; l < 4; ++l) acc[i][j][l] = 0.f;

    // reg-transpose path ids: 32 consecutive rows per warp -> conflict-free STS
    const int rr = tid & 127;           // m (or n) row
    const int kh = tid >> 7;            // k half: 0 -> k 0..15, 1 -> k 16..31
    float4 ra[4], rb[4];

    auto ldgA = [&](int kt) {
        if (AT == 0) {
            const float* p = &A[(size_t)(m0 + rr) * lda + kt * BK + kh * 16];
            #pragma unroll
            for (int q = 0; q < 4; ++q) ra[q] = *reinterpret_cast<const float4*>(p + q * 4);
        }
    };
    auto ldgB = [&](int kt) {
        if (BT == 0) {
            const float* p = &B[(size_t)(n0 + rr) * ldb + kt * BK + kh * 16];
            #pragma unroll
            for (int q = 0; q < 4; ++q) rb[q] = *reinterpret_cast<const float4*>(p + q * 4);
        }
    };
    auto stsA = [&](int s) {
        if (AT == 0) {
            uint32_t* as = sm + s * STAGE_WORDS;
            #pragma unroll
            for (int q = 0; q < 4; ++q) {
                int k = kh * 16 + q * 4;
                as[(k + 0) * LDROW + rr] = f2tf32(ra[q].x);
                as[(k + 1) * LDROW + rr] = f2tf32(ra[q].y);
                as[(k + 2) * LDROW + rr] = f2tf32(ra[q].z);
                as[(k + 3) * LDROW + rr] = f2tf32(ra[q].w);
            }
        }
    };
    auto stsB = [&](int s) {
        if (BT == 0) {
            uint32_t* bs = sm + (2 + s) * STAGE_WORDS;
            #pragma unroll
            for (int q = 0; q < 4; ++q) {
                int k = kh * 16 + q * 4;
                bs[(k + 0) * LDROW + rr] = f2tf32(rb[q].x);
                bs[(k + 1) * LDROW + rr] = f2tf32(rb[q].y);
                bs[(k + 2) * LDROW + rr] = f2tf32(rb[q].z);
                bs[(k + 3) * LDROW + rr] = f2tf32(rb[q].w);
            }
        }
    };
    auto asyncA = [&](int s, int kt) {
        if (AT == 1) {
            int j = tid & 31, kq = tid >> 5;     // j: 16B chunk, kq: base k row
            #pragma unroll
            for (int i = 0; i < 4; ++i) {
                int k = kq + i * 8;
                uint32_t d = smem0 + (s * STAGE_WORDS + k * LDROW + j * 4) * 4;
                CP_ASYNC16(d, A + (size_t)(kt * BK + k) * lda + m0 + j * 4);
            }
        }
    };
    auto asyncB = [&](int s, int kt) {
        if (BT == 1) {
            int j = tid & 31, kq = tid >> 5;
            #pragma unroll
            for (int i = 0; i < 4; ++i) {
                int k = kq + i * 8;
                uint32_t d = smem0 + ((2 + s) * STAGE_WORDS + k * LDROW + j * 4) * 4;
                CP_ASYNC16(d, B + (size_t)(kt * BK + k) * ldb + n0 + j * 4);
            }
        }
    };

    auto compute = [&](int s) {
        const uint32_t* as = sm + s * STAGE_WORDS;
        const uint32_t* bs = sm + (2 + s) * STAGE_WORDS;
        #pragma unroll
        for (int ks = 0; ks < BK; ks += 8) {
            uint32_t af[4][4];
            uint32_t bf[4][2];
            #pragma unroll
            for (int mt = 0; mt < 4; ++mt) {
                int mr = wm * 64 + mt * 16;
                af[mt][0] = as[(ks + t    ) * LDROW + mr + g    ];
                af[mt][1] = as[(ks + t    ) * LDROW + mr + g + 8];
                af[mt][2] = as[(ks + t + 4) * LDROW + mr + g    ];
                af[mt][3] = as[(ks + t + 4) * LDROW + mr + g + 8];
            }
            #pragma unroll
            for (int nt = 0; nt < 4; ++nt) {
                int nc = wn * 32 + nt * 8;
                bf[nt][0] = bs[(ks + t    ) * LDROW + nc + g];
                bf[nt][1] = bs[(ks + t + 4) * LDROW + nc + g];
            }
            #pragma unroll
            for (int mt = 0; mt < 4; ++mt)
                #pragma unroll
                for (int nt = 0; nt < 4; ++nt)
                    mma8(acc[mt][nt], af[mt], bf[nt]);
        }
    };

    const int KT = K / BK;
    // prologue: fill stage 0
    ldgA(0); ldgB(0);
    asyncA(0, 0); asyncB(0, 0); CP_COMMIT();
    stsA(0); stsB(0);
    CP_WAIT0();
    __syncthreads();

    for (int kt = 0; kt < KT; ++kt) {
        int s = kt & 1;
        if (kt + 1 < KT) {
            ldgA(kt + 1); ldgB(kt + 1);
            asyncA(1 - s, kt + 1); asyncB(1 - s, kt + 1); CP_COMMIT();
        }
        compute(s);
        if (kt + 1 < KT) {
            stsA(1 - s); stsB(1 - s);
            CP_WAIT0();
            __syncthreads();
        }
    }

    // ---------------- epilogue ----------------
    #pragma unroll
    for (int mt = 0; mt < 4; ++mt) {
        int r0 = m0 + wm * 64 + mt * 16 + g;
        float z0 = 1.f, z1 = 1.f;
        if (EPI == 4) { z0 = 1.f / axm[r0]; z1 = 1.f / axm[r0 + 8]; }
        #pragma unroll
        for (int nt = 0; nt < 4; ++nt) {
            int c = n0 + wn * 32 + nt * 8 + t * 2;
            float v0 = acc[mt][nt][0], v1 = acc[mt][nt][1];
            float v2 = acc[mt][nt][2], v3 = acc[mt][nt][3];
            if (EPI == 1 || EPI == 2) {
                float b0 = auxN[c], b1 = auxN[c + 1];
                v0 += b0; v1 += b1; v2 += b0; v3 += b1;
            }
            if (EPI == 2) {   // elu(x)+1 : x>0 -> x+1 else exp(x)
                v0 = v0 > 0.f ? v0 + 1.f : expf(v0);
                v1 = v1 > 0.f ? v1 + 1.f : expf(v1);
                v2 = v2 > 0.f ? v2 + 1.f : expf(v2);
                v3 = v3 > 0.f ? v3 + 1.f : expf(v3);
            }
            if (EPI == 4) {   // v/z + bias
                float b0 = auxN[c], b1 = auxN[c + 1];
                v0 = v0 * z0 + b0; v1 = v1 * z0 + b1;
                v2 = v2 * z1 + b0; v3 = v3 * z1 + b1;
            }
            *reinterpret_cast<float2*>(&C[(size_t)r0       * ldc + c]) = make_float2(v0, v1);
            *reinterpret_cast<float2*>(&C[(size_t)(r0 + 8) * ldc + c]) = make_float2(v2, v3);
        }
    }
}

// ---------------- K column-sum (+1e-6) ----------------
__global__ void ksum_init() {
    int i = blockIdx.x * 256 + threadIdx.x;
    g_Ksum[i] = 1e-6f;
}

__global__ void ksum_acc() {
    int b = blockIdx.y;
    int chunk = blockIdx.x;           // 16 chunks of 256 rows
    int d4 = threadIdx.x;
    float4 s = make_float4(0.f, 0.f, 0.f, 0.f);
    const float* base = g_Kf + ((size_t)b * N_SEQ + chunk * 256) * D_DIM + d4 * 4;
    #pragma unroll 4
    for (int n = 0; n < 256; ++n) {
        float4 v = *reinterpret_cast<const float4*>(base + (size_t)n * D_DIM);
        s.x += v.x; s.y += v.y; s.z += v.z; s.w += v.w;
    }
    float* ks = g_Ksum + b * D_DIM + d4 * 4;
    atomicAdd(ks + 0, s.x);
    atomicAdd(ks + 1, s.y);
    atomicAdd(ks + 2, s.z);
    atomicAdd(ks + 3, s.w);
}

// ---------------- Z[b,n] = Q[b,n,:] . Ksum[b,:] ----------------
__global__ void z_kernel() {
    int warp = threadIdx.x >> 5;
    int lane = threadIdx.x & 31;
    long row = (long)blockIdx.x * 8 + warp;
    int b = (int)(row >> 12);
    const float* q  = g_Q + row * D_DIM;
    const float* ks = g_Ksum + b * D_DIM;
    float s = 0.f;
    #pragma unroll
    for (int i = 0; i < 8; ++i) {
        int d = (lane + i * 32) * 4;
        float4 qv = *reinterpret_cast<const float4*>(&q[d]);
        float4 kv = *reinterpret_cast<const float4*>(&ks[d]);
        s += qv.x * kv.x + qv.y * kv.y + qv.z * kv.z + qv.w * kv.w;
    }
    #pragma unroll
    for (int o = 16; o > 0; o >>= 1) s += __shfl_xor_sync(0xFFFFFFFFu, s, o);
    if (lane == 0) g_Z[row] = s;
}

// ---------------- launch ----------------
extern "C" void kernel_launch(void* const* d_in, const int* in_sizes, int n_in,
                              void* d_out, int out_size)
{
    const float* x  = (const float*)d_in[0];
    const float* Wq = (const float*)d_in[1];
    const float* bq = (const float*)d_in[2];
    const float* Wk = (const float*)d_in[3];
    const float* bk = (const float*)d_in[4];
    const float* Wv = (const float*)d_in[5];
    const float* bv = (const float*)d_in[6];
    const float* Wo = (const float*)d_in[7];
    const float* bo = (const float*)d_in[8];
    float* out = (float*)d_out;

    float *pQ, *pK, *pV, *pKV, *pM, *pZ;
    cudaGetSymbolAddress((void**)&pQ,  g_Q);
    cudaGetSymbolAddress((void**)&pK,  g_Kf);
    cudaGetSymbolAddress((void**)&pV,  g_V);
    cudaGetSymbolAddress((void**)&pKV, g_KV);
    cudaGetSymbolAddress((void**)&pM,  g_M);
    cudaGetSymbolAddress((void**)&pZ,  g_Z);

    cudaFuncSetAttribute(gemm_tf32<0,0,1>, cudaFuncAttributeMaxDynamicSharedMemorySize, SMEM_BYTES);
    cudaFuncSetAttribute(gemm_tf32<0,0,2>, cudaFuncAttributeMaxDynamicSharedMemorySize, SMEM_BYTES);
    cudaFuncSetAttribute(gemm_tf32<1,1,0>, cudaFuncAttributeMaxDynamicSharedMemorySize, SMEM_BYTES);
    cudaFuncSetAttribute(gemm_tf32<0,0,0>, cudaFuncAttributeMaxDynamicSharedMemorySize, SMEM_BYTES);
    cudaFuncSetAttribute(gemm_tf32<0,1,4>, cudaFuncAttributeMaxDynamicSharedMemorySize, SMEM_BYTES);

    dim3 blk(256);
    dim3 gproj(D_DIM / BN, M_FLAT / BM, 1);          // (8, 256)

    // 1) Q/K/V projections: C = X @ W^T  (elu+1 fused on Q,K; bias on V)
    gemm_tf32<0,0,2><<<gproj, blk, SMEM_BYTES>>>(x, Wq, pQ, pZ, bq,
        D_DIM, D_DIM, D_DIM, D_DIM, 0, 0, 0, 0);
    gemm_tf32<0,0,2><<<gproj, blk, SMEM_BYTES>>>(x, Wk, pK, pZ, bk,
        D_DIM, D_DIM, D_DIM, D_DIM, 0, 0, 0, 0);
    gemm_tf32<0,0,1><<<gproj, blk, SMEM_BYTES>>>(x, Wv, pV, pZ, bv,
        D_DIM, D_DIM, D_DIM, D_DIM, 0, 0, 0, 0);

    // 2) Ksum (+eps) and Z
    ksum_init<<<(N_BATCH * D_DIM) / 256, 256>>>();
    ksum_acc<<<dim3(16, N_BATCH), 256>>>();
    z_kernel<<<M_FLAT / 8, 256>>>();

    // 3) KV[b][d,e] = sum_n K[b][n,d] * V[b][n,e]   (both cp.async, K=4096)
    gemm_tf32<1,1,0><<<dim3(D_DIM / BN, D_DIM / BM, N_BATCH), blk, SMEM_BYTES>>>(
        pK, pV, pKV, pZ, pZ,
        N_SEQ, D_DIM, D_DIM, D_DIM,
        (long)N_SEQ * D_DIM, (long)N_SEQ * D_DIM, (long)D_DIM * D_DIM, 0);

    // 4) M[b][d,f] = sum_e KV[b][d,e] * Wo[f,e]   (17.2 GF total)
    gemm_tf32<0,0,0><<<dim3(D_DIM / BN, D_DIM / BM, N_BATCH), blk, SMEM_BYTES>>>(
        pKV, Wo, pM, pZ, pZ,
        D_DIM, D_DIM, D_DIM, D_DIM,
        (long)D_DIM * D_DIM, 0, (long)D_DIM * D_DIM, 0);

    // 5) out[b][n,f] = (sum_d Q[b][n,d] * M[b][d,f]) / Z[b,n] + bo[f]
    gemm_tf32<0,1,4><<<dim3(D_DIM / BN, N_SEQ / BM, N_BATCH), blk, SMEM_BYTES>>>(
        pQ, pM, out, pZ, bo,
        D_DIM, D_DIM, D_DIM, D_DIM,
        (long)N_SEQ * D_DIM, (long)D_DIM * D_DIM, (long)N_SEQ * D_DIM, N_SEQ);
}

// round 5
// speedup vs baseline: 1.0017x; 1.0017x over previous
#include <cuda_runtime.h>
#include <cstdint>
#include <math.h>

#define D_DIM   1024
#define N_BATCH 8
#define N_SEQ   4096
#define M_FLAT  (N_BATCH * N_SEQ)   // 32768

// GEMM tile config
#define BM 128
#define BN 128
#define BK 32
#define LDROW 136                       // smem row pitch in words (conflict-free)
#define STAGE_WORDS (BK * LDROW)        // one operand, one stage
#define SMEM_WORDS  (4 * STAGE_WORDS)   // A0,A1,B0,B1
#define SMEM_BYTES  (SMEM_WORDS * 4)    // 69632 B

// ---------------- scratch (device globals: no allocation allowed) ----------
__device__ float g_Q  [(size_t)M_FLAT * D_DIM];           // 134 MB
__device__ float g_Kf [(size_t)M_FLAT * D_DIM];           // feature-mapped K
__device__ float g_V  [(size_t)M_FLAT * D_DIM];
__device__ float g_KV [(size_t)N_BATCH * D_DIM * D_DIM];  // K^T V  [d,e]
__device__ float g_M  [(size_t)N_BATCH * D_DIM * D_DIM];  // KV @ Wo^T  [d,f]
__device__ float g_Ksum[N_BATCH * D_DIM];
__device__ float g_Z[M_FLAT];

// ---------------- helpers ----------------
__device__ __forceinline__ uint32_t f2tf32(float f) {
    uint32_t u;
    asm("cvt.rna.tf32.f32 %0, %1;" : "=r"(u) : "f"(f));
    return u;
}

__device__ __forceinline__ uint32_t smem_u32(const void* p) {
    uint32_t a;
    asm("{ .reg .u64 t; cvta.to.shared.u64 t, %1; cvt.u32.u64 %0, t; }" : "=r"(a) : "l"(p));
    return a;
}

#define CP_ASYNC16(dst, src) \
    asm volatile("cp.async.cg.shared.global [%0], [%1], 16;" :: "r"(dst), "l"(src) : "memory")
#define CP_COMMIT() asm volatile("cp.async.commit_group;" ::: "memory")
#define CP_WAIT0()  asm volatile("cp.async.wait_group 0;" ::: "memory")

__device__ __forceinline__ void mma8(float c[4], const uint32_t a[4], const uint32_t b[2]) {
    asm volatile(
        "mma.sync.aligned.m16n8k8.row.col.f32.tf32.tf32.f32 "
        "{%0,%1,%2,%3}, {%4,%5,%6,%7}, {%8,%9}, {%0,%1,%2,%3};\n"
        : "+f"(c[0]), "+f"(c[1]), "+f"(c[2]), "+f"(c[3])
        : "r"(a[0]), "r"(a[1]), "r"(a[2]), "r"(a[3]), "r"(b[0]), "r"(b[1]));
}

// ---------------- generic tf32 GEMM ----------------
// C[M,N] = epi( sum_k A[m,k] * B[k,n] )
// AT==0: A[m,k] = A[m*lda + k]  (reg-transpose path, RNA cvt)
// AT==1: A[m,k] = A[k*lda + m]  (cp.async path, truncation)
// BT==0: B[k,n] = B[n*ldb + k]  (reg-transpose path)
// BT==1: B[k,n] = B[k*ldb + n]  (cp.async path)
// EPI: 0 none | 1 +biasN | 2 elu(+biasN)+1 | 4 v/zM + biasN
template<int AT, int BT, int EPI>
__global__ void __launch_bounds__(256, 1)
gemm_tf32(const float* __restrict__ Ag, const float* __restrict__ Bg,
          float* __restrict__ Cg,
          const float* __restrict__ auxM, const float* __restrict__ auxN,
          int K, int lda, int ldb, int ldc,
          long sA, long sB, long sC, long sAuxM)
{
    extern __shared__ uint32_t sm[];
    const int bz = blockIdx.z;
    const float* A = Ag + (size_t)bz * sA;
    const float* B = Bg + (size_t)bz * sB;
    float*       C = Cg + (size_t)bz * sC;
    const float* axm = auxM + (size_t)bz * sAuxM;

    const int tid  = threadIdx.x;
    const int lane = tid & 31;
    const int warp = tid >> 5;
    const int g    = lane >> 2;
    const int t    = lane & 3;
    const int wm   = warp & 1;          // 2 (m) x 4 (n) warp grid
    const int wn   = warp >> 1;
    const int m0   = blockIdx.y * BM;
    const int n0   = blockIdx.x * BN;

    const uint32_t smem0 = smem_u32(sm);

    float acc[4][4][4];
    #pragma unroll
    for (int i = 0; i < 4; ++i)
        #pragma unroll
        for (int j = 0; j < 4; ++j)
            #pragma unroll
            for (int l = 0; l < 4; ++l) acc[i][j][l] = 0.f;

    // reg-transpose path ids: 32 consecutive rows per warp -> conflict-free STS
    const int rr = tid & 127;           // m (or n) row
    const int kh = tid >> 7;            // k half: 0 -> k 0..15, 1 -> k 16..31
    float4 ra[4], rb[4];

    auto ldgA = [&](int kt) {
        if (AT == 0) {
            const float* p = &A[(size_t)(m0 + rr) * lda + kt * BK + kh * 16];
            #pragma unroll
            for (int q = 0; q < 4; ++q) ra[q] = *reinterpret_cast<const float4*>(p + q * 4);
        }
    };
    auto ldgB = [&](int kt) {
        if (BT == 0) {
            const float* p = &B[(size_t)(n0 + rr) * ldb + kt * BK + kh * 16];
            #pragma unroll
            for (int q = 0; q < 4; ++q) rb[q] = *reinterpret_cast<const float4*>(p + q * 4);
        }
    };
    auto stsA = [&](int s) {
        if (AT == 0) {
            uint32_t* as = sm + s * STAGE_WORDS;
            #pragma unroll
            for (int q = 0; q < 4; ++q) {
                int k = kh * 16 + q * 4;
                as[(k + 0) * LDROW + rr] = f2tf32(ra[q].x);
                as[(k + 1) * LDROW + rr] = f2tf32(ra[q].y);
                as[(k + 2) * LDROW + rr] = f2tf32(ra[q].z);
                as[(k + 3) * LDROW + rr] = f2tf32(ra[q].w);
            }
        }
    };
    auto stsB = [&](int s) {
        if (BT == 0) {
            uint32_t* bs = sm + (2 + s) * STAGE_WORDS;
            #pragma unroll
            for (int q = 0; q < 4; ++q) {
                int k = kh * 16 + q * 4;
                bs[(k + 0) * LDROW + rr] = f2tf32(rb[q].x);
                bs[(k + 1) * LDROW + rr] = f2tf32(rb[q].y);
                bs[(k + 2) * LDROW + rr] = f2tf32(rb[q].z);
                bs[(k + 3) * LDROW + rr] = f2tf32(rb[q].w);
            }
        }
    };
    auto asyncA = [&](int s, int kt) {
        if (AT == 1) {
            int j = tid & 31, kq = tid >> 5;     // j: 16B chunk, kq: base k row
            #pragma unroll
            for (int i = 0; i < 4; ++i) {
                int k = kq + i * 8;
                uint32_t d = smem0 + (s * STAGE_WORDS + k * LDROW + j * 4) * 4;
                CP_ASYNC16(d, A + (size_t)(kt * BK + k) * lda + m0 + j * 4);
            }
        }
    };
    auto asyncB = [&](int s, int kt) {
        if (BT == 1) {
            int j = tid & 31, kq = tid >> 5;
            #pragma unroll
            for (int i = 0; i < 4; ++i) {
                int k = kq + i * 8;
                uint32_t d = smem0 + ((2 + s) * STAGE_WORDS + k * LDROW + j * 4) * 4;
                CP_ASYNC16(d, B + (size_t)(kt * BK + k) * ldb + n0 + j * 4);
            }
        }
    };

    auto compute = [&](int s) {
        const uint32_t* as = sm + s * STAGE_WORDS;
        const uint32_t* bs = sm + (2 + s) * STAGE_WORDS;
        #pragma unroll
        for (int ks = 0; ks < BK; ks += 8) {
            uint32_t af[4][4];
            uint32_t bf[4][2];
            #pragma unroll
            for (int mt = 0; mt < 4; ++mt) {
                int mr = wm * 64 + mt * 16;
                af[mt][0] = as[(ks + t    ) * LDROW + mr + g    ];
                af[mt][1] = as[(ks + t    ) * LDROW + mr + g + 8];
                af[mt][2] = as[(ks + t + 4) * LDROW + mr + g    ];
                af[mt][3] = as[(ks + t + 4) * LDROW + mr + g + 8];
            }
            #pragma unroll
            for (int nt = 0; nt < 4; ++nt) {
                int nc = wn * 32 + nt * 8;
                bf[nt][0] = bs[(ks + t    ) * LDROW + nc + g];
                bf[nt][1] = bs[(ks + t + 4) * LDROW + nc + g];
            }
            #pragma unroll
            for (int mt = 0; mt < 4; ++mt)
                #pragma unroll
                for (int nt = 0; nt < 4; ++nt)
                    mma8(acc[mt][nt], af[mt], bf[nt]);
        }
    };

    const int KT = K / BK;
    // prologue: fill stage 0
    ldgA(0); ldgB(0);
    asyncA(0, 0); asyncB(0, 0); CP_COMMIT();
    stsA(0); stsB(0);
    CP_WAIT0();
    __syncthreads();

    for (int kt = 0; kt < KT; ++kt) {
        int s = kt & 1;
        if (kt + 1 < KT) {
            ldgA(kt + 1); ldgB(kt + 1);
            asyncA(1 - s, kt + 1); asyncB(1 - s, kt + 1); CP_COMMIT();
        }
        compute(s);
        if (kt + 1 < KT) {
            stsA(1 - s); stsB(1 - s);
            CP_WAIT0();
            __syncthreads();
        }
    }

    // ---------------- epilogue ----------------
    #pragma unroll
    for (int mt = 0; mt < 4; ++mt) {
        int r0 = m0 + wm * 64 + mt * 16 + g;
        float z0 = 1.f, z1 = 1.f;
        if (EPI == 4) { z0 = 1.f / axm[r0]; z1 = 1.f / axm[r0 + 8]; }
        #pragma unroll
        for (int nt = 0; nt < 4; ++nt) {
            int c = n0 + wn * 32 + nt * 8 + t * 2;
            float v0 = acc[mt][nt][0], v1 = acc[mt][nt][1];
            float v2 = acc[mt][nt][2], v3 = acc[mt][nt][3];
            if (EPI == 1 || EPI == 2) {
                float b0 = auxN[c], b1 = auxN[c + 1];
                v0 += b0; v1 += b1; v2 += b0; v3 += b1;
            }
            if (EPI == 2) {   // elu(x)+1 : x>0 -> x+1 else exp(x)
                v0 = v0 > 0.f ? v0 + 1.f : expf(v0);
                v1 = v1 > 0.f ? v1 + 1.f : expf(v1);
                v2 = v2 > 0.f ? v2 + 1.f : expf(v2);
                v3 = v3 > 0.f ? v3 + 1.f : expf(v3);
            }
            if (EPI == 4) {   // v/z + bias
                float b0 = auxN[c], b1 = auxN[c + 1];
                v0 = v0 * z0 + b0; v1 = v1 * z0 + b1;
                v2 = v2 * z1 + b0; v3 = v3 * z1 + b1;
            }
            *reinterpret_cast<float2*>(&C[(size_t)r0       * ldc + c]) = make_float2(v0, v1);
            *reinterpret_cast<float2*>(&C[(size_t)(r0 + 8) * ldc + c]) = make_float2(v2, v3);
        }
    }
}

// ---------------- K column-sum (+1e-6) ----------------
__global__ void ksum_init() {
    int i = blockIdx.x * 256 + threadIdx.x;
    g_Ksum[i] = 1e-6f;
}

__global__ void ksum_acc() {
    int b = blockIdx.y;
    int chunk = blockIdx.x;           // 16 chunks of 256 rows
    int d4 = threadIdx.x;
    float4 s = make_float4(0.f, 0.f, 0.f, 0.f);
    const float* base = g_Kf + ((size_t)b * N_SEQ + chunk * 256) * D_DIM + d4 * 4;
    #pragma unroll 4
    for (int n = 0; n < 256; ++n) {
        float4 v = *reinterpret_cast<const float4*>(base + (size_t)n * D_DIM);
        s.x += v.x; s.y += v.y; s.z += v.z; s.w += v.w;
    }
    float* ks = g_Ksum + b * D_DIM + d4 * 4;
    atomicAdd(ks + 0, s.x);
    atomicAdd(ks + 1, s.y);
    atomicAdd(ks + 2, s.z);
    atomicAdd(ks + 3, s.w);
}

// ---------------- Z[b,n] = Q[b,n,:] . Ksum[b,:] ----------------
__global__ void z_kernel() {
    int warp = threadIdx.x >> 5;
    int lane = threadIdx.x & 31;
    long row = (long)blockIdx.x * 8 + warp;
    int b = (int)(row >> 12);
    const float* q  = g_Q + row * D_DIM;
    const float* ks = g_Ksum + b * D_DIM;
    float s = 0.f;
    #pragma unroll
    for (int i = 0; i < 8; ++i) {
        int d = (lane + i * 32) * 4;
        float4 qv = *reinterpret_cast<const float4*>(&q[d]);
        float4 kv = *reinterpret_cast<const float4*>(&ks[d]);
        s += qv.x * kv.x + qv.y * kv.y + qv.z * kv.z + qv.w * kv.w;
    }
    #pragma unroll
    for (int o = 16; o > 0; o >>= 1) s += __shfl_xor_sync(0xFFFFFFFFu, s, o);
    if (lane == 0) g_Z[row] = s;
}

// ---------------- launch ----------------
extern "C" void kernel_launch(void* const* d_in, const int* in_sizes, int n_in,
                              void* d_out, int out_size)
{
    const float* x  = (const float*)d_in[0];
    const float* Wq = (const float*)d_in[1];
    const float* bq = (const float*)d_in[2];
    const float* Wk = (const float*)d_in[3];
    const float* bk = (const float*)d_in[4];
    const float* Wv = (const float*)d_in[5];
    const float* bv = (const float*)d_in[6];
    const float* Wo = (const float*)d_in[7];
    const float* bo = (const float*)d_in[8];
    float* out = (float*)d_out;

    float *pQ, *pK, *pV, *pKV, *pM, *pZ;
    cudaGetSymbolAddress((void**)&pQ,  g_Q);
    cudaGetSymbolAddress((void**)&pK,  g_Kf);
    cudaGetSymbolAddress((void**)&pV,  g_V);
    cudaGetSymbolAddress((void**)&pKV, g_KV);
    cudaGetSymbolAddress((void**)&pM,  g_M);
    cudaGetSymbolAddress((void**)&pZ,  g_Z);

    cudaFuncSetAttribute(gemm_tf32<0,0,1>, cudaFuncAttributeMaxDynamicSharedMemorySize, SMEM_BYTES);
    cudaFuncSetAttribute(gemm_tf32<0,0,2>, cudaFuncAttributeMaxDynamicSharedMemorySize, SMEM_BYTES);
    cudaFuncSetAttribute(gemm_tf32<1,1,0>, cudaFuncAttributeMaxDynamicSharedMemorySize, SMEM_BYTES);
    cudaFuncSetAttribute(gemm_tf32<0,0,0>, cudaFuncAttributeMaxDynamicSharedMemorySize, SMEM_BYTES);
    cudaFuncSetAttribute(gemm_tf32<0,1,4>, cudaFuncAttributeMaxDynamicSharedMemorySize, SMEM_BYTES);

    dim3 blk(256);
    dim3 gproj(D_DIM / BN, M_FLAT / BM, 1);          // (8, 256)

    // 1) Q/K/V projections: C = X @ W^T  (elu+1 fused on Q,K; bias on V)
    gemm_tf32<0,0,2><<<gproj, blk, SMEM_BYTES>>>(x, Wq, pQ, pZ, bq,
        D_DIM, D_DIM, D_DIM, D_DIM, 0, 0, 0, 0);
    gemm_tf32<0,0,2><<<gproj, blk, SMEM_BYTES>>>(x, Wk, pK, pZ, bk,
        D_DIM, D_DIM, D_DIM, D_DIM, 0, 0, 0, 0);
    gemm_tf32<0,0,1><<<gproj, blk, SMEM_BYTES>>>(x, Wv, pV, pZ, bv,
        D_DIM, D_DIM, D_DIM, D_DIM, 0, 0, 0, 0);

    // 2) Ksum (+eps) and Z
    ksum_init<<<(N_BATCH * D_DIM) / 256, 256>>>();
    ksum_acc<<<dim3(16, N_BATCH), 256>>>();
    z_kernel<<<M_FLAT / 8, 256>>>();

    // 3) KV[b][d,e] = sum_n K[b][n,d] * V[b][n,e]   (both cp.async, K=4096)
    gemm_tf32<1,1,0><<<dim3(D_DIM / BN, D_DIM / BM, N_BATCH), blk, SMEM_BYTES>>>(
        pK, pV, pKV, pZ, pZ,
        N_SEQ, D_DIM, D_DIM, D_DIM,
        (long)N_SEQ * D_DIM, (long)N_SEQ * D_DIM, (long)D_DIM * D_DIM, 0);

    // 4) M[b][d,f] = sum_e KV[b][d,e] * Wo[f,e]   (17.2 GF total)
    gemm_tf32<0,0,0><<<dim3(D_DIM / BN, D_DIM / BM, N_BATCH), blk, SMEM_BYTES>>>(
        pKV, Wo, pM, pZ, pZ,
        D_DIM, D_DIM, D_DIM, D_DIM,
        (long)D_DIM * D_DIM, 0, (long)D_DIM * D_DIM, 0);

    // 5) out[b][n,f] = (sum_d Q[b][n,d] * M[b][d,f]) / Z[b,n] + bo[f]
    gemm_tf32<0,1,4><<<dim3(D_DIM / BN, N_SEQ / BM, N_BATCH), blk, SMEM_BYTES>>>(
        pQ, pM, out, pZ, bo,
        D_DIM, D_DIM, D_DIM, D_DIM,
        (long)N_SEQ * D_DIM, (long)D_DIM * D_DIM, (long)N_SEQ * D_DIM, N_SEQ);
}

// round 6
// speedup vs baseline: 1.0025x; 1.0009x over previous
#include <cuda_runtime.h>
#include <cstdint>
#include <math.h>

#define D_DIM   1024
#define N_BATCH 8
#define N_SEQ   4096
#define M_FLAT  (N_BATCH * N_SEQ)   // 32768

// GEMM tile config
#define BM 128
#define BN 128
#define BK 32
#define LDROW 136                       // smem row pitch in words (conflict-free)
#define STAGE_WORDS (BK * LDROW)        // one operand, one stage
#define SMEM_WORDS  (4 * STAGE_WORDS)   // A0,A1,B0,B1
#define SMEM_BYTES  (SMEM_WORDS * 4)    // 69632 B

// ---------------- scratch (device globals: no allocation allowed) ----------
__device__ float g_Q  [(size_t)M_FLAT * D_DIM];           // 134 MB
__device__ float g_Kf [(size_t)M_FLAT * D_DIM];           // feature-mapped K
__device__ float g_V  [(size_t)M_FLAT * D_DIM];
__device__ float g_KV [(size_t)N_BATCH * D_DIM * D_DIM];  // K^T V  [d,e]
__device__ float g_M  [(size_t)N_BATCH * D_DIM * D_DIM];  // KV @ Wo^T  [d,f]
__device__ float g_Ksum[N_BATCH * D_DIM];
__device__ float g_Z[M_FLAT];

// ---------------- helpers ----------------
__device__ __forceinline__ uint32_t f2tf32(float f) {
    uint32_t u;
    asm("cvt.rna.tf32.f32 %0, %1;" : "=r"(u) : "f"(f));
    return u;
}

__device__ __forceinline__ uint32_t smem_u32(const void* p) {
    uint32_t a;
    asm("{ .reg .u64 t; cvta.to.shared.u64 t, %1; cvt.u32.u64 %0, t; }" : "=r"(a) : "l"(p));
    return a;
}

#define CP_ASYNC16(dst, src) \
    asm volatile("cp.async.cg.shared.global [%0], [%1], 16;" :: "r"(dst), "l"(src) : "memory")
#define CP_COMMIT() asm volatile("cp.async.commit_group;" ::: "memory")
#define CP_WAIT0()  asm volatile("cp.async.wait_group 0;" ::: "memory")

__device__ __forceinline__ void mma8(float c[4], const uint32_t a[4], const uint32_t b[2]) {
    asm volatile(
        "mma.sync.aligned.m16n8k8.row.col.f32.tf32.tf32.f32 "
        "{%0,%1,%2,%3}, {%4,%5,%6,%7}, {%8,%9}, {%0,%1,%2,%3};\n"
        : "+f"(c[0]), "+f"(c[1]), "+f"(c[2]), "+f"(c[3])
        : "r"(a[0]), "r"(a[1]), "r"(a[2]), "r"(a[3]), "r"(b[0]), "r"(b[1]));
}

// ---------------- generic tf32 GEMM ----------------
// C[M,N] = epi( sum_k A[m,k] * B[k,n] )
// AT==0: A[m,k] = A[m*lda + k]  (reg-transpose path, RNA cvt)
// AT==1: A[m,k] = A[k*lda + m]  (cp.async path, truncation)
// BT==0: B[k,n] = B[n*ldb + k]  (reg-transpose path)
// BT==1: B[k,n] = B[k*ldb + n]  (cp.async path)
// EPI: 0 none | 1 +biasN | 2 elu(+biasN)+1 | 4 v/zM + biasN
template<int AT, int BT, int EPI>
__global__ void __launch_bounds__(256, 1)
gemm_tf32(const float* __restrict__ Ag, const float* __restrict__ Bg,
          float* __restrict__ Cg,
          const float* __restrict__ auxM, const float* __restrict__ auxN,
          int K, int lda, int ldb, int ldc,
          long sA, long sB, long sC, long sAuxM)
{
    extern __shared__ uint32_t sm[];
    const int bz = blockIdx.z;
    const float* A = Ag + (size_t)bz * sA;
    const float* B = Bg + (size_t)bz * sB;
    float*       C = Cg + (size_t)bz * sC;
    const float* axm = auxM + (size_t)bz * sAuxM;

    const int tid  = threadIdx.x;
    const int lane = tid & 31;
    const int warp = tid >> 5;
    const int g    = lane >> 2;
    const int t    = lane & 3;
    const int wm   = warp & 1;          // 2 (m) x 4 (n) warp grid
    const int wn   = warp >> 1;
    const int m0   = blockIdx.y * BM;
    const int n0   = blockIdx.x * BN;

    const uint32_t smem0 = smem_u32(sm);

    float acc[4][4][4];
    #pragma unroll
    for (int i = 0; i < 4; ++i)
        #pragma unroll
        for (int j = 0; j < 4; ++j)
            #pragma unroll
            for (int l = 0; l < 4; ++l) acc[i][j][l] = 0.f;

    // reg-transpose path ids: 32 consecutive rows per warp -> conflict-free STS
    const int rr = tid & 127;           // m (or n) row
    const int kh = tid >> 7;            // k half: 0 -> k 0..15, 1 -> k 16..31
    float4 ra[4], rb[4];

    auto ldgA = [&](int kt) {
        if (AT == 0) {
            const float* p = &A[(size_t)(m0 + rr) * lda + kt * BK + kh * 16];
            #pragma unroll
            for (int q = 0; q < 4; ++q) ra[q] = *reinterpret_cast<const float4*>(p + q * 4);
        }
    };
    auto ldgB = [&](int kt) {
        if (BT == 0) {
            const float* p = &B[(size_t)(n0 + rr) * ldb + kt * BK + kh * 16];
            #pragma unroll
            for (int q = 0; q < 4; ++q) rb[q] = *reinterpret_cast<const float4*>(p + q * 4);
        }
    };
    auto stsA = [&](int s) {
        if (AT == 0) {
            uint32_t* as = sm + s * STAGE_WORDS;
            #pragma unroll
            for (int q = 0; q < 4; ++q) {
                int k = kh * 16 + q * 4;
                as[(k + 0) * LDROW + rr] = f2tf32(ra[q].x);
                as[(k + 1) * LDROW + rr] = f2tf32(ra[q].y);
                as[(k + 2) * LDROW + rr] = f2tf32(ra[q].z);
                as[(k + 3) * LDROW + rr] = f2tf32(ra[q].w);
            }
        }
    };
    auto stsB = [&](int s) {
        if (BT == 0) {
            uint32_t* bs = sm + (2 + s) * STAGE_WORDS;
            #pragma unroll
            for (int q = 0; q < 4; ++q) {
                int k = kh * 16 + q * 4;
                bs[(k + 0) * LDROW + rr] = f2tf32(rb[q].x);
                bs[(k + 1) * LDROW + rr] = f2tf32(rb[q].y);
                bs[(k + 2) * LDROW + rr] = f2tf32(rb[q].z);
                bs[(k + 3) * LDROW + rr] = f2tf32(rb[q].w);
            }
        }
    };
    auto asyncA = [&](int s, int kt) {
        if (AT == 1) {
            int j = tid & 31, kq = tid >> 5;     // j: 16B chunk, kq: base k row
            #pragma unroll
            for (int i = 0; i < 4; ++i) {
                int k = kq + i * 8;
                uint32_t d = smem0 + (s * STAGE_WORDS + k * LDROW + j * 4) * 4;
                CP_ASYNC16(d, A + (size_t)(kt * BK + k) * lda + m0 + j * 4);
            }
        }
    };
    auto asyncB = [&](int s, int kt) {
        if (BT == 1) {
            int j = tid & 31, kq = tid >> 5;
            #pragma unroll
            for (int i = 0; i < 4; ++i) {
                int k = kq + i * 8;
                uint32_t d = smem0 + ((2 + s) * STAGE_WORDS + k * LDROW + j * 4) * 4;
                CP_ASYNC16(d, B + (size_t)(kt * BK + k) * ldb + n0 + j * 4);
            }
        }
    };

    auto compute = [&](int s) {
        const uint32_t* as = sm + s * STAGE_WORDS;
        const uint32_t* bs = sm + (2 + s) * STAGE_WORDS;
        #pragma unroll
        for (int ks = 0; ks < BK; ks += 8) {
            uint32_t af[4][4];
            uint32_t bf[4][2];
            #pragma unroll
            for (int mt = 0; mt < 4; ++mt) {
                int mr = wm * 64 + mt * 16;
                af[mt][0] = as[(ks + t    ) * LDROW + mr + g    ];
                af[mt][1] = as[(ks + t    ) * LDROW + mr + g + 8];
                af[mt][2] = as[(ks + t + 4) * LDROW + mr + g    ];
                af[mt][3] = as[(ks + t + 4) * LDROW + mr + g + 8];
            }
            #pragma unroll
            for (int nt = 0; nt < 4; ++nt) {
                int nc = wn * 32 + nt * 8;
                bf[nt][0] = bs[(ks + t    ) * LDROW + nc + g];
                bf[nt][1] = bs[(ks + t + 4) * LDROW + nc + g];
            }
            #pragma unroll
            for (int mt = 0; mt < 4; ++mt)
                #pragma unroll
                for (int nt = 0; nt < 4; ++nt)
                    mma8(acc[mt][nt], af[mt], bf[nt]);
        }
    };

    const int KT = K / BK;
    // prologue: fill stage 0
    ldgA(0); ldgB(0);
    asyncA(0, 0); asyncB(0, 0); CP_COMMIT();
    stsA(0); stsB(0);
    CP_WAIT0();
    __syncthreads();

    for (int kt = 0; kt < KT; ++kt) {
        int s = kt & 1;
        if (kt + 1 < KT) {
            ldgA(kt + 1); ldgB(kt + 1);
            asyncA(1 - s, kt + 1); asyncB(1 - s, kt + 1); CP_COMMIT();
        }
        compute(s);
        if (kt + 1 < KT) {
            stsA(1 - s); stsB(1 - s);
            CP_WAIT0();
            __syncthreads();
        }
    }

    // ---------------- epilogue ----------------
    #pragma unroll
    for (int mt = 0; mt < 4; ++mt) {
        int r0 = m0 + wm * 64 + mt * 16 + g;
        float z0 = 1.f, z1 = 1.f;
        if (EPI == 4) { z0 = 1.f / axm[r0]; z1 = 1.f / axm[r0 + 8]; }
        #pragma unroll
        for (int nt = 0; nt < 4; ++nt) {
            int c = n0 + wn * 32 + nt * 8 + t * 2;
            float v0 = acc[mt][nt][0], v1 = acc[mt][nt][1];
            float v2 = acc[mt][nt][2], v3 = acc[mt][nt][3];
            if (EPI == 1 || EPI == 2) {
                float b0 = auxN[c], b1 = auxN[c + 1];
                v0 += b0; v1 += b1; v2 += b0; v3 += b1;
            }
            if (EPI == 2) {   // elu(x)+1 : x>0 -> x+1 else exp(x)
                v0 = v0 > 0.f ? v0 + 1.f : expf(v0);
                v1 = v1 > 0.f ? v1 + 1.f : expf(v1);
                v2 = v2 > 0.f ? v2 + 1.f : expf(v2);
                v3 = v3 > 0.f ? v3 + 1.f : expf(v3);
            }
            if (EPI == 4) {   // v/z + bias
                float b0 = auxN[c], b1 = auxN[c + 1];
                v0 = v0 * z0 + b0; v1 = v1 * z0 + b1;
                v2 = v2 * z1 + b0; v3 = v3 * z1 + b1;
            }
            *reinterpret_cast<float2*>(&C[(size_t)r0       * ldc + c]) = make_float2(v0, v1);
            *reinterpret_cast<float2*>(&C[(size_t)(r0 + 8) * ldc + c]) = make_float2(v2, v3);
        }
    }
}

// ---------------- K column-sum (+1e-6) ----------------
__global__ void ksum_init() {
    int i = blockIdx.x * 256 + threadIdx.x;
    g_Ksum[i] = 1e-6f;
}

__global__ void ksum_acc() {
    int b = blockIdx.y;
    int chunk = blockIdx.x;           // 16 chunks of 256 rows
    int d4 = threadIdx.x;
    float4 s = make_float4(0.f, 0.f, 0.f, 0.f);
    const float* base = g_Kf + ((size_t)b * N_SEQ + chunk * 256) * D_DIM + d4 * 4;
    #pragma unroll 4
    for (int n = 0; n < 256; ++n) {
        float4 v = *reinterpret_cast<const float4*>(base + (size_t)n * D_DIM);
        s.x += v.x; s.y += v.y; s.z += v.z; s.w += v.w;
    }
    float* ks = g_Ksum + b * D_DIM + d4 * 4;
    atomicAdd(ks + 0, s.x);
    atomicAdd(ks + 1, s.y);
    atomicAdd(ks + 2, s.z);
    atomicAdd(ks + 3, s.w);
}

// ---------------- Z[b,n] = Q[b,n,:] . Ksum[b,:] ----------------
__global__ void z_kernel() {
    int warp = threadIdx.x >> 5;
    int lane = threadIdx.x & 31;
    long row = (long)blockIdx.x * 8 + warp;
    int b = (int)(row >> 12);
    const float* q  = g_Q + row * D_DIM;
    const float* ks = g_Ksum + b * D_DIM;
    float s = 0.f;
    #pragma unroll
    for (int i = 0; i < 8; ++i) {
        int d = (lane + i * 32) * 4;
        float4 qv = *reinterpret_cast<const float4*>(&q[d]);
        float4 kv = *reinterpret_cast<const float4*>(&ks[d]);
        s += qv.x * kv.x + qv.y * kv.y + qv.z * kv.z + qv.w * kv.w;
    }
    #pragma unroll
    for (int o = 16; o > 0; o >>= 1) s += __shfl_xor_sync(0xFFFFFFFFu, s, o);
    if (lane == 0) g_Z[row] = s;
}

// ---------------- launch ----------------
extern "C" void kernel_launch(void* const* d_in, const int* in_sizes, int n_in,
                              void* d_out, int out_size)
{
    const float* x  = (const float*)d_in[0];
    const float* Wq = (const float*)d_in[1];
    const float* bq = (const float*)d_in[2];
    const float* Wk = (const float*)d_in[3];
    const float* bk = (const float*)d_in[4];
    const float* Wv = (const float*)d_in[5];
    const float* bv = (const float*)d_in[6];
    const float* Wo = (const float*)d_in[7];
    const float* bo = (const float*)d_in[8];
    float* out = (float*)d_out;

    float *pQ, *pK, *pV, *pKV, *pM, *pZ;
    cudaGetSymbolAddress((void**)&pQ,  g_Q);
    cudaGetSymbolAddress((void**)&pK,  g_Kf);
    cudaGetSymbolAddress((void**)&pV,  g_V);
    cudaGetSymbolAddress((void**)&pKV, g_KV);
    cudaGetSymbolAddress((void**)&pM,  g_M);
    cudaGetSymbolAddress((void**)&pZ,  g_Z);

    cudaFuncSetAttribute(gemm_tf32<0,0,1>, cudaFuncAttributeMaxDynamicSharedMemorySize, SMEM_BYTES);
    cudaFuncSetAttribute(gemm_tf32<0,0,2>, cudaFuncAttributeMaxDynamicSharedMemorySize, SMEM_BYTES);
    cudaFuncSetAttribute(gemm_tf32<1,1,0>, cudaFuncAttributeMaxDynamicSharedMemorySize, SMEM_BYTES);
    cudaFuncSetAttribute(gemm_tf32<0,0,0>, cudaFuncAttributeMaxDynamicSharedMemorySize, SMEM_BYTES);
    cudaFuncSetAttribute(gemm_tf32<0,1,4>, cudaFuncAttributeMaxDynamicSharedMemorySize, SMEM_BYTES);

    dim3 blk(256);
    dim3 gproj(D_DIM / BN, M_FLAT / BM, 1);          // (8, 256)

    // 1) Q/K/V projections: C = X @ W^T  (elu+1 fused on Q,K; bias on V)
    gemm_tf32<0,0,2><<<gproj, blk, SMEM_BYTES>>>(x, Wq, pQ, pZ, bq,
        D_DIM, D_DIM, D_DIM, D_DIM, 0, 0, 0, 0);
    gemm_tf32<0,0,2><<<gproj, blk, SMEM_BYTES>>>(x, Wk, pK, pZ, bk,
        D_DIM, D_DIM, D_DIM, D_DIM, 0, 0, 0, 0);
    gemm_tf32<0,0,1><<<gproj, blk, SMEM_BYTES>>>(x, Wv, pV, pZ, bv,
        D_DIM, D_DIM, D_DIM, D_DIM, 0, 0, 0, 0);

    // 2) Ksum (+eps) and Z
    ksum_init<<<(N_BATCH * D_DIM) / 256, 256>>>();
    ksum_acc<<<dim3(16, N_BATCH), 256>>>();
    z_kernel<<<M_FLAT / 8, 256>>>();

    // 3) KV[b][d,e] = sum_n K[b][n,d] * V[b][n,e]   (both cp.async, K=4096)
    gemm_tf32<1,1,0><<<dim3(D_DIM / BN, D_DIM / BM, N_BATCH), blk, SMEM_BYTES>>>(
        pK, pV, pKV, pZ, pZ,
        N_SEQ, D_DIM, D_DIM, D_DIM,
        (long)N_SEQ * D_DIM, (long)N_SEQ * D_DIM, (long)D_DIM * D_DIM, 0);

    // 4) M[b][d,f] = sum_e KV[b][d,e] * Wo[f,e]   (17.2 GF total)
    gemm_tf32<0,0,0><<<dim3(D_DIM / BN, D_DIM / BM, N_BATCH), blk, SMEM_BYTES>>>(
        pKV, Wo, pM, pZ, pZ,
        D_DIM, D_DIM, D_DIM, D_DIM,
        (long)D_DIM * D_DIM, 0, (long)D_DIM * D_DIM, 0);

    // 5) out[b][n,f] = (sum_d Q[b][n,d] * M[b][d,f]) / Z[b,n] + bo[f]
    gemm_tf32<0,1,4><<<dim3(D_DIM / BN, N_SEQ / BM, N_BATCH), blk, SMEM_BYTES>>>(
        pQ, pM, out, pZ, bo,
        D_DIM, D_DIM, D_DIM, D_DIM,
        (long)N_SEQ * D_DIM, (long)D_DIM * D_DIM, (long)N_SEQ * D_DIM, N_SEQ);
}

// round 8
// speedup vs baseline: 1.3993x; 1.3958x over previous
#include <cuda_runtime.h>
#include <cstdint>
#include <math.h>

#define D_DIM   1024
#define N_BATCH 8
#define N_SEQ   4096
#define M_FLAT  (N_BATCH * N_SEQ)   // 32768

// ---------------- scratch (device globals: no allocation allowed) ----------
__device__ float g_Q  [(size_t)M_FLAT * D_DIM];           // 134 MB
__device__ float g_Kf [(size_t)M_FLAT * D_DIM];           // feature-mapped K
__device__ float g_V  [(size_t)M_FLAT * D_DIM];
__device__ float g_KV [(size_t)N_BATCH * D_DIM * D_DIM];  // K^T V   [d,e]
__device__ float g_M  [(size_t)N_BATCH * D_DIM * D_DIM];  // KV @ Wo^T [d,f]
__device__ float g_Ksum[N_BATCH * D_DIM];
__device__ float g_Z[M_FLAT];

// ---------------- helpers ----------------
__device__ __forceinline__ uint32_t f2tf32(float f) {
    uint32_t u;
    asm("cvt.rna.tf32.f32 %0, %1;" : "=r"(u) : "f"(f));
    return u;
}

__device__ __forceinline__ void mma8(float c[4], const uint32_t a[4], const uint32_t b[2]) {
    asm volatile(
        "mma.sync.aligned.m16n8k8.row.col.f32.tf32.tf32.f32 "
        "{%0,%1,%2,%3}, {%4,%5,%6,%7}, {%8,%9}, {%0,%1,%2,%3};\n"
        : "+f"(c[0]), "+f"(c[1]), "+f"(c[2]), "+f"(c[3])
        : "r"(a[0]), "r"(a[1]), "r"(a[2]), "r"(a[3]), "r"(b[0]), "r"(b[1]));
}

// ---------------- generic tf32 GEMM (round-2 proven core, double-buffered) ----
// C[M,N] = epilogue( sum_k A[m,k]*B[k,n] )
// AT==0: A[m,k] = A[m*lda + k]   (K contiguous)
// AT==1: A[m,k] = A[k*lda + m]   (M contiguous; used for K^T in KV)
// BT==0: B[k,n] = B[n*ldb + k]   (weights, stored [N,K])
// BT==1: B[k,n] = B[k*ldb + n]   (N contiguous)
// EPI: 0 none | 1 +biasN | 2 elu(+biasN)+1 | 4 v/zM + biasN
template<int AT, int BT, int EPI>
__global__ void __launch_bounds__(256)
gemm_tf32(const float* __restrict__ Ag, const float* __restrict__ Bg,
          float* __restrict__ Cg,
          const float* __restrict__ auxM, const float* __restrict__ auxN,
          int M, int N, int K, int lda, int ldb, int ldc,
          long sA, long sB, long sC, long sAuxM)
{
    // 2-stage double buffer: 2 * (16*136)*4B * 2 arrays = 34.8 KB (static OK)
    __shared__ uint32_t As[2][16][136];   // ld=136 -> conflict-free frag loads
    __shared__ uint32_t Bs[2][16][136];

    const int bz = blockIdx.z;
    const float* A = Ag + (long)bz * sA;
    const float* B = Bg + (long)bz * sB;
    float*       C = Cg + (long)bz * sC;
    const float* axm = auxM + (long)bz * sAuxM;

    const int tid  = threadIdx.x;
    const int lane = tid & 31;
    const int warp = tid >> 5;
    const int g    = lane >> 2;   // groupID (row within mma tile)
    const int t    = lane & 3;    // threadID_in_group
    const int wm   = warp & 1;    // warp grid 2 (m) x 4 (n)
    const int wn   = warp >> 1;
    const int m0   = blockIdx.y * 128;
    const int n0   = blockIdx.x * 128;

    float acc[4][4][4];
    #pragma unroll
    for (int i = 0; i < 4; ++i)
        #pragma unroll
        for (int j = 0; j < 4; ++j)
            #pragma unroll
            for (int l = 0; l < 4; ++l) acc[i][j][l] = 0.f;

    float4 ra[2], rb[2];

    auto loadA = [&](int k0) {
        #pragma unroll
        for (int it = 0; it < 2; ++it) {
            if (AT == 0) {
                int row = (tid >> 2) + it * 64;
                int sub = tid & 3;
                ra[it] = *reinterpret_cast<const float4*>(
                    &A[(long)(m0 + row) * lda + k0 + sub * 4]);
            } else {
                int kk = (tid >> 5) + it * 8;
                int mq = tid & 31;
                ra[it] = *reinterpret_cast<const float4*>(
                    &A[(long)(k0 + kk) * lda + m0 + mq * 4]);
            }
        }
    };
    auto loadB = [&](int k0) {
        #pragma unroll
        for (int it = 0; it < 2; ++it) {
            if (BT == 0) {
                int row = (tid >> 2) + it * 64;
                int sub = tid & 3;
                rb[it] = *reinterpret_cast<const float4*>(
                    &B[(long)(n0 + row) * ldb + k0 + sub * 4]);
            } else {
                int kk = (tid >> 5) + it * 8;
                int nq = tid & 31;
                rb[it] = *reinterpret_cast<const float4*>(
                    &B[(long)(k0 + kk) * ldb + n0 + nq * 4]);
            }
        }
    };
    auto storeA = [&](int s) {
        #pragma unroll
        for (int it = 0; it < 2; ++it) {
            if (AT == 0) {
                int row = (tid >> 2) + it * 64;
                int sub = tid & 3;
                As[s][sub * 4 + 0][row] = f2tf32(ra[it].x);
                As[s][sub * 4 + 1][row] = f2tf32(ra[it].y);
                As[s][sub * 4 + 2][row] = f2tf32(ra[it].z);
                As[s][sub * 4 + 3][row] = f2tf32(ra[it].w);
            } else {
                int kk = (tid >> 5) + it * 8;
                int mq = tid & 31;
                uint4 v;
                v.x = f2tf32(ra[it].x); v.y = f2tf32(ra[it].y);
                v.z = f2tf32(ra[it].z); v.w = f2tf32(ra[it].w);
                *reinterpret_cast<uint4*>(&As[s][kk][mq * 4]) = v;
            }
        }
    };
    auto storeB = [&](int s) {
        #pragma unroll
        for (int it = 0; it < 2; ++it) {
            if (BT == 0) {
                int row = (tid >> 2) + it * 64;
                int sub = tid & 3;
                Bs[s][sub * 4 + 0][row] = f2tf32(rb[it].x);
                Bs[s][sub * 4 + 1][row] = f2tf32(rb[it].y);
                Bs[s][sub * 4 + 2][row] = f2tf32(rb[it].z);
                Bs[s][sub * 4 + 3][row] = f2tf32(rb[it].w);
            } else {
                int kk = (tid >> 5) + it * 8;
                int nq = tid & 31;
                uint4 v;
                v.x = f2tf32(rb[it].x); v.y = f2tf32(rb[it].y);
                v.z = f2tf32(rb[it].z); v.w = f2tf32(rb[it].w);
                *reinterpret_cast<uint4*>(&Bs[s][kk][nq * 4]) = v;
            }
        }
    };
    auto compute = [&](int s) {
        #pragma unroll
        for (int ks = 0; ks < 16; ks += 8) {
            uint32_t af[4][4];
            uint32_t bf[4][2];
            #pragma unroll
            for (int mt = 0; mt < 4; ++mt) {
                int mr = wm * 64 + mt * 16;
                af[mt][0] = As[s][ks + t    ][mr + g    ];
                af[mt][1] = As[s][ks + t    ][mr + g + 8];
                af[mt][2] = As[s][ks + t + 4][mr + g    ];
                af[mt][3] = As[s][ks + t + 4][mr + g + 8];
            }
            #pragma unroll
            for (int nt = 0; nt < 4; ++nt) {
                int nc = wn * 32 + nt * 8;
                bf[nt][0] = Bs[s][ks + t    ][nc + g];
                bf[nt][1] = Bs[s][ks + t + 4][nc + g];
            }
            #pragma unroll
            for (int mt = 0; mt < 4; ++mt)
                #pragma unroll
                for (int nt = 0; nt < 4; ++nt)
                    mma8(acc[mt][nt], af[mt], bf[nt]);
        }
    };

    const int KT = K / 16;
    loadA(0); loadB(0);
    storeA(0); storeB(0);
    __syncthreads();
    for (int kt = 0; kt < KT; ++kt) {
        if (kt + 1 < KT) { loadA((kt + 1) * 16); loadB((kt + 1) * 16); }
        compute(kt & 1);
        if (kt + 1 < KT) {
            storeA((kt + 1) & 1); storeB((kt + 1) & 1);
            __syncthreads();
        }
    }

    // ---------------- epilogue ----------------
    #pragma unroll
    for (int mt = 0; mt < 4; ++mt) {
        int r0 = m0 + wm * 64 + mt * 16 + g;
        float z0 = 1.f, z1 = 1.f;
        if (EPI == 4) { z0 = 1.f / axm[r0]; z1 = 1.f / axm[r0 + 8]; }
        #pragma unroll
        for (int nt = 0; nt < 4; ++nt) {
            int c = n0 + wn * 32 + nt * 8 + t * 2;
            float v0 = acc[mt][nt][0], v1 = acc[mt][nt][1];
            float v2 = acc[mt][nt][2], v3 = acc[mt][nt][3];
            if (EPI == 1 || EPI == 2) {
                float b0 = auxN[c], b1 = auxN[c + 1];
                v0 += b0; v1 += b1; v2 += b0; v3 += b1;
            }
            if (EPI == 2) {   // elu(x)+1 : x>0 -> x+1 else exp(x)
                v0 = v0 > 0.f ? v0 + 1.f : expf(v0);
                v1 = v1 > 0.f ? v1 + 1.f : expf(v1);
                v2 = v2 > 0.f ? v2 + 1.f : expf(v2);
                v3 = v3 > 0.f ? v3 + 1.f : expf(v3);
            }
            if (EPI == 4) {   // v/z + bias
                float b0 = auxN[c], b1 = auxN[c + 1];
                v0 = v0 * z0 + b0; v1 = v1 * z0 + b1;
                v2 = v2 * z1 + b0; v3 = v3 * z1 + b1;
            }
            *reinterpret_cast<float2*>(&C[(long)r0       * ldc + c]) = make_float2(v0, v1);
            *reinterpret_cast<float2*>(&C[(long)(r0 + 8) * ldc + c]) = make_float2(v2, v3);
        }
    }
}

// ---------------- K column-sum (+1e-6) ----------------
__global__ void ksum_init() {
    int i = blockIdx.x * 256 + threadIdx.x;
    g_Ksum[i] = 1e-6f;
}

__global__ void ksum_acc() {
    int b = blockIdx.y;
    int chunk = blockIdx.x;           // 16 chunks of 256 rows
    int d4 = threadIdx.x;             // 0..255 -> float4 column group
    float4 s = make_float4(0.f, 0.f, 0.f, 0.f);
    const float* base = g_Kf + ((long)b * N_SEQ + chunk * 256) * D_DIM + d4 * 4;
    #pragma unroll 4
    for (int n = 0; n < 256; ++n) {
        float4 v = *reinterpret_cast<const float4*>(base + (long)n * D_DIM);
        s.x += v.x; s.y += v.y; s.z += v.z; s.w += v.w;
    }
    float* ks = g_Ksum + b * D_DIM + d4 * 4;
    atomicAdd(ks + 0, s.x);
    atomicAdd(ks + 1, s.y);
    atomicAdd(ks + 2, s.z);
    atomicAdd(ks + 3, s.w);
}

// ---------------- Z[b,n] = Q[b,n,:] . Ksum[b,:] ----------------
__global__ void z_kernel() {
    int warp = threadIdx.x >> 5;
    int lane = threadIdx.x & 31;
    long row = (long)blockIdx.x * 8 + warp;   // 32768 rows total
    int b = (int)(row >> 12);
    const float* q  = g_Q + row * D_DIM;
    const float* ks = g_Ksum + b * D_DIM;
    float s = 0.f;
    #pragma unroll
    for (int i = 0; i < 8; ++i) {
        int d = (lane + i * 32) * 4;
        float4 qv = *reinterpret_cast<const float4*>(&q[d]);
        float4 kv = *reinterpret_cast<const float4*>(&ks[d]);
        s += qv.x * kv.x + qv.y * kv.y + qv.z * kv.z + qv.w * kv.w;
    }
    #pragma unroll
    for (int o = 16; o > 0; o >>= 1) s += __shfl_xor_sync(0xFFFFFFFFu, s, o);
    if (lane == 0) g_Z[row] = s;
}

// ---------------- launch ----------------
extern "C" void kernel_launch(void* const* d_in, const int* in_sizes, int n_in,
                              void* d_out, int out_size)
{
    const float* x  = (const float*)d_in[0];
    const float* Wq = (const float*)d_in[1];
    const float* bq = (const float*)d_in[2];
    const float* Wk = (const float*)d_in[3];
    const float* bk = (const float*)d_in[4];
    const float* Wv = (const float*)d_in[5];
    const float* bv = (const float*)d_in[6];
    const float* Wo = (const float*)d_in[7];
    const float* bo = (const float*)d_in[8];
    float* out = (float*)d_out;

    float *pQ, *pK, *pV, *pKV, *pM, *pZ;
    cudaGetSymbolAddress((void**)&pQ,  g_Q);
    cudaGetSymbolAddress((void**)&pK,  g_Kf);
    cudaGetSymbolAddress((void**)&pV,  g_V);
    cudaGetSymbolAddress((void**)&pKV, g_KV);
    cudaGetSymbolAddress((void**)&pM,  g_M);
    cudaGetSymbolAddress((void**)&pZ,  g_Z);

    dim3 blk(256);
    dim3 gproj(D_DIM / 128, M_FLAT / 128, 1);        // (8, 256)

    // 1) Q/K/V projections: C = X @ W^T  (elu+1 fused on Q,K; bias on V)
    gemm_tf32<0,0,2><<<gproj, blk>>>(x, Wq, pQ, pZ, bq,
        M_FLAT, D_DIM, D_DIM, D_DIM, D_DIM, D_DIM, 0, 0, 0, 0);
    gemm_tf32<0,0,2><<<gproj, blk>>>(x, Wk, pK, pZ, bk,
        M_FLAT, D_DIM, D_DIM, D_DIM, D_DIM, D_DIM, 0, 0, 0, 0);
    gemm_tf32<0,0,1><<<gproj, blk>>>(x, Wv, pV, pZ, bv,
        M_FLAT, D_DIM, D_DIM, D_DIM, D_DIM, D_DIM, 0, 0, 0, 0);

    // 2) Ksum (+eps) and Z
    ksum_init<<<(N_BATCH * D_DIM) / 256, 256>>>();
    ksum_acc<<<dim3(16, N_BATCH), 256>>>();
    z_kernel<<<M_FLAT / 8, 256>>>();

    // 3) KV[b][d,e] = sum_n K[b][n,d] * V[b][n,e]   (M=D, N=D, K=seq)
    gemm_tf32<1,1,0><<<dim3(8, 8, N_BATCH), blk>>>(pK, pV, pKV, pZ, pZ,
        D_DIM, D_DIM, N_SEQ, D_DIM, D_DIM, D_DIM,
        (long)N_SEQ * D_DIM, (long)N_SEQ * D_DIM, (long)D_DIM * D_DIM, 0);

    // 4) M[b][d,f] = sum_e KV[b][d,e] * Wo[f,e]   (17.2 GF total)
    gemm_tf32<0,0,0><<<dim3(8, 8, N_BATCH), blk>>>(pKV, Wo, pM, pZ, pZ,
        D_DIM, D_DIM, D_DIM, D_DIM, D_DIM, D_DIM,
        (long)D_DIM * D_DIM, 0, (long)D_DIM * D_DIM, 0);

    // 5) out[b][n,f] = (sum_d Q[b][n,d] * M[b][d,f]) / Z[b,n] + bo[f]
    gemm_tf32<0,1,4><<<dim3(8, 32, N_BATCH), blk>>>(pQ, pM, out, pZ, bo,
        N_SEQ, D_DIM, D_DIM, D_DIM, D_DIM, D_DIM,
        (long)N_SEQ * D_DIM, (long)D_DIM * D_DIM, (long)N_SEQ * D_DIM, N_SEQ);
}

// round 10
// speedup vs baseline: 1.4211x; 1.0155x over previous
#include <cuda_runtime.h>
#include <cstdint>
#include <math.h>

#define D_DIM   1024
#define N_BATCH 8
#define N_SEQ   4096
#define M_FLAT  (N_BATCH * N_SEQ)   // 32768

// ---------------- scratch (device globals: no allocation allowed) ----------
__device__ float g_Q  [(size_t)M_FLAT * D_DIM];           // 134 MB
__device__ float g_Kf [(size_t)M_FLAT * D_DIM];           // feature-mapped K
__device__ float g_V  [(size_t)M_FLAT * D_DIM];
__device__ float g_KV [(size_t)N_BATCH * D_DIM * D_DIM];  // K^T V   [d,e]
__device__ float g_M  [(size_t)N_BATCH * D_DIM * D_DIM];  // KV @ Wo^T [d,f]
__device__ float g_Ksum[N_BATCH * D_DIM];
__device__ float g_Z[M_FLAT];

// ---------------- helpers ----------------
__device__ __forceinline__ uint32_t f2tf32(float f) {
    uint32_t u;
    asm("cvt.rna.tf32.f32 %0, %1;" : "=r"(u) : "f"(f));
    return u;
}

__device__ __forceinline__ void mma8(float c[4], const uint32_t a[4], const uint32_t b[2]) {
    asm volatile(
        "mma.sync.aligned.m16n8k8.row.col.f32.tf32.tf32.f32 "
        "{%0,%1,%2,%3}, {%4,%5,%6,%7}, {%8,%9}, {%0,%1,%2,%3};\n"
        : "+f"(c[0]), "+f"(c[1]), "+f"(c[2]), "+f"(c[3])
        : "r"(a[0]), "r"(a[1]), "r"(a[2]), "r"(a[3]), "r"(b[0]), "r"(b[1]));
}

// ---------------- generic tf32 GEMM (proven core; now 2 CTAs/SM) ----------
// C[M,N] = epilogue( sum_k A[m,k]*B[k,n] )
// AT==0: A[m,k] = A[m*lda + k]   (K contiguous)
// AT==1: A[m,k] = A[k*lda + m]   (M contiguous; used for K^T in KV)
// BT==0: B[k,n] = B[n*ldb + k]   (weights, stored [N,K])
// BT==1: B[k,n] = B[k*ldb + n]   (N contiguous)
// EPI: 0 none | 1 +biasN | 2 elu(+biasN)+1 | 4 v/zM + biasN
template<int AT, int BT, int EPI>
__global__ void __launch_bounds__(256, 2)
gemm_tf32(const float* __restrict__ Ag, const float* __restrict__ Bg,
          float* __restrict__ Cg,
          const float* __restrict__ auxM, const float* __restrict__ auxN,
          int M, int N, int K, int lda, int ldb, int ldc,
          long sA, long sB, long sC, long sAuxM)
{
    // 2-stage double buffer: 2 * (16*136)*4B * 2 arrays = 34.8 KB
    // (x2 CTAs/SM = 69.6 KB/SM, fits 228 KB carveout)
    __shared__ uint32_t As[2][16][136];   // ld=136 -> conflict-free frag loads
    __shared__ uint32_t Bs[2][16][136];

    const int bz = blockIdx.z;
    const float* A = Ag + (long)bz * sA;
    const float* B = Bg + (long)bz * sB;
    float*       C = Cg + (long)bz * sC;
    const float* axm = auxM + (long)bz * sAuxM;

    const int tid  = threadIdx.x;
    const int lane = tid & 31;
    const int warp = tid >> 5;
    const int g    = lane >> 2;   // groupID (row within mma tile)
    const int t    = lane & 3;    // threadID_in_group
    const int wm   = warp & 1;    // warp grid 2 (m) x 4 (n)
    const int wn   = warp >> 1;
    const int m0   = blockIdx.y * 128;
    const int n0   = blockIdx.x * 128;

    float acc[4][4][4];
    #pragma unroll
    for (int i = 0; i < 4; ++i)
        #pragma unroll
        for (int j = 0; j < 4; ++j)
            #pragma unroll
            for (int l = 0; l < 4; ++l) acc[i][j][l] = 0.f;

    float4 ra[2], rb[2];

    auto loadA = [&](int k0) {
        #pragma unroll
        for (int it = 0; it < 2; ++it) {
            if (AT == 0) {
                int row = (tid >> 2) + it * 64;
                int sub = tid & 3;
                ra[it] = *reinterpret_cast<const float4*>(
                    &A[(long)(m0 + row) * lda + k0 + sub * 4]);
            } else {
                int kk = (tid >> 5) + it * 8;
                int mq = tid & 31;
                ra[it] = *reinterpret_cast<const float4*>(
                    &A[(long)(k0 + kk) * lda + m0 + mq * 4]);
            }
        }
    };
    auto loadB = [&](int k0) {
        #pragma unroll
        for (int it = 0; it < 2; ++it) {
            if (BT == 0) {
                int row = (tid >> 2) + it * 64;
                int sub = tid & 3;
                rb[it] = *reinterpret_cast<const float4*>(
                    &B[(long)(n0 + row) * ldb + k0 + sub * 4]);
            } else {
                int kk = (tid >> 5) + it * 8;
                int nq = tid & 31;
                rb[it] = *reinterpret_cast<const float4*>(
                    &B[(long)(k0 + kk) * ldb + n0 + nq * 4]);
            }
        }
    };
    auto storeA = [&](int s) {
        #pragma unroll
        for (int it = 0; it < 2; ++it) {
            if (AT == 0) {
                int row = (tid >> 2) + it * 64;
                int sub = tid & 3;
                As[s][sub * 4 + 0][row] = f2tf32(ra[it].x);
                As[s][sub * 4 + 1][row] = f2tf32(ra[it].y);
                As[s][sub * 4 + 2][row] = f2tf32(ra[it].z);
                As[s][sub * 4 + 3][row] = f2tf32(ra[it].w);
            } else {
                int kk = (tid >> 5) + it * 8;
                int mq = tid & 31;
                uint4 v;
                v.x = f2tf32(ra[it].x); v.y = f2tf32(ra[it].y);
                v.z = f2tf32(ra[it].z); v.w = f2tf32(ra[it].w);
                *reinterpret_cast<uint4*>(&As[s][kk][mq * 4]) = v;
            }
        }
    };
    auto storeB = [&](int s) {
        #pragma unroll
        for (int it = 0; it < 2; ++it) {
            if (BT == 0) {
                int row = (tid >> 2) + it * 64;
                int sub = tid & 3;
                Bs[s][sub * 4 + 0][row] = f2tf32(rb[it].x);
                Bs[s][sub * 4 + 1][row] = f2tf32(rb[it].y);
                Bs[s][sub * 4 + 2][row] = f2tf32(rb[it].z);
                Bs[s][sub * 4 + 3][row] = f2tf32(rb[it].w);
            } else {
                int kk = (tid >> 5) + it * 8;
                int nq = tid & 31;
                uint4 v;
                v.x = f2tf32(rb[it].x); v.y = f2tf32(rb[it].y);
                v.z = f2tf32(rb[it].z); v.w = f2tf32(rb[it].w);
                *reinterpret_cast<uint4*>(&Bs[s][kk][nq * 4]) = v;
            }
        }
    };
    auto compute = [&](int s) {
        #pragma unroll
        for (int ks = 0; ks < 16; ks += 8) {
            uint32_t af[4][4];
            uint32_t bf[4][2];
            #pragma unroll
            for (int mt = 0; mt < 4; ++mt) {
                int mr = wm * 64 + mt * 16;
                af[mt][0] = As[s][ks + t    ][mr + g    ];
                af[mt][1] = As[s][ks + t    ][mr + g + 8];
                af[mt][2] = As[s][ks + t + 4][mr + g    ];
                af[mt][3] = As[s][ks + t + 4][mr + g + 8];
            }
            #pragma unroll
            for (int nt = 0; nt < 4; ++nt) {
                int nc = wn * 32 + nt * 8;
                bf[nt][0] = Bs[s][ks + t    ][nc + g];
                bf[nt][1] = Bs[s][ks + t + 4][nc + g];
            }
            #pragma unroll
            for (int mt = 0; mt < 4; ++mt)
                #pragma unroll
                for (int nt = 0; nt < 4; ++nt)
                    mma8(acc[mt][nt], af[mt], bf[nt]);
        }
    };

    const int KT = K / 16;
    loadA(0); loadB(0);
    storeA(0); storeB(0);
    __syncthreads();
    for (int kt = 0; kt < KT; ++kt) {
        if (kt + 1 < KT) { loadA((kt + 1) * 16); loadB((kt + 1) * 16); }
        compute(kt & 1);
        if (kt + 1 < KT) {
            storeA((kt + 1) & 1); storeB((kt + 1) & 1);
            __syncthreads();
        }
    }

    // ---------------- epilogue ----------------
    #pragma unroll
    for (int mt = 0; mt < 4; ++mt) {
        int r0 = m0 + wm * 64 + mt * 16 + g;
        float z0 = 1.f, z1 = 1.f;
        if (EPI == 4) { z0 = 1.f / axm[r0]; z1 = 1.f / axm[r0 + 8]; }
        #pragma unroll
        for (int nt = 0; nt < 4; ++nt) {
            int c = n0 + wn * 32 + nt * 8 + t * 2;
            float v0 = acc[mt][nt][0], v1 = acc[mt][nt][1];
            float v2 = acc[mt][nt][2], v3 = acc[mt][nt][3];
            if (EPI == 1 || EPI == 2) {
                float b0 = auxN[c], b1 = auxN[c + 1];
                v0 += b0; v1 += b1; v2 += b0; v3 += b1;
            }
            if (EPI == 2) {   // elu(x)+1 : x>0 -> x+1 else exp(x)
                v0 = v0 > 0.f ? v0 + 1.f : expf(v0);
                v1 = v1 > 0.f ? v1 + 1.f : expf(v1);
                v2 = v2 > 0.f ? v2 + 1.f : expf(v2);
                v3 = v3 > 0.f ? v3 + 1.f : expf(v3);
            }
            if (EPI == 4) {   // v/z + bias
                float b0 = auxN[c], b1 = auxN[c + 1];
                v0 = v0 * z0 + b0; v1 = v1 * z0 + b1;
                v2 = v2 * z1 + b0; v3 = v3 * z1 + b1;
            }
            *reinterpret_cast<float2*>(&C[(long)r0       * ldc + c]) = make_float2(v0, v1);
            *reinterpret_cast<float2*>(&C[(long)(r0 + 8) * ldc + c]) = make_float2(v2, v3);
        }
    }
}

// ---------------- K column-sum (+1e-6) ----------------
__global__ void ksum_init() {
    int i = blockIdx.x * 256 + threadIdx.x;
    g_Ksum[i] = 1e-6f;
}

__global__ void ksum_acc() {
    int b = blockIdx.y;
    int chunk = blockIdx.x;           // 16 chunks of 256 rows
    int d4 = threadIdx.x;             // 0..255 -> float4 column group
    float4 s = make_float4(0.f, 0.f, 0.f, 0.f);
    const float* base = g_Kf + ((long)b * N_SEQ + chunk * 256) * D_DIM + d4 * 4;
    #pragma unroll 4
    for (int n = 0; n < 256; ++n) {
        float4 v = *reinterpret_cast<const float4*>(base + (long)n * D_DIM);
        s.x += v.x; s.y += v.y; s.z += v.z; s.w += v.w;
    }
    float* ks = g_Ksum + b * D_DIM + d4 * 4;
    atomicAdd(ks + 0, s.x);
    atomicAdd(ks + 1, s.y);
    atomicAdd(ks + 2, s.z);
    atomicAdd(ks + 3, s.w);
}

// ---------------- Z[b,n] = Q[b,n,:] . Ksum[b,:] ----------------
__global__ void z_kernel() {
    int warp = threadIdx.x >> 5;
    int lane = threadIdx.x & 31;
    long row = (long)blockIdx.x * 8 + warp;   // 32768 rows total
    int b = (int)(row >> 12);
    const float* q  = g_Q + row * D_DIM;
    const float* ks = g_Ksum + b * D_DIM;
    float s = 0.f;
    #pragma unroll
    for (int i = 0; i < 8; ++i) {
        int d = (lane + i * 32) * 4;
        float4 qv = *reinterpret_cast<const float4*>(&q[d]);
        float4 kv = *reinterpret_cast<const float4*>(&ks[d]);
        s += qv.x * kv.x + qv.y * kv.y + qv.z * kv.z + qv.w * kv.w;
    }
    #pragma unroll
    for (int o = 16; o > 0; o >>= 1) s += __shfl_xor_sync(0xFFFFFFFFu, s, o);
    if (lane == 0) g_Z[row] = s;
}

// ---------------- launch ----------------
extern "C" void kernel_launch(void* const* d_in, const int* in_sizes, int n_in,
                              void* d_out, int out_size)
{
    const float* x  = (const float*)d_in[0];
    const float* Wq = (const float*)d_in[1];
    const float* bq = (const float*)d_in[2];
    const float* Wk = (const float*)d_in[3];
    const float* bk = (const float*)d_in[4];
    const float* Wv = (const float*)d_in[5];
    const float* bv = (const float*)d_in[6];
    const float* Wo = (const float*)d_in[7];
    const float* bo = (const float*)d_in[8];
    float* out = (float*)d_out;

    float *pQ, *pK, *pV, *pKV, *pM, *pZ;
    cudaGetSymbolAddress((void**)&pQ,  g_Q);
    cudaGetSymbolAddress((void**)&pK,  g_Kf);
    cudaGetSymbolAddress((void**)&pV,  g_V);
    cudaGetSymbolAddress((void**)&pKV, g_KV);
    cudaGetSymbolAddress((void**)&pM,  g_M);
    cudaGetSymbolAddress((void**)&pZ,  g_Z);

    dim3 blk(256);
    dim3 gproj(D_DIM / 128, M_FLAT / 128, 1);        // (8, 256)

    // 1) Q/K/V projections: C = X @ W^T  (elu+1 fused on Q,K; bias on V)
    gemm_tf32<0,0,2><<<gproj, blk>>>(x, Wq, pQ, pZ, bq,
        M_FLAT, D_DIM, D_DIM, D_DIM, D_DIM, D_DIM, 0, 0, 0, 0);
    gemm_tf32<0,0,2><<<gproj, blk>>>(x, Wk, pK, pZ, bk,
        M_FLAT, D_DIM, D_DIM, D_DIM, D_DIM, D_DIM, 0, 0, 0, 0);
    gemm_tf32<0,0,1><<<gproj, blk>>>(x, Wv, pV, pZ, bv,
        M_FLAT, D_DIM, D_DIM, D_DIM, D_DIM, D_DIM, 0, 0, 0, 0);

    // 2) Ksum (+eps) and Z
    ksum_init<<<(N_BATCH * D_DIM) / 256, 256>>>();
    ksum_acc<<<dim3(16, N_BATCH), 256>>>();
    z_kernel<<<M_FLAT / 8, 256>>>();

    // 3) KV[b][d,e] = sum_n K[b][n,d] * V[b][n,e]   (M=D, N=D, K=seq)
    gemm_tf32<1,1,0><<<dim3(8, 8, N_BATCH), blk>>>(pK, pV, pKV, pZ, pZ,
        D_DIM, D_DIM, N_SEQ, D_DIM, D_DIM, D_DIM,
        (long)N_SEQ * D_DIM, (long)N_SEQ * D_DIM, (long)D_DIM * D_DIM, 0);

    // 4) M[b][d,f] = sum_e KV[b][d,e] * Wo[f,e]   (17.2 GF total)
    gemm_tf32<0,0,0><<<dim3(8, 8, N_BATCH), blk>>>(pKV, Wo, pM, pZ, pZ,
        D_DIM, D_DIM, D_DIM, D_DIM, D_DIM, D_DIM,
        (long)D_DIM * D_DIM, 0, (long)D_DIM * D_DIM, 0);

    // 5) out[b][n,f] = (sum_d Q[b][n,d] * M[b][d,f]) / Z[b,n] + bo[f]
    gemm_tf32<0,1,4><<<dim3(8, 32, N_BATCH), blk>>>(pQ, pM, out, pZ, bo,
        N_SEQ, D_DIM, D_DIM, D_DIM, D_DIM, D_DIM,
        (long)N_SEQ * D_DIM, (long)D_DIM * D_DIM, (long)N_SEQ * D_DIM, N_SEQ);
}

// round 12
// speedup vs baseline: 2.1737x; 1.5296x over previous
#include <cuda_runtime.h>
#include <cuda_fp16.h>
#include <cstdint>
#include <math.h>

#define D_DIM   1024
#define N_BATCH 8
#define N_SEQ   4096
#define M_FLAT  (N_BATCH * N_SEQ)   // 32768

// ---------------- scratch (device globals: no allocation allowed) ----------
__device__ float g_Q  [(size_t)M_FLAT * D_DIM];           // 134 MB
__device__ float g_Kf [(size_t)M_FLAT * D_DIM];           // feature-mapped K
__device__ float g_V  [(size_t)M_FLAT * D_DIM];
__device__ float g_KV [(size_t)N_BATCH * D_DIM * D_DIM];  // K^T V   [d,e]
__device__ float g_M  [(size_t)N_BATCH * D_DIM * D_DIM];  // KV @ Wo^T [d,f]
__device__ float g_Ksum[N_BATCH * D_DIM];
__device__ float g_Z[M_FLAT];

// ---------------- helpers ----------------
// pack (lo, hi) floats -> fp16x2 word (lo in low half = even-k element)
__device__ __forceinline__ uint32_t f2h2(float lo, float hi) {
    __half2 h = __floats2half2_rn(lo, hi);
    return *reinterpret_cast<uint32_t*>(&h);
}

__device__ __forceinline__ void mma16(float c[4], const uint32_t a[4], const uint32_t b[2]) {
    asm volatile(
        "mma.sync.aligned.m16n8k16.row.col.f32.f16.f16.f32 "
        "{%0,%1,%2,%3}, {%4,%5,%6,%7}, {%8,%9}, {%0,%1,%2,%3};\n"
        : "+f"(c[0]), "+f"(c[1]), "+f"(c[2]), "+f"(c[3])
        : "r"(a[0]), "r"(a[1]), "r"(a[2]), "r"(a[3]), "r"(b[0]), "r"(b[1]));
}

// ---------------- generic fp16-input / fp32-accum GEMM ----------------
// C[M,N] = epilogue( sum_k A[m,k]*B[k,n] ),  f32 in gmem, fp16 in smem/MMA.
// smem layout per operand: [k/2][m] of fp16x2 (even k in low half).
// AT==0: A[m,k] = A[m*lda + k]   (K contiguous)
// AT==1: A[m,k] = A[k*lda + m]   (M contiguous)
// BT==0: B[k,n] = B[n*ldb + k]   (weights, stored [N,K])
// BT==1: B[k,n] = B[k*ldb + n]   (N contiguous)
// EPI: 0 none | 1 +biasN | 2 elu(+biasN)+1 | 4 v/zM + biasN
template<int AT, int BT, int EPI>
__global__ void __launch_bounds__(256, 2)
gemm_f16(const float* __restrict__ Ag, const float* __restrict__ Bg,
         float* __restrict__ Cg,
         const float* __restrict__ auxM, const float* __restrict__ auxN,
         int M, int N, int K, int lda, int ldb, int ldc,
         long sA, long sB, long sC, long sAuxM)
{
    // 2-stage double buffer: 2 * (8*136)*4B * 2 arrays = 17.4 KB
    __shared__ uint32_t As[2][8][136];   // [k2][m] fp16x2, ld=136 conflict-free
    __shared__ uint32_t Bs[2][8][136];   // [k2][n]

    const int bz = blockIdx.z;
    const float* A = Ag + (long)bz * sA;
    const float* B = Bg + (long)bz * sB;
    float*       C = Cg + (long)bz * sC;
    const float* axm = auxM + (long)bz * sAuxM;

    const int tid  = threadIdx.x;
    const int lane = tid & 31;
    const int warp = tid >> 5;
    const int g    = lane >> 2;   // groupID (row within mma tile)
    const int t    = lane & 3;    // threadID_in_group
    const int wm   = warp & 1;    // warp grid 2 (m) x 4 (n)
    const int wn   = warp >> 1;
    const int m0   = blockIdx.y * 128;
    const int n0   = blockIdx.x * 128;

    float acc[4][4][4];
    #pragma unroll
    for (int i = 0; i < 4; ++i)
        #pragma unroll
        for (int j = 0; j < 4; ++j)
            #pragma unroll
            for (int l = 0; l < 4; ++l) acc[i][j][l] = 0.f;

    float4 ra[2], rb[2];

    // AT==0 loader: thread -> rows (tid>>2, +64), k = k0 + (tid&3)*4 .. +3
    // AT==1 loader: thread -> k rows (2*warp, 2*warp+1), m = m0 + (lane)*4 .. +3
    auto loadA = [&](int k0) {
        if (AT == 0) {
            #pragma unroll
            for (int it = 0; it < 2; ++it) {
                int row = (tid >> 2) + it * 64;
                int sub = tid & 3;
                ra[it] = *reinterpret_cast<const float4*>(
                    &A[(long)(m0 + row) * lda + k0 + sub * 4]);
            }
        } else {
            int k2 = tid >> 5;          // 0..7
            int mq = tid & 31;
            #pragma unroll
            for (int it = 0; it < 2; ++it)
                ra[it] = *reinterpret_cast<const float4*>(
                    &A[(long)(k0 + k2 * 2 + it) * lda + m0 + mq * 4]);
        }
    };
    auto loadB = [&](int k0) {
        if (BT == 0) {
            #pragma unroll
            for (int it = 0; it < 2; ++it) {
                int row = (tid >> 2) + it * 64;
                int sub = tid & 3;
                rb[it] = *reinterpret_cast<const float4*>(
                    &B[(long)(n0 + row) * ldb + k0 + sub * 4]);
            }
        } else {
            int k2 = tid >> 5;
            int nq = tid & 31;
            #pragma unroll
            for (int it = 0; it < 2; ++it)
                rb[it] = *reinterpret_cast<const float4*>(
                    &B[(long)(k0 + k2 * 2 + it) * ldb + n0 + nq * 4]);
        }
    };
    auto storeA = [&](int s) {
        if (AT == 0) {
            #pragma unroll
            for (int it = 0; it < 2; ++it) {
                int row = (tid >> 2) + it * 64;
                int sub = tid & 3;
                As[s][sub * 2 + 0][row] = f2h2(ra[it].x, ra[it].y);
                As[s][sub * 2 + 1][row] = f2h2(ra[it].z, ra[it].w);
            }
        } else {
            int k2 = tid >> 5;
            int mq = tid & 31;
            uint4 v;
            v.x = f2h2(ra[0].x, ra[1].x);
            v.y = f2h2(ra[0].y, ra[1].y);
            v.z = f2h2(ra[0].z, ra[1].z);
            v.w = f2h2(ra[0].w, ra[1].w);
            *reinterpret_cast<uint4*>(&As[s][k2][mq * 4]) = v;   // STS.128, cf
        }
    };
    auto storeB = [&](int s) {
        if (BT == 0) {
            #pragma unroll
            for (int it = 0; it < 2; ++it) {
                int row = (tid >> 2) + it * 64;
                int sub = tid & 3;
                Bs[s][sub * 2 + 0][row] = f2h2(rb[it].x, rb[it].y);
                Bs[s][sub * 2 + 1][row] = f2h2(rb[it].z, rb[it].w);
            }
        } else {
            int k2 = tid >> 5;
            int nq = tid & 31;
            uint4 v;
            v.x = f2h2(rb[0].x, rb[1].x);
            v.y = f2h2(rb[0].y, rb[1].y);
            v.z = f2h2(rb[0].z, rb[1].z);
            v.w = f2h2(rb[0].w, rb[1].w);
            *reinterpret_cast<uint4*>(&Bs[s][k2][nq * 4]) = v;
        }
    };
    // one m16n8k16 block consumes the whole 16-K stage
    auto compute = [&](int s) {
        uint32_t af[4][4];
        uint32_t bf[4][2];
        #pragma unroll
        for (int mt = 0; mt < 4; ++mt) {
            int mr = wm * 64 + mt * 16;
            af[mt][0] = As[s][t    ][mr + g    ];
            af[mt][1] = As[s][t    ][mr + g + 8];
            af[mt][2] = As[s][t + 4][mr + g    ];
            af[mt][3] = As[s][t + 4][mr + g + 8];
        }
        #pragma unroll
        for (int nt = 0; nt < 4; ++nt) {
            int nc = wn * 32 + nt * 8;
            bf[nt][0] = Bs[s][t    ][nc + g];
            bf[nt][1] = Bs[s][t + 4][nc + g];
        }
        #pragma unroll
        for (int mt = 0; mt < 4; ++mt)
            #pragma unroll
            for (int nt = 0; nt < 4; ++nt)
                mma16(acc[mt][nt], af[mt], bf[nt]);
    };

    const int KT = K / 16;
    loadA(0); loadB(0);
    storeA(0); storeB(0);
    __syncthreads();
    for (int kt = 0; kt < KT; ++kt) {
        if (kt + 1 < KT) { loadA((kt + 1) * 16); loadB((kt + 1) * 16); }
        compute(kt & 1);
        if (kt + 1 < KT) {
            storeA((kt + 1) & 1); storeB((kt + 1) & 1);
            __syncthreads();
        }
    }

    // ---------------- epilogue (f32 accumulators, unchanged) ----------------
    #pragma unroll
    for (int mt = 0; mt < 4; ++mt) {
        int r0 = m0 + wm * 64 + mt * 16 + g;
        float z0 = 1.f, z1 = 1.f;
        if (EPI == 4) { z0 = 1.f / axm[r0]; z1 = 1.f / axm[r0 + 8]; }
        #pragma unroll
        for (int nt = 0; nt < 4; ++nt) {
            int c = n0 + wn * 32 + nt * 8 + t * 2;
            float v0 = acc[mt][nt][0], v1 = acc[mt][nt][1];
            float v2 = acc[mt][nt][2], v3 = acc[mt][nt][3];
            if (EPI == 1 || EPI == 2) {
                float b0 = auxN[c], b1 = auxN[c + 1];
                v0 += b0; v1 += b1; v2 += b0; v3 += b1;
            }
            if (EPI == 2) {   // elu(x)+1 : x>0 -> x+1 else exp(x)
                v0 = v0 > 0.f ? v0 + 1.f : expf(v0);
                v1 = v1 > 0.f ? v1 + 1.f : expf(v1);
                v2 = v2 > 0.f ? v2 + 1.f : expf(v2);
                v3 = v3 > 0.f ? v3 + 1.f : expf(v3);
            }
            if (EPI == 4) {   // v/z + bias
                float b0 = auxN[c], b1 = auxN[c + 1];
                v0 = v0 * z0 + b0; v1 = v1 * z0 + b1;
                v2 = v2 * z1 + b0; v3 = v3 * z1 + b1;
            }
            *reinterpret_cast<float2*>(&C[(long)r0       * ldc + c]) = make_float2(v0, v1);
            *reinterpret_cast<float2*>(&C[(long)(r0 + 8) * ldc + c]) = make_float2(v2, v3);
        }
    }
}

// ---------------- K column-sum (+1e-6) ----------------
__global__ void ksum_init() {
    int i = blockIdx.x * 256 + threadIdx.x;
    g_Ksum[i] = 1e-6f;
}

__global__ void ksum_acc() {
    int b = blockIdx.y;
    int chunk = blockIdx.x;           // 16 chunks of 256 rows
    int d4 = threadIdx.x;             // 0..255 -> float4 column group
    float4 s = make_float4(0.f, 0.f, 0.f, 0.f);
    const float* base = g_Kf + ((long)b * N_SEQ + chunk * 256) * D_DIM + d4 * 4;
    #pragma unroll 4
    for (int n = 0; n < 256; ++n) {
        float4 v = *reinterpret_cast<const float4*>(base + (long)n * D_DIM);
        s.x += v.x; s.y += v.y; s.z += v.z; s.w += v.w;
    }
    float* ks = g_Ksum + b * D_DIM + d4 * 4;
    atomicAdd(ks + 0, s.x);
    atomicAdd(ks + 1, s.y);
    atomicAdd(ks + 2, s.z);
    atomicAdd(ks + 3, s.w);
}

// ---------------- Z[b,n] = Q[b,n,:] . Ksum[b,:] ----------------
__global__ void z_kernel() {
    int warp = threadIdx.x >> 5;
    int lane = threadIdx.x & 31;
    long row = (long)blockIdx.x * 8 + warp;   // 32768 rows total
    int b = (int)(row >> 12);
    const float* q  = g_Q + row * D_DIM;
    const float* ks = g_Ksum + b * D_DIM;
    float s = 0.f;
    #pragma unroll
    for (int i = 0; i < 8; ++i) {
        int d = (lane + i * 32) * 4;
        float4 qv = *reinterpret_cast<const float4*>(&q[d]);
        float4 kv = *reinterpret_cast<const float4*>(&ks[d]);
        s += qv.x * kv.x + qv.y * kv.y + qv.z * kv.z + qv.w * kv.w;
    }
    #pragma unroll
    for (int o = 16; o > 0; o >>= 1) s += __shfl_xor_sync(0xFFFFFFFFu, s, o);
    if (lane == 0) g_Z[row] = s;
}

// ---------------- launch ----------------
extern "C" void kernel_launch(void* const* d_in, const int* in_sizes, int n_in,
                              void* d_out, int out_size)
{
    const float* x  = (const float*)d_in[0];
    const float* Wq = (const float*)d_in[1];
    const float* bq = (const float*)d_in[2];
    const float* Wk = (const float*)d_in[3];
    const float* bk = (const float*)d_in[4];
    const float* Wv = (const float*)d_in[5];
    const float* bv = (const float*)d_in[6];
    const float* Wo = (const float*)d_in[7];
    const float* bo = (const float*)d_in[8];
    float* out = (float*)d_out;

    float *pQ, *pK, *pV, *pKV, *pM, *pZ;
    cudaGetSymbolAddress((void**)&pQ,  g_Q);
    cudaGetSymbolAddress((void**)&pK,  g_Kf);
    cudaGetSymbolAddress((void**)&pV,  g_V);
    cudaGetSymbolAddress((void**)&pKV, g_KV);
    cudaGetSymbolAddress((void**)&pM,  g_M);
    cudaGetSymbolAddress((void**)&pZ,  g_Z);

    dim3 blk(256);
    dim3 gproj(D_DIM / 128, M_FLAT / 128, 1);        // (8, 256)

    // 1) Q/K/V projections: C = X @ W^T  (elu+1 fused on Q,K; bias on V)
    gemm_f16<0,0,2><<<gproj, blk>>>(x, Wq, pQ, pZ, bq,
        M_FLAT, D_DIM, D_DIM, D_DIM, D_DIM, D_DIM, 0, 0, 0, 0);
    gemm_f16<0,0,2><<<gproj, blk>>>(x, Wk, pK, pZ, bk,
        M_FLAT, D_DIM, D_DIM, D_DIM, D_DIM, D_DIM, 0, 0, 0, 0);
    gemm_f16<0,0,1><<<gproj, blk>>>(x, Wv, pV, pZ, bv,
        M_FLAT, D_DIM, D_DIM, D_DIM, D_DIM, D_DIM, 0, 0, 0, 0);

    // 2) Ksum (+eps) and Z
    ksum_init<<<(N_BATCH * D_DIM) / 256, 256>>>();
    ksum_acc<<<dim3(16, N_BATCH), 256>>>();
    z_kernel<<<M_FLAT / 8, 256>>>();

    // 3) KV[b][d,e] = sum_n K[b][n,d] * V[b][n,e]   (M=D, N=D, K=seq)
    gemm_f16<1,1,0><<<dim3(8, 8, N_BATCH), blk>>>(pK, pV, pKV, pZ, pZ,
        D_DIM, D_DIM, N_SEQ, D_DIM, D_DIM, D_DIM,
        (long)N_SEQ * D_DIM, (long)N_SEQ * D_DIM, (long)D_DIM * D_DIM, 0);

    // 4) M[b][d,f] = sum_e KV[b][d,e] * Wo[f,e]   (17.2 GF total)
    gemm_f16<0,0,0><<<dim3(8, 8, N_BATCH), blk>>>(pKV, Wo, pM, pZ, pZ,
        D_DIM, D_DIM, D_DIM, D_DIM, D_DIM, D_DIM,
        (long)D_DIM * D_DIM, 0, (long)D_DIM * D_DIM, 0);

    // 5) out[b][n,f] = (sum_d Q[b][n,d] * M[b][d,f]) / Z[b,n] + bo[f]
    gemm_f16<0,1,4><<<dim3(8, 32, N_BATCH), blk>>>(pQ, pM, out, pZ, bo,
        N_SEQ, D_DIM, D_DIM, D_DIM, D_DIM, D_DIM,
        (long)N_SEQ * D_DIM, (long)D_DIM * D_DIM, (long)N_SEQ * D_DIM, N_SEQ);
}

// round 13
// speedup vs baseline: 2.2181x; 1.0204x over previous
#include <cuda_runtime.h>
#include <cuda_fp16.h>
#include <cstdint>
#include <math.h>

#define D_DIM   1024
#define N_BATCH 8
#define N_SEQ   4096
#define M_FLAT  (N_BATCH * N_SEQ)   // 32768

// ---------------- scratch (device globals: no allocation allowed) ----------
__device__ __half g_Q  [(size_t)M_FLAT * D_DIM];           // 67 MB
__device__ __half g_Kf [(size_t)M_FLAT * D_DIM];
__device__ __half g_V  [(size_t)M_FLAT * D_DIM];
__device__ __half g_KV [(size_t)N_BATCH * D_DIM * D_DIM];  // K^T V [d,e]
__device__ __half g_M  [(size_t)N_BATCH * D_DIM * D_DIM];  // KV @ Wo^T [d,f]
__device__ float  g_Ksum[N_BATCH * D_DIM];
__device__ float  g_Z[M_FLAT];

// ---------------- helpers ----------------
__device__ __forceinline__ uint32_t f2h2(float lo, float hi) {
    __half2 h = __floats2half2_rn(lo, hi);
    return *reinterpret_cast<uint32_t*>(&h);
}

__device__ __forceinline__ void mma16(float c[4], const uint32_t a[4], const uint32_t b[2]) {
    asm volatile(
        "mma.sync.aligned.m16n8k16.row.col.f32.f16.f16.f32 "
        "{%0,%1,%2,%3}, {%4,%5,%6,%7}, {%8,%9}, {%0,%1,%2,%3};\n"
        : "+f"(c[0]), "+f"(c[1]), "+f"(c[2]), "+f"(c[3])
        : "r"(a[0]), "r"(a[1]), "r"(a[2]), "r"(a[3]), "r"(b[0]), "r"(b[1]));
}

// ---------------- generic mixed-type fp16-MMA GEMM ----------------
// C[M,N] = epilogue( sum_k A[m,k]*B[k,n] ); fp16 in smem/MMA, f32 accum.
// smem per operand: [k/2][m] fp16x2 words (even k in low half), ld=136 words.
// AT==0: A[m,k] = A[m*lda + k]  (K contiguous)    TA = float or __half
// AT==1: A[m,k] = A[k*lda + m]  (M contiguous)    TA = __half only
// BT==0: B[k,n] = B[n*ldb + k]  (weights [N,K])   TB = float only
// BT==1: B[k,n] = B[k*ldb + n]  (N contiguous)    TB = __half only
// EPI: 0 none | 1 +biasN | 2 elu(+biasN)+1 | 4 v/zM + biasN
// TC: __half (intermediates) or float (final out)
template<int AT, int BT, int EPI, typename TA, typename TB, typename TC>
__global__ void __launch_bounds__(256, 2)
gemm_h(const TA* __restrict__ Ag, const TB* __restrict__ Bg,
       TC* __restrict__ Cg,
       const float* __restrict__ auxM, const float* __restrict__ auxN,
       int M, int N, int K, int lda, int ldb, int ldc,
       long sA, long sB, long sC, long sAuxM)
{
    __shared__ uint32_t As[2][8][136];   // [k2][m] fp16x2
    __shared__ uint32_t Bs[2][8][136];   // [k2][n]

    const int bz = blockIdx.z;
    const TA* A = Ag + (long)bz * sA;
    const TB* B = Bg + (long)bz * sB;
    TC*       C = Cg + (long)bz * sC;
    const float* axm = auxM + (long)bz * sAuxM;

    const int tid  = threadIdx.x;
    const int lane = tid & 31;
    const int warp = tid >> 5;
    const int g    = lane >> 2;
    const int t    = lane & 3;
    const int wm   = warp & 1;          // 2 (m) x 4 (n) warp grid
    const int wn   = warp >> 1;
    const int m0   = blockIdx.y * 128;
    const int n0   = blockIdx.x * 128;

    float acc[4][4][4];
    #pragma unroll
    for (int i = 0; i < 4; ++i)
        #pragma unroll
        for (int j = 0; j < 4; ++j)
            #pragma unroll
            for (int l = 0; l < 4; ++l) acc[i][j][l] = 0.f;

    // load buffers (unused ones are optimized away)
    float4 raf[2], rbf[2];      // float operand paths
    uint4  rah;                 // half AT=0 path (8 halves)
    uint2  ral[2];              // half AT=1 path (2 k-rows x 4 halves)
    uint2  rbl[2];              // half BT=1 path

    auto loadA = [&](int k0) {
        if (sizeof(TA) == 4) {          // float, AT==0
            #pragma unroll
            for (int it = 0; it < 2; ++it) {
                int row = (tid >> 2) + it * 64;
                int sub = tid & 3;
                raf[it] = *reinterpret_cast<const float4*>(
                    (const float*)A + (long)(m0 + row) * lda + k0 + sub * 4);
            }
        } else if (AT == 0) {           // half, K contiguous
            int row = tid >> 1;         // 0..127
            int sub = tid & 1;          // k half: 8 halves each
            rah = *reinterpret_cast<const uint4*>(
                (const __half*)A + (long)(m0 + row) * lda + k0 + sub * 8);
        } else {                        // half, M contiguous
            int k2 = tid >> 5;          // 0..7
            int mq = tid & 31;          // 4 halves each
            #pragma unroll
            for (int it = 0; it < 2; ++it)
                ral[it] = *reinterpret_cast<const uint2*>(
                    (const __half*)A + (long)(k0 + k2 * 2 + it) * lda + m0 + mq * 4);
        }
    };
    auto loadB = [&](int k0) {
        if (sizeof(TB) == 4) {          // float, BT==0
            #pragma unroll
            for (int it = 0; it < 2; ++it) {
                int row = (tid >> 2) + it * 64;
                int sub = tid & 3;
                rbf[it] = *reinterpret_cast<const float4*>(
                    (const float*)B + (long)(n0 + row) * ldb + k0 + sub * 4);
            }
        } else {                        // half, BT==1 (N contiguous)
            int k2 = tid >> 5;
            int nq = tid & 31;
            #pragma unroll
            for (int it = 0; it < 2; ++it)
                rbl[it] = *reinterpret_cast<const uint2*>(
                    (const __half*)B + (long)(k0 + k2 * 2 + it) * ldb + n0 + nq * 4);
        }
    };
    auto storeA = [&](int s) {
        if (sizeof(TA) == 4) {
            #pragma unroll
            for (int it = 0; it < 2; ++it) {
                int row = (tid >> 2) + it * 64;
                int sub = tid & 3;
                As[s][sub * 2 + 0][row] = f2h2(raf[it].x, raf[it].y);
                As[s][sub * 2 + 1][row] = f2h2(raf[it].z, raf[it].w);
            }
        } else if (AT == 0) {           // gmem fp16 pairs are already smem words
            int row = tid >> 1;
            int sub = tid & 1;
            As[s][sub * 4 + 0][row] = rah.x;
            As[s][sub * 4 + 1][row] = rah.y;
            As[s][sub * 4 + 2][row] = rah.z;
            As[s][sub * 4 + 3][row] = rah.w;
        } else {                        // interleave two k-rows into fp16x2 words
            int k2 = tid >> 5;
            int mq = tid & 31;
            uint4 v;
            v.x = __byte_perm(ral[0].x, ral[1].x, 0x5410);
            v.y = __byte_perm(ral[0].x, ral[1].x, 0x7632);
            v.z = __byte_perm(ral[0].y, ral[1].y, 0x5410);
            v.w = __byte_perm(ral[0].y, ral[1].y, 0x7632);
            *reinterpret_cast<uint4*>(&As[s][k2][mq * 4]) = v;
        }
    };
    auto storeB = [&](int s) {
        if (sizeof(TB) == 4) {
            #pragma unroll
            for (int it = 0; it < 2; ++it) {
                int row = (tid >> 2) + it * 64;
                int sub = tid & 3;
                Bs[s][sub * 2 + 0][row] = f2h2(rbf[it].x, rbf[it].y);
                Bs[s][sub * 2 + 1][row] = f2h2(rbf[it].z, rbf[it].w);
            }
        } else {
            int k2 = tid >> 5;
            int nq = tid & 31;
            uint4 v;
            v.x = __byte_perm(rbl[0].x, rbl[1].x, 0x5410);
            v.y = __byte_perm(rbl[0].x, rbl[1].x, 0x7632);
            v.z = __byte_perm(rbl[0].y, rbl[1].y, 0x5410);
            v.w = __byte_perm(rbl[0].y, rbl[1].y, 0x7632);
            *reinterpret_cast<uint4*>(&Bs[s][k2][nq * 4]) = v;
        }
    };
    auto compute = [&](int s) {
        uint32_t af[4][4];
        uint32_t bf[4][2];
        #pragma unroll
        for (int mt = 0; mt < 4; ++mt) {
            int mr = wm * 64 + mt * 16;
            af[mt][0] = As[s][t    ][mr + g    ];
            af[mt][1] = As[s][t    ][mr + g + 8];
            af[mt][2] = As[s][t + 4][mr + g    ];
            af[mt][3] = As[s][t + 4][mr + g + 8];
        }
        #pragma unroll
        for (int nt = 0; nt < 4; ++nt) {
            int nc = wn * 32 + nt * 8;
            bf[nt][0] = Bs[s][t    ][nc + g];
            bf[nt][1] = Bs[s][t + 4][nc + g];
        }
        #pragma unroll
        for (int mt = 0; mt < 4; ++mt)
            #pragma unroll
            for (int nt = 0; nt < 4; ++nt)
                mma16(acc[mt][nt], af[mt], bf[nt]);
    };

    const int KT = K / 16;
    loadA(0); loadB(0);
    storeA(0); storeB(0);
    __syncthreads();
    for (int kt = 0; kt < KT; ++kt) {
        if (kt + 1 < KT) { loadA((kt + 1) * 16); loadB((kt + 1) * 16); }
        compute(kt & 1);
        if (kt + 1 < KT) {
            storeA((kt + 1) & 1); storeB((kt + 1) & 1);
            __syncthreads();
        }
    }

    // ---------------- epilogue ----------------
    #pragma unroll
    for (int mt = 0; mt < 4; ++mt) {
        int r0 = m0 + wm * 64 + mt * 16 + g;
        float z0 = 1.f, z1 = 1.f;
        if (EPI == 4) { z0 = 1.f / axm[r0]; z1 = 1.f / axm[r0 + 8]; }
        #pragma unroll
        for (int nt = 0; nt < 4; ++nt) {
            int c = n0 + wn * 32 + nt * 8 + t * 2;
            float v0 = acc[mt][nt][0], v1 = acc[mt][nt][1];
            float v2 = acc[mt][nt][2], v3 = acc[mt][nt][3];
            if (EPI == 1 || EPI == 2) {
                float b0 = auxN[c], b1 = auxN[c + 1];
                v0 += b0; v1 += b1; v2 += b0; v3 += b1;
            }
            if (EPI == 2) {   // elu(x)+1 : x>0 -> x+1 else exp(x)
                v0 = v0 > 0.f ? v0 + 1.f : expf(v0);
                v1 = v1 > 0.f ? v1 + 1.f : expf(v1);
                v2 = v2 > 0.f ? v2 + 1.f : expf(v2);
                v3 = v3 > 0.f ? v3 + 1.f : expf(v3);
            }
            if (EPI == 4) {   // v/z + bias
                float b0 = auxN[c], b1 = auxN[c + 1];
                v0 = v0 * z0 + b0; v1 = v1 * z0 + b1;
                v2 = v2 * z1 + b0; v3 = v3 * z1 + b1;
            }
            if (sizeof(TC) == 2) {
                __half2* cp0 = reinterpret_cast<__half2*>((__half*)C + (long)r0 * ldc + c);
                __half2* cp1 = reinterpret_cast<__half2*>((__half*)C + (long)(r0 + 8) * ldc + c);
                *cp0 = __floats2half2_rn(v0, v1);
                *cp1 = __floats2half2_rn(v2, v3);
            } else {
                *reinterpret_cast<float2*>((float*)C + (long)r0       * ldc + c) = make_float2(v0, v1);
                *reinterpret_cast<float2*>((float*)C + (long)(r0 + 8) * ldc + c) = make_float2(v2, v3);
            }
        }
    }
}

// ---------------- unpack 8 halves -> 8 floats ----------------
__device__ __forceinline__ void h8f(const uint4& u, float* f) {
    const __half2* h = reinterpret_cast<const __half2*>(&u);
    #pragma unroll
    for (int i = 0; i < 4; ++i) {
        float2 t = __half22float2(h[i]);
        f[2 * i] = t.x; f[2 * i + 1] = t.y;
    }
}

// ---------------- K column-sum (+1e-6) ----------------
__global__ void ksum_init() {
    int i = blockIdx.x * 256 + threadIdx.x;
    g_Ksum[i] = 1e-6f;
}

__global__ void ksum_acc() {
    int b = blockIdx.y;
    int chunk = blockIdx.x;               // 16 chunks of 256 rows
    int c8 = threadIdx.x;                 // 0..127 -> 8 columns each
    float s[8];
    #pragma unroll
    for (int j = 0; j < 8; ++j) s[j] = 0.f;
    const __half* base = g_Kf + ((long)b * N_SEQ + chunk * 256) * D_DIM + c8 * 8;
    for (int n = 0; n < 256; ++n) {
        uint4 u = *reinterpret_cast<const uint4*>(base + (long)n * D_DIM);
        float f[8]; h8f(u, f);
        #pragma unroll
        for (int j = 0; j < 8; ++j) s[j] += f[j];
    }
    float* ks = g_Ksum + b * D_DIM + c8 * 8;
    #pragma unroll
    for (int j = 0; j < 8; ++j) atomicAdd(ks + j, s[j]);
}

// ---------------- Z[b,n] = Q[b,n,:] . Ksum[b,:] ----------------
__global__ void z_kernel() {
    int warp = threadIdx.x >> 5;
    int lane = threadIdx.x & 31;
    long row = (long)blockIdx.x * 8 + warp;   // 32768 rows
    int b = (int)(row >> 12);
    const __half* q  = g_Q + row * D_DIM;
    const float*  ks = g_Ksum + b * D_DIM;
    float s = 0.f;
    #pragma unroll
    for (int i = 0; i < 4; ++i) {
        int d = (lane + i * 32) * 8;
        uint4 u = *reinterpret_cast<const uint4*>(q + d);
        float f[8]; h8f(u, f);
        float4 k0 = *reinterpret_cast<const float4*>(&ks[d]);
        float4 k1 = *reinterpret_cast<const float4*>(&ks[d + 4]);
        s += f[0] * k0.x + f[1] * k0.y + f[2] * k0.z + f[3] * k0.w
           + f[4] * k1.x + f[5] * k1.y + f[6] * k1.z + f[7] * k1.w;
    }
    #pragma unroll
    for (int o = 16; o > 0; o >>= 1) s += __shfl_xor_sync(0xFFFFFFFFu, s, o);
    if (lane == 0) g_Z[row] = s;
}

// ---------------- launch ----------------
extern "C" void kernel_launch(void* const* d_in, const int* in_sizes, int n_in,
                              void* d_out, int out_size)
{
    const float* x  = (const float*)d_in[0];
    const float* Wq = (const float*)d_in[1];
    const float* bq = (const float*)d_in[2];
    const float* Wk = (const float*)d_in[3];
    const float* bk = (const float*)d_in[4];
    const float* Wv = (const float*)d_in[5];
    const float* bv = (const float*)d_in[6];
    const float* Wo = (const float*)d_in[7];
    const float* bo = (const float*)d_in[8];
    float* out = (float*)d_out;

    __half *pQ, *pK, *pV, *pKV, *pM;
    float *pZ;
    cudaGetSymbolAddress((void**)&pQ,  g_Q);
    cudaGetSymbolAddress((void**)&pK,  g_Kf);
    cudaGetSymbolAddress((void**)&pV,  g_V);
    cudaGetSymbolAddress((void**)&pKV, g_KV);
    cudaGetSymbolAddress((void**)&pM,  g_M);
    cudaGetSymbolAddress((void**)&pZ,  g_Z);

    dim3 blk(256);
    dim3 gproj(D_DIM / 128, M_FLAT / 128, 1);        // (8, 256)

    // 1) Q/K/V projections: C = X @ W^T  (elu+1 fused on Q,K; bias on V) -> fp16
    gemm_h<0,0,2,float,float,__half><<<gproj, blk>>>(x, Wq, pQ, pZ, bq,
        M_FLAT, D_DIM, D_DIM, D_DIM, D_DIM, D_DIM, 0, 0, 0, 0);
    gemm_h<0,0,2,float,float,__half><<<gproj, blk>>>(x, Wk, pK, pZ, bk,
        M_FLAT, D_DIM, D_DIM, D_DIM, D_DIM, D_DIM, 0, 0, 0, 0);
    gemm_h<0,0,1,float,float,__half><<<gproj, blk>>>(x, Wv, pV, pZ, bv,
        M_FLAT, D_DIM, D_DIM, D_DIM, D_DIM, D_DIM, 0, 0, 0, 0);

    // 2) Ksum (+eps) and Z
    ksum_init<<<(N_BATCH * D_DIM) / 256, 256>>>();
    ksum_acc<<<dim3(16, N_BATCH), 128>>>();
    z_kernel<<<M_FLAT / 8, 256>>>();

    // 3) KV[b][d,e] = sum_n K[b][n,d] * V[b][n,e]   (fp16 in/out, K=4096)
    gemm_h<1,1,0,__half,__half,__half><<<dim3(8, 8, N_BATCH), blk>>>(pK, pV, pKV, pZ, pZ,
        D_DIM, D_DIM, N_SEQ, D_DIM, D_DIM, D_DIM,
        (long)N_SEQ * D_DIM, (long)N_SEQ * D_DIM, (long)D_DIM * D_DIM, 0);

    // 4) M[b][d,f] = sum_e KV[b][d,e] * Wo[f,e]
    gemm_h<0,0,0,__half,float,__half><<<dim3(8, 8, N_BATCH), blk>>>(pKV, Wo, pM, pZ, pZ,
        D_DIM, D_DIM, D_DIM, D_DIM, D_DIM, D_DIM,
        (long)D_DIM * D_DIM, 0, (long)D_DIM * D_DIM, 0);

    // 5) out[b][n,f] = (sum_d Q[b][n,d] * M[b][d,f]) / Z[b,n] + bo[f]   -> f32
    gemm_h<0,1,4,__half,__half,float><<<dim3(8, 32, N_BATCH), blk>>>(pQ, pM, out, pZ, bo,
        N_SEQ, D_DIM, D_DIM, D_DIM, D_DIM, D_DIM,
        (long)N_SEQ * D_DIM, (long)D_DIM * D_DIM, (long)N_SEQ * D_DIM, N_SEQ);
}

// round 14
// speedup vs baseline: 2.6205x; 1.1814x over previous
#include <cuda_runtime.h>
#include <cuda_fp16.h>
#include <cstdint>
#include <math.h>

#define D_DIM   1024
#define N_BATCH 8
#define N_SEQ   4096
#define M_FLAT  (N_BATCH * N_SEQ)   // 32768

// smem geometry (halves): K-contig stage = 128 rows x 40 (16 data + pad);
// M/N-contig stage = 32 k-rows x 136 (128 data + pad). Both <= 5120 halves.
#define ST_HALVES 5120

// ---------------- scratch (device globals: no allocation allowed) ----------
__device__ __half g_Q  [(size_t)M_FLAT * D_DIM];
__device__ __half g_Kf [(size_t)M_FLAT * D_DIM];
__device__ __half g_V  [(size_t)M_FLAT * D_DIM];
__device__ __half g_KV [(size_t)N_BATCH * D_DIM * D_DIM];  // K^T V [d,e]
__device__ __half g_M  [(size_t)N_BATCH * D_DIM * D_DIM];  // KV @ Wo^T [d,f]
__device__ float  g_Ksum[N_BATCH * D_DIM];
__device__ float  g_Z[M_FLAT];

// ---------------- helpers ----------------
__device__ __forceinline__ uint32_t f2h2(float lo, float hi) {
    __half2 h = __floats2half2_rn(lo, hi);
    return *reinterpret_cast<uint32_t*>(&h);
}

__device__ __forceinline__ uint32_t smem_u32(const void* p) {
    uint32_t a;
    asm("{ .reg .u64 t; cvta.to.shared.u64 t, %1; cvt.u32.u64 %0, t; }" : "=r"(a) : "l"(p));
    return a;
}

__device__ __forceinline__ void mma16(float c[4], const uint32_t a[4], const uint32_t b[2]) {
    asm volatile(
        "mma.sync.aligned.m16n8k16.row.col.f32.f16.f16.f32 "
        "{%0,%1,%2,%3}, {%4,%5,%6,%7}, {%8,%9}, {%0,%1,%2,%3};\n"
        : "+f"(c[0]), "+f"(c[1]), "+f"(c[2]), "+f"(c[3])
        : "r"(a[0]), "r"(a[1]), "r"(a[2]), "r"(a[3]), "r"(b[0]), "r"(b[1]));
}

__device__ __forceinline__ void ldmx4(uint32_t* r, uint32_t a) {
    asm volatile("ldmatrix.sync.aligned.m8n8.x4.shared.b16 {%0,%1,%2,%3}, [%4];"
                 : "=r"(r[0]), "=r"(r[1]), "=r"(r[2]), "=r"(r[3]) : "r"(a));
}
__device__ __forceinline__ void ldmx4t(uint32_t* r, uint32_t a) {
    asm volatile("ldmatrix.sync.aligned.m8n8.x4.trans.shared.b16 {%0,%1,%2,%3}, [%4];"
                 : "=r"(r[0]), "=r"(r[1]), "=r"(r[2]), "=r"(r[3]) : "r"(a));
}
__device__ __forceinline__ void ldmx2(uint32_t* r, uint32_t a) {
    asm volatile("ldmatrix.sync.aligned.m8n8.x2.shared.b16 {%0,%1}, [%2];"
                 : "=r"(r[0]), "=r"(r[1]) : "r"(a));
}
__device__ __forceinline__ void ldmx2t(uint32_t* r, uint32_t a) {
    asm volatile("ldmatrix.sync.aligned.m8n8.x2.trans.shared.b16 {%0,%1}, [%2];"
                 : "=r"(r[0]), "=r"(r[1]) : "r"(a));
}

// ---------------- generic fp16-MMA GEMM, ldmatrix fragments, BK=32 ----------
// C[M,N] = epilogue( sum_k A[m,k]*B[k,n] ); fp16 smem/MMA, f32 accum.
// A: float (AT=0, K-contig) | half AT=0 (K-contig) | half AT=1 (M-contig)
// B: float (BT=0, [N,K] K-contig) | half BT=1 ([K,N] N-contig)
// smem: K-contig operand stored [row][k] pitch 40 halves (ldmatrix non-trans);
//       M/N-contig stored [k][row] pitch 136 halves (ldmatrix .trans).
// EPI: 0 none | 1 +biasN | 2 elu(+biasN)+1 | 4 v/zM + biasN
template<int AT, int BT, int EPI, typename TA, typename TB, typename TC>
__global__ void __launch_bounds__(256, 2)
gemm_h(const TA* __restrict__ Ag, const TB* __restrict__ Bg,
       TC* __restrict__ Cg,
       const float* __restrict__ auxM, const float* __restrict__ auxN,
       int M, int N, int K, int lda, int ldb, int ldc,
       long sA, long sB, long sC, long sAuxM)
{
    __shared__ __align__(16) __half sm[2][2][ST_HALVES];   // [stage][op] 40.0 KB

    const int bz = blockIdx.z;
    const TA* A = Ag + (long)bz * sA;
    const TB* B = Bg + (long)bz * sB;
    TC*       C = Cg + (long)bz * sC;
    const float* axm = auxM + (long)bz * sAuxM;

    const int tid  = threadIdx.x;
    const int lane = tid & 31;
    const int warp = tid >> 5;
    const int g    = lane >> 2;
    const int t    = lane & 3;
    const int wm   = warp & 1;          // 2 (m) x 4 (n) warp grid
    const int wn   = warp >> 1;
    const int m0   = blockIdx.y * 128;
    const int n0   = blockIdx.x * 128;

    const uint32_t sbase = smem_u32(sm);

    float acc[4][4][4];
    #pragma unroll
    for (int i = 0; i < 4; ++i)
        #pragma unroll
        for (int j = 0; j < 4; ++j)
            #pragma unroll
            for (int l = 0; l < 4; ++l) acc[i][j][l] = 0.f;

    // lane-level byte offsets for ldmatrix (within one operand stage)
    // K-contig (pitch 40 halves = 80 B): x4 rows (lane&15), k-chunk (lane>>4)*16B
    const uint32_t akc = (uint32_t)((lane & 15) * 80 + (lane >> 4) * 16);
    const uint32_t bkc = (uint32_t)((lane & 7) * 80 + ((lane >> 3) & 1) * 16);
    // M/N-contig (pitch 136 halves = 272 B): x4 k-rows (lane&7)+(lane>>4)*8, m-chunk ((lane>>3)&1)*8
    const uint32_t amc = (uint32_t)(((lane & 7) + (lane >> 4) * 8) * 272 + ((lane >> 3) & 1) * 16);
    const uint32_t bmc = (uint32_t)(((lane & 7) + ((lane >> 3) & 1) * 8) * 272);

    // prefetch register buffers
    float4 rf[4];   // float K-contig (4 x float4 = 2 rows x 2 k-halves)
    uint4  rh[2];   // half  K-contig (2 x 8 halves)
    uint4  rm[2];   // half  M-contig (2 x 8 halves)
    float4 rgf[4];  // float B
    uint4  rgm[2];  // half  B (M/N-contig)

    auto loadA = [&](int k0) {
        if (sizeof(TA) == 4) {
            #pragma unroll
            for (int it = 0; it < 2; ++it)
                #pragma unroll
                for (int kh = 0; kh < 2; ++kh)
                    rf[it * 2 + kh] = *reinterpret_cast<const float4*>(
                        (const float*)A + (long)(m0 + (tid >> 2) + it * 64) * lda
                        + k0 + kh * 16 + (tid & 3) * 4);
        } else if (AT == 0) {
            int row = tid >> 1, hf = tid & 1;
            #pragma unroll
            for (int it = 0; it < 2; ++it)
                rh[it] = *reinterpret_cast<const uint4*>(
                    (const __half*)A + (long)(m0 + row) * lda + k0 + hf * 16 + it * 8);
        } else {
            int kk = tid >> 3, mq = tid & 7;
            #pragma unroll
            for (int it = 0; it < 2; ++it)
                rm[it] = *reinterpret_cast<const uint4*>(
                    (const __half*)A + (long)(k0 + kk) * lda + m0 + mq * 16 + it * 8);
        }
    };
    auto loadB = [&](int k0) {
        if (sizeof(TB) == 4) {
            #pragma unroll
            for (int it = 0; it < 2; ++it)
                #pragma unroll
                for (int kh = 0; kh < 2; ++kh)
                    rgf[it * 2 + kh] = *reinterpret_cast<const float4*>(
                        (const float*)B + (long)(n0 + (tid >> 2) + it * 64) * ldb
                        + k0 + kh * 16 + (tid & 3) * 4);
        } else {
            int kk = tid >> 3, nq = tid & 7;
            #pragma unroll
            for (int it = 0; it < 2; ++it)
                rgm[it] = *reinterpret_cast<const uint4*>(
                    (const __half*)B + (long)(k0 + kk) * ldb + n0 + nq * 16 + it * 8);
        }
    };
    auto storeA = [&](int s) {
        uint32_t* w = (uint32_t*)&sm[s][0][0];
        if (sizeof(TA) == 4) {
            #pragma unroll
            for (int it = 0; it < 2; ++it)
                #pragma unroll
                for (int kh = 0; kh < 2; ++kh) {
                    const float4& v = rf[it * 2 + kh];
                    uint2 u = make_uint2(f2h2(v.x, v.y), f2h2(v.z, v.w));
                    *reinterpret_cast<uint2*>(
                        &w[((tid >> 2) + it * 64) * 20 + kh * 8 + (tid & 3) * 2]) = u;
                }
        } else if (AT == 0) {
            int row = tid >> 1, hf = tid & 1;
            #pragma unroll
            for (int it = 0; it < 2; ++it)
                *reinterpret_cast<uint4*>(&w[row * 20 + hf * 8 + it * 4]) = rh[it];
        } else {
            int kk = tid >> 3, mq = tid & 7;
            #pragma unroll
            for (int it = 0; it < 2; ++it)
                *reinterpret_cast<uint4*>(&w[kk * 68 + mq * 8 + it * 4]) = rm[it];
        }
    };
    auto storeB = [&](int s) {
        uint32_t* w = (uint32_t*)&sm[s][1][0];
        if (sizeof(TB) == 4) {
            #pragma unroll
            for (int it = 0; it < 2; ++it)
                #pragma unroll
                for (int kh = 0; kh < 2; ++kh) {
                    const float4& v = rgf[it * 2 + kh];
                    uint2 u = make_uint2(f2h2(v.x, v.y), f2h2(v.z, v.w));
                    *reinterpret_cast<uint2*>(
                        &w[((tid >> 2) + it * 64) * 20 + kh * 8 + (tid & 3) * 2]) = u;
                }
        } else {
            int kk = tid >> 3, nq = tid & 7;
            #pragma unroll
            for (int it = 0; it < 2; ++it)
                *reinterpret_cast<uint4*>(&w[kk * 68 + nq * 8 + it * 4]) = rgm[it];
        }
    };
    auto compute = [&](int s) {
        uint32_t sA_ = sbase + (uint32_t)((s * 2 + 0) * ST_HALVES * 2);
        uint32_t sB_ = sbase + (uint32_t)((s * 2 + 1) * ST_HALVES * 2);
        #pragma unroll
        for (int ks = 0; ks < 2; ++ks) {     // two 16-K steps per BK=32 stage
            uint32_t af[4][4];
            uint32_t bf[4][2];
            #pragma unroll
            for (int mt = 0; mt < 4; ++mt) {
                int mr = wm * 64 + mt * 16;
                if (AT == 0)
                    ldmx4(af[mt], sA_ + (uint32_t)(mr * 80) + akc + (uint32_t)(ks * 32));
                else
                    ldmx4t(af[mt], sA_ + (uint32_t)(ks * 16 * 272) + amc + (uint32_t)(mr * 2));
            }
            #pragma unroll
            for (int nt = 0; nt < 4; ++nt) {
                int nc = wn * 32 + nt * 8;
                if (BT == 0)
                    ldmx2(bf[nt], sB_ + (uint32_t)(nc * 80) + bkc + (uint32_t)(ks * 32));
                else
                    ldmx2t(bf[nt], sB_ + (uint32_t)(ks * 16 * 272) + bmc + (uint32_t)(nc * 2));
            }
            #pragma unroll
            for (int mt = 0; mt < 4; ++mt)
                #pragma unroll
                for (int nt = 0; nt < 4; ++nt)
                    mma16(acc[mt][nt], af[mt], bf[nt]);
        }
    };

    const int KT = K / 32;
    loadA(0); loadB(0);
    storeA(0); storeB(0);
    __syncthreads();
    for (int kt = 0; kt < KT; ++kt) {
        if (kt + 1 < KT) { loadA((kt + 1) * 32); loadB((kt + 1) * 32); }
        compute(kt & 1);
        if (kt + 1 < KT) {
            storeA((kt + 1) & 1); storeB((kt + 1) & 1);
            __syncthreads();
        }
    }

    // ---------------- epilogue ----------------
    #pragma unroll
    for (int mt = 0; mt < 4; ++mt) {
        int r0 = m0 + wm * 64 + mt * 16 + g;
        float z0 = 1.f, z1 = 1.f;
        if (EPI == 4) { z0 = 1.f / axm[r0]; z1 = 1.f / axm[r0 + 8]; }
        #pragma unroll
        for (int nt = 0; nt < 4; ++nt) {
            int c = n0 + wn * 32 + nt * 8 + t * 2;
            float v0 = acc[mt][nt][0], v1 = acc[mt][nt][1];
            float v2 = acc[mt][nt][2], v3 = acc[mt][nt][3];
            if (EPI == 1 || EPI == 2) {
                float b0 = auxN[c], b1 = auxN[c + 1];
                v0 += b0; v1 += b1; v2 += b0; v3 += b1;
            }
            if (EPI == 2) {
                v0 = v0 > 0.f ? v0 + 1.f : expf(v0);
                v1 = v1 > 0.f ? v1 + 1.f : expf(v1);
                v2 = v2 > 0.f ? v2 + 1.f : expf(v2);
                v3 = v3 > 0.f ? v3 + 1.f : expf(v3);
            }
            if (EPI == 4) {
                float b0 = auxN[c], b1 = auxN[c + 1];
                v0 = v0 * z0 + b0; v1 = v1 * z0 + b1;
                v2 = v2 * z1 + b0; v3 = v3 * z1 + b1;
            }
            if (sizeof(TC) == 2) {
                *reinterpret_cast<__half2*>((__half*)C + (long)r0 * ldc + c) =
                    __floats2half2_rn(v0, v1);
                *reinterpret_cast<__half2*>((__half*)C + (long)(r0 + 8) * ldc + c) =
                    __floats2half2_rn(v2, v3);
            } else {
                *reinterpret_cast<float2*>((float*)C + (long)r0       * ldc + c) = make_float2(v0, v1);
                *reinterpret_cast<float2*>((float*)C + (long)(r0 + 8) * ldc + c) = make_float2(v2, v3);
            }
        }
    }
}

// ---------------- unpack 8 halves -> 8 floats ----------------
__device__ __forceinline__ void h8f(const uint4& u, float* f) {
    const __half2* h = reinterpret_cast<const __half2*>(&u);
    #pragma unroll
    for (int i = 0; i < 4; ++i) {
        float2 t = __half22float2(h[i]);
        f[2 * i] = t.x; f[2 * i + 1] = t.y;
    }
}

// ---------------- K column-sum (+1e-6) ----------------
__global__ void ksum_init() {
    int i = blockIdx.x * 256 + threadIdx.x;
    g_Ksum[i] = 1e-6f;
}

__global__ void ksum_acc() {
    int b = blockIdx.y;
    int chunk = blockIdx.x;               // 16 chunks of 256 rows
    int c8 = threadIdx.x;                 // 0..127 -> 8 columns each
    float s[8];
    #pragma unroll
    for (int j = 0; j < 8; ++j) s[j] = 0.f;
    const __half* base = g_Kf + ((long)b * N_SEQ + chunk * 256) * D_DIM + c8 * 8;
    for (int n = 0; n < 256; ++n) {
        uint4 u = *reinterpret_cast<const uint4*>(base + (long)n * D_DIM);
        float f[8]; h8f(u, f);
        #pragma unroll
        for (int j = 0; j < 8; ++j) s[j] += f[j];
    }
    float* ks = g_Ksum + b * D_DIM + c8 * 8;
    #pragma unroll
    for (int j = 0; j < 8; ++j) atomicAdd(ks + j, s[j]);
}

// ---------------- Z[b,n] = Q[b,n,:] . Ksum[b,:] ----------------
__global__ void z_kernel() {
    int warp = threadIdx.x >> 5;
    int lane = threadIdx.x & 31;
    long row = (long)blockIdx.x * 8 + warp;
    int b = (int)(row >> 12);
    const __half* q  = g_Q + row * D_DIM;
    const float*  ks = g_Ksum + b * D_DIM;
    float s = 0.f;
    #pragma unroll
    for (int i = 0; i < 4; ++i) {
        int d = (lane + i * 32) * 8;
        uint4 u = *reinterpret_cast<const uint4*>(q + d);
        float f[8]; h8f(u, f);
        float4 k0 = *reinterpret_cast<const float4*>(&ks[d]);
        float4 k1 = *reinterpret_cast<const float4*>(&ks[d + 4]);
        s += f[0] * k0.x + f[1] * k0.y + f[2] * k0.z + f[3] * k0.w
           + f[4] * k1.x + f[5] * k1.y + f[6] * k1.z + f[7] * k1.w;
    }
    #pragma unroll
    for (int o = 16; o > 0; o >>= 1) s += __shfl_xor_sync(0xFFFFFFFFu, s, o);
    if (lane == 0) g_Z[row] = s;
}

// ---------------- launch ----------------
extern "C" void kernel_launch(void* const* d_in, const int* in_sizes, int n_in,
                              void* d_out, int out_size)
{
    const float* x  = (const float*)d_in[0];
    const float* Wq = (const float*)d_in[1];
    const float* bq = (const float*)d_in[2];
    const float* Wk = (const float*)d_in[3];
    const float* bk = (const float*)d_in[4];
    const float* Wv = (const float*)d_in[5];
    const float* bv = (const float*)d_in[6];
    const float* Wo = (const float*)d_in[7];
    const float* bo = (const float*)d_in[8];
    float* out = (float*)d_out;

    __half *pQ, *pK, *pV, *pKV, *pM;
    float *pZ;
    cudaGetSymbolAddress((void**)&pQ,  g_Q);
    cudaGetSymbolAddress((void**)&pK,  g_Kf);
    cudaGetSymbolAddress((void**)&pV,  g_V);
    cudaGetSymbolAddress((void**)&pKV, g_KV);
    cudaGetSymbolAddress((void**)&pM,  g_M);
    cudaGetSymbolAddress((void**)&pZ,  g_Z);

    dim3 blk(256);
    dim3 gproj(D_DIM / 128, M_FLAT / 128, 1);        // (8, 256)

    // 1) Q/K/V projections: C = X @ W^T  (elu+1 fused on Q,K; bias on V) -> fp16
    gemm_h<0,0,2,float,float,__half><<<gproj, blk>>>(x, Wq, pQ, pZ, bq,
        M_FLAT, D_DIM, D_DIM, D_DIM, D_DIM, D_DIM, 0, 0, 0, 0);
    gemm_h<0,0,2,float,float,__half><<<gproj, blk>>>(x, Wk, pK, pZ, bk,
        M_FLAT, D_DIM, D_DIM, D_DIM, D_DIM, D_DIM, 0, 0, 0, 0);
    gemm_h<0,0,1,float,float,__half><<<gproj, blk>>>(x, Wv, pV, pZ, bv,
        M_FLAT, D_DIM, D_DIM, D_DIM, D_DIM, D_DIM, 0, 0, 0, 0);

    // 2) Ksum (+eps) and Z
    ksum_init<<<(N_BATCH * D_DIM) / 256, 256>>>();
    ksum_acc<<<dim3(16, N_BATCH), 128>>>();
    z_kernel<<<M_FLAT / 8, 256>>>();

    // 3) KV[b][d,e] = sum_n K[b][n,d] * V[b][n,e]   (fp16, K=4096, both .trans)
    gemm_h<1,1,0,__half,__half,__half><<<dim3(8, 8, N_BATCH), blk>>>(pK, pV, pKV, pZ, pZ,
        D_DIM, D_DIM, N_SEQ, D_DIM, D_DIM, D_DIM,
        (long)N_SEQ * D_DIM, (long)N_SEQ * D_DIM, (long)D_DIM * D_DIM, 0);

    // 4) M[b][d,f] = sum_e KV[b][d,e] * Wo[f,e]
    gemm_h<0,0,0,__half,float,__half><<<dim3(8, 8, N_BATCH), blk>>>(pKV, Wo, pM, pZ, pZ,
        D_DIM, D_DIM, D_DIM, D_DIM, D_DIM, D_DIM,
        (long)D_DIM * D_DIM, 0, (long)D_DIM * D_DIM, 0);

    // 5) out[b][n,f] = (sum_d Q[b][n,d] * M[b][d,f]) / Z[b,n] + bo[f]   -> f32
    gemm_h<0,1,4,__half,__half,float><<<dim3(8, 32, N_BATCH), blk>>>(pQ, pM, out, pZ, bo,
        N_SEQ, D_DIM, D_DIM, D_DIM, D_DIM, D_DIM,
        (long)N_SEQ * D_DIM, (long)D_DIM * D_DIM, (long)N_SEQ * D_DIM, N_SEQ);
}

// round 15
// speedup vs baseline: 3.4251x; 1.3071x over previous
#include <cuda_runtime.h>
#include <cuda_fp16.h>
#include <cstdint>
#include <math.h>

#define D_DIM   1024
#define N_BATCH 8
#define N_SEQ   4096
#define M_FLAT  (N_BATCH * N_SEQ)   // 32768

// GEMM tiles: block 128(M) x 256(N) x 32(K); 8 warps as 2(m) x 4(n), warp 64x64
// smem stages (halves): A: K-contig 128x40 / M-contig 32x136  -> ASZ 5120
//                       B: K-contig 256x40 / N-contig 32x264  -> BSZ 10240
#define ASZ 5120
#define BSZ 10240
#define NST 3
#define SMEM_BYTES (NST * (ASZ + BSZ) * 2)   // 92160 B

// ---------------- scratch (device globals: no allocation allowed) ----------
__device__ __half g_Xh [(size_t)M_FLAT * D_DIM];           // fp16 copy of x
__device__ __half g_Wh [(size_t)4 * D_DIM * D_DIM];        // Wq,Wk,Wv,Wo fp16
__device__ __half g_Q  [(size_t)M_FLAT * D_DIM];
__device__ __half g_Kf [(size_t)M_FLAT * D_DIM];
__device__ __half g_V  [(size_t)M_FLAT * D_DIM];
__device__ __half g_KV [(size_t)N_BATCH * D_DIM * D_DIM];  // K^T V [d,e]
__device__ __half g_M  [(size_t)N_BATCH * D_DIM * D_DIM];  // KV @ Wo^T [d,f]
__device__ float  g_Ksum[N_BATCH * D_DIM];
__device__ float  g_Z[M_FLAT];

// ---------------- helpers ----------------
__device__ __forceinline__ uint32_t f2h2(float lo, float hi) {
    __half2 h = __floats2half2_rn(lo, hi);
    return *reinterpret_cast<uint32_t*>(&h);
}

__device__ __forceinline__ uint32_t smem_u32(const void* p) {
    uint32_t a;
    asm("{ .reg .u64 t; cvta.to.shared.u64 t, %1; cvt.u32.u64 %0, t; }" : "=r"(a) : "l"(p));
    return a;
}

#define CP16(dst, src) \
    asm volatile("cp.async.cg.shared.global [%0], [%1], 16;" :: "r"(dst), "l"(src) : "memory")
#define CP_COMMIT() asm volatile("cp.async.commit_group;" ::: "memory")
#define CP_WAIT1()  asm volatile("cp.async.wait_group 1;" ::: "memory")

__device__ __forceinline__ void mma16(float c[4], const uint32_t a[4], const uint32_t b[2]) {
    asm volatile(
        "mma.sync.aligned.m16n8k16.row.col.f32.f16.f16.f32 "
        "{%0,%1,%2,%3}, {%4,%5,%6,%7}, {%8,%9}, {%0,%1,%2,%3};\n"
        : "+f"(c[0]), "+f"(c[1]), "+f"(c[2]), "+f"(c[3])
        : "r"(a[0]), "r"(a[1]), "r"(a[2]), "r"(a[3]), "r"(b[0]), "r"(b[1]));
}

__device__ __forceinline__ void ldmx4(uint32_t* r, uint32_t a) {
    asm volatile("ldmatrix.sync.aligned.m8n8.x4.shared.b16 {%0,%1,%2,%3}, [%4];"
                 : "=r"(r[0]), "=r"(r[1]), "=r"(r[2]), "=r"(r[3]) : "r"(a));
}
__device__ __forceinline__ void ldmx4t(uint32_t* r, uint32_t a) {
    asm volatile("ldmatrix.sync.aligned.m8n8.x4.trans.shared.b16 {%0,%1,%2,%3}, [%4];"
                 : "=r"(r[0]), "=r"(r[1]), "=r"(r[2]), "=r"(r[3]) : "r"(a));
}

// ---------------- fp16 GEMM: cp.async + ldmatrix, 128x256x32, 3-stage -------
// C[M,N] = epilogue( sum_k A[m,k]*B[k,n] );  all operands __half in gmem.
// AT==0: A[m,k] = A[m*lda + k] (K-contig, smem [row][k] pitch 40, ldmx4)
// AT==1: A[m,k] = A[k*lda + m] (M-contig, smem [k][m] pitch 136, ldmx4t)
// BT==0: B[k,n] = B[n*ldb + k] ([N,K] K-contig, pitch 40, ldmx4)
// BT==1: B[k,n] = B[k*ldb + n] ([K,N] N-contig, pitch 264, ldmx4t)
// EPI: 0 none | 1 +biasN | 2 elu(+biasN)+1 | 4 v/zM + biasN
template<int AT, int BT, int EPI, typename TC>
__global__ void __launch_bounds__(256, 1)
gemm_h(const __half* __restrict__ Ag, const __half* __restrict__ Bg,
       TC* __restrict__ Cg,
       const float* __restrict__ auxM, const float* __restrict__ auxN,
       int M, int N, int K, int lda, int ldb, int ldc,
       long sA, long sB, long sC, long sAuxM)
{
    extern __shared__ __align__(16) __half dsm[];

    const int bz = blockIdx.z;
    const __half* A = Ag + (long)bz * sA;
    const __half* B = Bg + (long)bz * sB;
    TC*           C = Cg + (long)bz * sC;
    const float* axm = auxM + (long)bz * sAuxM;

    const int tid  = threadIdx.x;
    const int lane = tid & 31;
    const int warp = tid >> 5;
    const int g    = lane >> 2;
    const int t    = lane & 3;
    const int wm   = warp & 1;          // 2 (m) x 4 (n)
    const int wn   = warp >> 1;
    const int m0   = blockIdx.y * 128;
    const int n0   = blockIdx.x * 256;

    const uint32_t sb = smem_u32(dsm);
    auto Ast = [&](int s) -> uint32_t { return sb + (uint32_t)(s * (ASZ + BSZ) * 2); };
    auto Bst = [&](int s) -> uint32_t { return Ast(s) + ASZ * 2; };

    float acc[4][8][4];
    #pragma unroll
    for (int i = 0; i < 4; ++i)
        #pragma unroll
        for (int j = 0; j < 8; ++j)
            #pragma unroll
            for (int l = 0; l < 4; ++l) acc[i][j][l] = 0.f;

    // ---- cp.async stage fills ----
    auto loadA = [&](int s, int kt) {
        uint32_t d0 = Ast(s);
        int k0 = kt * 32;
        if (AT == 0) {          // 128 rows x 4 chunks (16B) -> 2 per thread
            #pragma unroll
            for (int i = 0; i < 2; ++i) {
                int id  = tid + 256 * i;
                int row = id >> 2, ch = id & 3;
                CP16(d0 + (uint32_t)(row * 80 + ch * 16),
                     A + (long)(m0 + row) * lda + k0 + ch * 8);
            }
        } else {                // 32 k-rows x 16 chunks -> 2 per thread
            #pragma unroll
            for (int i = 0; i < 2; ++i) {
                int id  = tid + 256 * i;
                int row = id >> 4, col = id & 15;
                CP16(d0 + (uint32_t)(row * 272 + col * 16),
                     A + (long)(k0 + row) * lda + m0 + col * 8);
            }
        }
    };
    auto loadB = [&](int s, int kt) {
        uint32_t d0 = Bst(s);
        int k0 = kt * 32;
        if (BT == 0) {          // 256 rows x 4 chunks -> 4 per thread
            #pragma unroll
            for (int i = 0; i < 4; ++i) {
                int id  = tid + 256 * i;
                int row = id >> 2, ch = id & 3;
                CP16(d0 + (uint32_t)(row * 80 + ch * 16),
                     B + (long)(n0 + row) * ldb + k0 + ch * 8);
            }
        } else {                // 32 k-rows x 32 chunks -> 4 per thread
            #pragma unroll
            for (int i = 0; i < 4; ++i) {
                int id  = tid + 256 * i;
                int row = id >> 5, col = id & 31;
                CP16(d0 + (uint32_t)(row * 528 + col * 16),
                     B + (long)(k0 + row) * ldb + n0 + col * 8);
            }
        }
    };

    // ---- ldmatrix lane offsets ----
    const uint32_t aK = (uint32_t)((lane & 15) * 80 + (lane >> 4) * 16);                 // AT=0
    const uint32_t aM = (uint32_t)(((lane & 7) + (lane >> 4) * 8) * 272
                                   + ((lane >> 3) & 1) * 16);                            // AT=1
    const uint32_t bK = (uint32_t)(((lane & 7) + (lane >> 4) * 8) * 80
                                   + ((lane >> 3) & 1) * 16);                            // BT=0
    const uint32_t bN = (uint32_t)(((lane & 7) + ((lane >> 3) & 1) * 8) * 528
                                   + (lane >> 4) * 16);                                  // BT=1

    auto compute = [&](int s) {
        uint32_t sA_ = Ast(s), sB_ = Bst(s);
        #pragma unroll
        for (int ks = 0; ks < 2; ++ks) {
            uint32_t af[4][4];
            uint32_t bf[8][2];
            #pragma unroll
            for (int mt = 0; mt < 4; ++mt) {
                int mr = wm * 64 + mt * 16;
                if (AT == 0) ldmx4(af[mt],  sA_ + (uint32_t)(mr * 80) + aK + (uint32_t)(ks * 32));
                else         ldmx4t(af[mt], sA_ + (uint32_t)(ks * 16 * 272) + aM + (uint32_t)(mr * 2));
            }
            #pragma unroll
            for (int jp = 0; jp < 4; ++jp) {    // two n8 tiles per ldmx4
                int nb = wn * 64 + jp * 16;
                uint32_t r[4];
                if (BT == 0) ldmx4(r,  sB_ + (uint32_t)(nb * 80) + bK + (uint32_t)(ks * 32));
                else         ldmx4t(r, sB_ + (uint32_t)(ks * 16 * 528) + bN + (uint32_t)(nb * 2));
                bf[jp * 2 + 0][0] = r[0]; bf[jp * 2 + 0][1] = r[1];
                bf[jp * 2 + 1][0] = r[2]; bf[jp * 2 + 1][1] = r[3];
            }
            #pragma unroll
            for (int mt = 0; mt < 4; ++mt)
                #pragma unroll
                for (int nt = 0; nt < 8; ++nt)
                    mma16(acc[mt][nt], af[mt], bf[nt]);
        }
    };

    const int KT = K / 32;
    loadA(0, 0); loadB(0, 0); CP_COMMIT();
    loadA(1, 1); loadB(1, 1); CP_COMMIT();          // KT >= 2 always here
    for (int kt = 0; kt < KT; ++kt) {
        CP_WAIT1();                  // group kt complete (kt+1 may be in flight)
        __syncthreads();
        compute(kt % 3);
        if (kt + 2 < KT) { loadA((kt + 2) % 3, kt + 2); loadB((kt + 2) % 3, kt + 2); }
        CP_COMMIT();
    }

    // ---------------- epilogue ----------------
    #pragma unroll
    for (int mt = 0; mt < 4; ++mt) {
        int r0 = m0 + wm * 64 + mt * 16 + g;
        float z0 = 1.f, z1 = 1.f;
        if (EPI == 4) { z0 = 1.f / axm[r0]; z1 = 1.f / axm[r0 + 8]; }
        #pragma unroll
        for (int nt = 0; nt < 8; ++nt) {
            int c = n0 + wn * 64 + nt * 8 + t * 2;
            float v0 = acc[mt][nt][0], v1 = acc[mt][nt][1];
            float v2 = acc[mt][nt][2], v3 = acc[mt][nt][3];
            if (EPI == 1 || EPI == 2) {
                float b0 = auxN[c], b1 = auxN[c + 1];
                v0 += b0; v1 += b1; v2 += b0; v3 += b1;
            }
            if (EPI == 2) {   // elu(x)+1
                v0 = v0 > 0.f ? v0 + 1.f : expf(v0);
                v1 = v1 > 0.f ? v1 + 1.f : expf(v1);
                v2 = v2 > 0.f ? v2 + 1.f : expf(v2);
                v3 = v3 > 0.f ? v3 + 1.f : expf(v3);
            }
            if (EPI == 4) {   // v/z + bias
                float b0 = auxN[c], b1 = auxN[c + 1];
                v0 = v0 * z0 + b0; v1 = v1 * z0 + b1;
                v2 = v2 * z1 + b0; v3 = v3 * z1 + b1;
            }
            if (sizeof(TC) == 2) {
                *reinterpret_cast<__half2*>((__half*)C + (long)r0 * ldc + c) =
                    __floats2half2_rn(v0, v1);
                *reinterpret_cast<__half2*>((__half*)C + (long)(r0 + 8) * ldc + c) =
                    __floats2half2_rn(v2, v3);
            } else {
                *reinterpret_cast<float2*>((float*)C + (long)r0       * ldc + c) = make_float2(v0, v1);
                *reinterpret_cast<float2*>((float*)C + (long)(r0 + 8) * ldc + c) = make_float2(v2, v3);
            }
        }
    }
}

// ---------------- f32 -> f16 convert (pre-pass) ----------------
__global__ void f2h_kernel(const float* __restrict__ src, __half* __restrict__ dst) {
    long i = (long)blockIdx.x * blockDim.x + threadIdx.x;     // one float4 each
    float4 v = reinterpret_cast<const float4*>(src)[i];
    reinterpret_cast<uint2*>(dst)[i] = make_uint2(f2h2(v.x, v.y), f2h2(v.z, v.w));
}

// ---------------- unpack 8 halves -> 8 floats ----------------
__device__ __forceinline__ void h8f(const uint4& u, float* f) {
    const __half2* h = reinterpret_cast<const __half2*>(&u);
    #pragma unroll
    for (int i = 0; i < 4; ++i) {
        float2 t = __half22float2(h[i]);
        f[2 * i] = t.x; f[2 * i + 1] = t.y;
    }
}

// ---------------- K column-sum (+1e-6) ----------------
__global__ void ksum_init() {
    int i = blockIdx.x * 256 + threadIdx.x;
    g_Ksum[i] = 1e-6f;
}

__global__ void ksum_acc() {
    int b = blockIdx.y;
    int chunk = blockIdx.x;
    int c8 = threadIdx.x;
    float s[8];
    #pragma unroll
    for (int j = 0; j < 8; ++j) s[j] = 0.f;
    const __half* base = g_Kf + ((long)b * N_SEQ + chunk * 256) * D_DIM + c8 * 8;
    for (int n = 0; n < 256; ++n) {
        uint4 u = *reinterpret_cast<const uint4*>(base + (long)n * D_DIM);
        float f[8]; h8f(u, f);
        #pragma unroll
        for (int j = 0; j < 8; ++j) s[j] += f[j];
    }
    float* ks = g_Ksum + b * D_DIM + c8 * 8;
    #pragma unroll
    for (int j = 0; j < 8; ++j) atomicAdd(ks + j, s[j]);
}

// ---------------- Z[b,n] = Q[b,n,:] . Ksum[b,:] ----------------
__global__ void z_kernel() {
    int warp = threadIdx.x >> 5;
    int lane = threadIdx.x & 31;
    long row = (long)blockIdx.x * 8 + warp;
    int b = (int)(row >> 12);
    const __half* q  = g_Q + row * D_DIM;
    const float*  ks = g_Ksum + b * D_DIM;
    float s = 0.f;
    #pragma unroll
    for (int i = 0; i < 4; ++i) {
        int d = (lane + i * 32) * 8;
        uint4 u = *reinterpret_cast<const uint4*>(q + d);
        float f[8]; h8f(u, f);
        float4 k0 = *reinterpret_cast<const float4*>(&ks[d]);
        float4 k1 = *reinterpret_cast<const float4*>(&ks[d + 4]);
        s += f[0] * k0.x + f[1] * k0.y + f[2] * k0.z + f[3] * k0.w
           + f[4] * k1.x + f[5] * k1.y + f[6] * k1.z + f[7] * k1.w;
    }
    #pragma unroll
    for (int o = 16; o > 0; o >>= 1) s += __shfl_xor_sync(0xFFFFFFFFu, s, o);
    if (lane == 0) g_Z[row] = s;
}

// ---------------- launch ----------------
extern "C" void kernel_launch(void* const* d_in, const int* in_sizes, int n_in,
                              void* d_out, int out_size)
{
    const float* x  = (const float*)d_in[0];
    const float* Wq = (const float*)d_in[1];
    const float* bq = (const float*)d_in[2];
    const float* Wk = (const float*)d_in[3];
    const float* bk = (const float*)d_in[4];
    const float* Wv = (const float*)d_in[5];
    const float* bv = (const float*)d_in[6];
    const float* Wo = (const float*)d_in[7];
    const float* bo = (const float*)d_in[8];
    float* out = (float*)d_out;

    __half *pXh, *pWh, *pQ, *pK, *pV, *pKV, *pM;
    float *pZ;
    cudaGetSymbolAddress((void**)&pXh, g_Xh);
    cudaGetSymbolAddress((void**)&pWh, g_Wh);
    cudaGetSymbolAddress((void**)&pQ,  g_Q);
    cudaGetSymbolAddress((void**)&pK,  g_Kf);
    cudaGetSymbolAddress((void**)&pV,  g_V);
    cudaGetSymbolAddress((void**)&pKV, g_KV);
    cudaGetSymbolAddress((void**)&pM,  g_M);
    cudaGetSymbolAddress((void**)&pZ,  g_Z);

    __half* pWqh = pWh;
    __half* pWkh = pWh + (size_t)D_DIM * D_DIM;
    __half* pWvh = pWh + (size_t)2 * D_DIM * D_DIM;
    __half* pWoh = pWh + (size_t)3 * D_DIM * D_DIM;

    static bool attr_done = false;
    if (!attr_done) {
        cudaFuncSetAttribute(gemm_h<0,0,2,__half>, cudaFuncAttributeMaxDynamicSharedMemorySize, SMEM_BYTES);
        cudaFuncSetAttribute(gemm_h<0,0,1,__half>, cudaFuncAttributeMaxDynamicSharedMemorySize, SMEM_BYTES);
        cudaFuncSetAttribute(gemm_h<1,1,0,__half>, cudaFuncAttributeMaxDynamicSharedMemorySize, SMEM_BYTES);
        cudaFuncSetAttribute(gemm_h<0,0,0,__half>, cudaFuncAttributeMaxDynamicSharedMemorySize, SMEM_BYTES);
        cudaFuncSetAttribute(gemm_h<0,1,4,float >, cudaFuncAttributeMaxDynamicSharedMemorySize, SMEM_BYTES);
        attr_done = true;
    }

    dim3 blk(256);

    // 0) convert x + weights to fp16 (rounding-equivalent: GEMMs rounded anyway)
    f2h_kernel<<<(M_FLAT / 256) * (D_DIM / 4), 256>>>(x, pXh);       // 32768 blocks
    f2h_kernel<<<D_DIM * D_DIM / 1024, 256>>>(Wq, pWqh);
    f2h_kernel<<<D_DIM * D_DIM / 1024, 256>>>(Wk, pWkh);
    f2h_kernel<<<D_DIM * D_DIM / 1024, 256>>>(Wv, pWvh);
    f2h_kernel<<<D_DIM * D_DIM / 1024, 256>>>(Wo, pWoh);

    dim3 gproj(D_DIM / 256, M_FLAT / 128, 1);        // (4, 256)

    // 1) Q/K/V projections
    gemm_h<0,0,2,__half><<<gproj, blk, SMEM_BYTES>>>(pXh, pWqh, pQ, pZ, bq,
        M_FLAT, D_DIM, D_DIM, D_DIM, D_DIM, D_DIM, 0, 0, 0, 0);
    gemm_h<0,0,2,__half><<<gproj, blk, SMEM_BYTES>>>(pXh, pWkh, pK, pZ, bk,
        M_FLAT, D_DIM, D_DIM, D_DIM, D_DIM, D_DIM, 0, 0, 0, 0);
    gemm_h<0,0,1,__half><<<gproj, blk, SMEM_BYTES>>>(pXh, pWvh, pV, pZ, bv,
        M_FLAT, D_DIM, D_DIM, D_DIM, D_DIM, D_DIM, 0, 0, 0, 0);

    // 2) Ksum (+eps) and Z
    ksum_init<<<(N_BATCH * D_DIM) / 256, 256>>>();
    ksum_acc<<<dim3(16, N_BATCH), 128>>>();
    z_kernel<<<M_FLAT / 8, 256>>>();

    // 3) KV[b][d,e] = sum_n K[b][n,d] * V[b][n,e]
    gemm_h<1,1,0,__half><<<dim3(D_DIM / 256, D_DIM / 128, N_BATCH), blk, SMEM_BYTES>>>(
        pK, pV, pKV, pZ, pZ,
        D_DIM, D_DIM, N_SEQ, D_DIM, D_DIM, D_DIM,
        (long)N_SEQ * D_DIM, (long)N_SEQ * D_DIM, (long)D_DIM * D_DIM, 0);

    // 4) M[b][d,f] = sum_e KV[b][d,e] * Wo[f,e]
    gemm_h<0,0,0,__half><<<dim3(D_DIM / 256, D_DIM / 128, N_BATCH), blk, SMEM_BYTES>>>(
        pKV, pWoh, pM, pZ, pZ,
        D_DIM, D_DIM, D_DIM, D_DIM, D_DIM, D_DIM,
        (long)D_DIM * D_DIM, 0, (long)D_DIM * D_DIM, 0);

    // 5) out[b][n,f] = (sum_d Q[b][n,d] * M[b][d,f]) / Z[b,n] + bo[f]
    gemm_h<0,1,4,float><<<dim3(D_DIM / 256, N_SEQ / 128, N_BATCH), blk, SMEM_BYTES>>>(
        pQ, pM, out, pZ, bo,
        N_SEQ, D_DIM, D_DIM, D_DIM, D_DIM, D_DIM,
        (long)N_SEQ * D_DIM, (long)D_DIM * D_DIM, (long)N_SEQ * D_DIM, N_SEQ);
}

// round 16
// speedup vs baseline: 3.5858x; 1.0469x over previous
#include <cuda_runtime.h>
#include <cuda_fp16.h>
#include <cstdint>
#include <math.h>

#define D_DIM   1024
#define N_BATCH 8
#define N_SEQ   4096
#define M_FLAT  (N_BATCH * N_SEQ)   // 32768

// GEMM tiles: block 128(M) x 256(N) x 32(K); 8 warps as 2(m) x 4(n), warp 64x64
// smem stages (halves): A: K-contig 128x40 / M-contig 32x136  -> ASZ 5120
//                       B: K-contig 256x40 / N-contig 32x264  -> BSZ 10240
#define ASZ 5120
#define BSZ 10240
#define NST 4
#define SMEM_BYTES (NST * (ASZ + BSZ) * 2)   // 122880 B

// ---------------- scratch (device globals: no allocation allowed) ----------
__device__ __half g_Xh [(size_t)M_FLAT * D_DIM];           // fp16 copy of x
__device__ __half g_Wh [(size_t)4 * D_DIM * D_DIM];        // Wq,Wk,Wv,Wo fp16
__device__ __half g_Wvo[(size_t)D_DIM * D_DIM];            // (Wo @ Wv) fp16  [f,k]
__device__ float  g_bvo[D_DIM];                            // Wo @ bv
__device__ __half g_Q  [(size_t)M_FLAT * D_DIM];
__device__ __half g_Kf [(size_t)M_FLAT * D_DIM];
__device__ __half g_Vo [(size_t)M_FLAT * D_DIM];           // x @ Wvo^T + bvo
__device__ __half g_MV [(size_t)N_BATCH * D_DIM * D_DIM];  // K^T Vo  [d,f]
__device__ float  g_Ksum[N_BATCH * D_DIM];
__device__ float  g_Z[M_FLAT];

// ---------------- helpers ----------------
__device__ __forceinline__ uint32_t f2h2(float lo, float hi) {
    __half2 h = __floats2half2_rn(lo, hi);
    return *reinterpret_cast<uint32_t*>(&h);
}

__device__ __forceinline__ uint32_t smem_u32(const void* p) {
    uint32_t a;
    asm("{ .reg .u64 t; cvta.to.shared.u64 t, %1; cvt.u32.u64 %0, t; }" : "=r"(a) : "l"(p));
    return a;
}

#define CP16(dst, src) \
    asm volatile("cp.async.cg.shared.global [%0], [%1], 16;" :: "r"(dst), "l"(src) : "memory")
#define CP_COMMIT() asm volatile("cp.async.commit_group;" ::: "memory")
#define CP_WAIT2()  asm volatile("cp.async.wait_group 2;" ::: "memory")

__device__ __forceinline__ void mma16(float c[4], const uint32_t a[4], const uint32_t b[2]) {
    asm volatile(
        "mma.sync.aligned.m16n8k16.row.col.f32.f16.f16.f32 "
        "{%0,%1,%2,%3}, {%4,%5,%6,%7}, {%8,%9}, {%0,%1,%2,%3};\n"
        : "+f"(c[0]), "+f"(c[1]), "+f"(c[2]), "+f"(c[3])
        : "r"(a[0]), "r"(a[1]), "r"(a[2]), "r"(a[3]), "r"(b[0]), "r"(b[1]));
}

__device__ __forceinline__ void ldmx4(uint32_t* r, uint32_t a) {
    asm volatile("ldmatrix.sync.aligned.m8n8.x4.shared.b16 {%0,%1,%2,%3}, [%4];"
                 : "=r"(r[0]), "=r"(r[1]), "=r"(r[2]), "=r"(r[3]) : "r"(a));
}
__device__ __forceinline__ void ldmx4t(uint32_t* r, uint32_t a) {
    asm volatile("ldmatrix.sync.aligned.m8n8.x4.trans.shared.b16 {%0,%1,%2,%3}, [%4];"
                 : "=r"(r[0]), "=r"(r[1]), "=r"(r[2]), "=r"(r[3]) : "r"(a));
}

// ---------------- fp16 GEMM: cp.async + ldmatrix, 128x256x32, 4-stage -------
// C[M,N] = epilogue( sum_k A[m,k]*B[k,n] );  all operands __half in gmem.
// AT==0: A[m,k] = A[m*lda + k] (K-contig, smem [row][k] pitch 40, ldmx4)
// AT==1: A[m,k] = A[k*lda + m] (M-contig, smem [k][m] pitch 136, ldmx4t)
// BT==0: B[k,n] = B[n*ldb + k] ([N,K] K-contig, pitch 40, ldmx4)
// BT==1: B[k,n] = B[k*ldb + n] ([K,N] N-contig, pitch 264, ldmx4t)
// EPI: 0 none | 1 +biasN | 2 elu(+biasN)+1 | 4 v/zM + biasN
template<int AT, int BT, int EPI, typename TC>
__global__ void __launch_bounds__(256, 1)
gemm_h(const __half* __restrict__ Ag, const __half* __restrict__ Bg,
       TC* __restrict__ Cg,
       const float* __restrict__ auxM, const float* __restrict__ auxN,
       int M, int N, int K, int lda, int ldb, int ldc,
       long sA, long sB, long sC, long sAuxM)
{
    extern __shared__ __align__(16) __half dsm[];

    const int bz = blockIdx.z;
    const __half* A = Ag + (long)bz * sA;
    const __half* B = Bg + (long)bz * sB;
    TC*           C = Cg + (long)bz * sC;
    const float* axm = auxM + (long)bz * sAuxM;

    const int tid  = threadIdx.x;
    const int lane = tid & 31;
    const int warp = tid >> 5;
    const int g    = lane >> 2;
    const int t    = lane & 3;
    const int wm   = warp & 1;          // 2 (m) x 4 (n)
    const int wn   = warp >> 1;
    const int m0   = blockIdx.y * 128;
    const int n0   = blockIdx.x * 256;

    const uint32_t sb = smem_u32(dsm);
    auto Ast = [&](int s) -> uint32_t { return sb + (uint32_t)(s * (ASZ + BSZ) * 2); };
    auto Bst = [&](int s) -> uint32_t { return Ast(s) + ASZ * 2; };

    float acc[4][8][4];
    #pragma unroll
    for (int i = 0; i < 4; ++i)
        #pragma unroll
        for (int j = 0; j < 8; ++j)
            #pragma unroll
            for (int l = 0; l < 4; ++l) acc[i][j][l] = 0.f;

    // ---- cp.async stage fills ----
    auto loadA = [&](int s, int kt) {
        uint32_t d0 = Ast(s);
        int k0 = kt * 32;
        if (AT == 0) {
            #pragma unroll
            for (int i = 0; i < 2; ++i) {
                int id  = tid + 256 * i;
                int row = id >> 2, ch = id & 3;
                CP16(d0 + (uint32_t)(row * 80 + ch * 16),
                     A + (long)(m0 + row) * lda + k0 + ch * 8);
            }
        } else {
            #pragma unroll
            for (int i = 0; i < 2; ++i) {
                int id  = tid + 256 * i;
                int row = id >> 4, col = id & 15;
                CP16(d0 + (uint32_t)(row * 272 + col * 16),
                     A + (long)(k0 + row) * lda + m0 + col * 8);
            }
        }
    };
    auto loadB = [&](int s, int kt) {
        uint32_t d0 = Bst(s);
        int k0 = kt * 32;
        if (BT == 0) {
            #pragma unroll
            for (int i = 0; i < 4; ++i) {
                int id  = tid + 256 * i;
                int row = id >> 2, ch = id & 3;
                CP16(d0 + (uint32_t)(row * 80 + ch * 16),
                     B + (long)(n0 + row) * ldb + k0 + ch * 8);
            }
        } else {
            #pragma unroll
            for (int i = 0; i < 4; ++i) {
                int id  = tid + 256 * i;
                int row = id >> 5, col = id & 31;
                CP16(d0 + (uint32_t)(row * 528 + col * 16),
                     B + (long)(k0 + row) * ldb + n0 + col * 8);
            }
        }
    };

    // ---- ldmatrix lane offsets ----
    const uint32_t aK = (uint32_t)((lane & 15) * 80 + (lane >> 4) * 16);
    const uint32_t aM = (uint32_t)(((lane & 7) + (lane >> 4) * 8) * 272
                                   + ((lane >> 3) & 1) * 16);
    const uint32_t bK = (uint32_t)(((lane & 7) + (lane >> 4) * 8) * 80
                                   + ((lane >> 3) & 1) * 16);
    const uint32_t bN = (uint32_t)(((lane & 7) + ((lane >> 3) & 1) * 8) * 528
                                   + (lane >> 4) * 16);

    auto compute = [&](int s) {
        uint32_t sA_ = Ast(s), sB_ = Bst(s);
        #pragma unroll
        for (int ks = 0; ks < 2; ++ks) {
            uint32_t af[4][4];
            uint32_t bf[8][2];
            #pragma unroll
            for (int mt = 0; mt < 4; ++mt) {
                int mr = wm * 64 + mt * 16;
                if (AT == 0) ldmx4(af[mt],  sA_ + (uint32_t)(mr * 80) + aK + (uint32_t)(ks * 32));
                else         ldmx4t(af[mt], sA_ + (uint32_t)(ks * 16 * 272) + aM + (uint32_t)(mr * 2));
            }
            #pragma unroll
            for (int jp = 0; jp < 4; ++jp) {
                int nb = wn * 64 + jp * 16;
                uint32_t r[4];
                if (BT == 0) ldmx4(r,  sB_ + (uint32_t)(nb * 80) + bK + (uint32_t)(ks * 32));
                else         ldmx4t(r, sB_ + (uint32_t)(ks * 16 * 528) + bN + (uint32_t)(nb * 2));
                bf[jp * 2 + 0][0] = r[0]; bf[jp * 2 + 0][1] = r[1];
                bf[jp * 2 + 1][0] = r[2]; bf[jp * 2 + 1][1] = r[3];
            }
            #pragma unroll
            for (int mt = 0; mt < 4; ++mt)
                #pragma unroll
                for (int nt = 0; nt < 8; ++nt)
                    mma16(acc[mt][nt], af[mt], bf[nt]);
        }
    };

    const int KT = K / 32;   // >= 32 for all our shapes
    loadA(0, 0); loadB(0, 0); CP_COMMIT();
    loadA(1, 1); loadB(1, 1); CP_COMMIT();
    loadA(2, 2); loadB(2, 2); CP_COMMIT();
    for (int kt = 0; kt < KT; ++kt) {
        CP_WAIT2();                  // group kt done (kt+1, kt+2 may be in flight)
        __syncthreads();
        compute(kt & 3);
        if (kt + 3 < KT) { loadA((kt + 3) & 3, kt + 3); loadB((kt + 3) & 3, kt + 3); }
        CP_COMMIT();
    }

    // ---------------- epilogue ----------------
    #pragma unroll
    for (int mt = 0; mt < 4; ++mt) {
        int r0 = m0 + wm * 64 + mt * 16 + g;
        float z0 = 1.f, z1 = 1.f;
        if (EPI == 4) { z0 = 1.f / axm[r0]; z1 = 1.f / axm[r0 + 8]; }
        #pragma unroll
        for (int nt = 0; nt < 8; ++nt) {
            int c = n0 + wn * 64 + nt * 8 + t * 2;
            float v0 = acc[mt][nt][0], v1 = acc[mt][nt][1];
            float v2 = acc[mt][nt][2], v3 = acc[mt][nt][3];
            if (EPI == 1 || EPI == 2) {
                float b0 = auxN[c], b1 = auxN[c + 1];
                v0 += b0; v1 += b1; v2 += b0; v3 += b1;
            }
            if (EPI == 2) {   // elu(x)+1
                v0 = v0 > 0.f ? v0 + 1.f : expf(v0);
                v1 = v1 > 0.f ? v1 + 1.f : expf(v1);
                v2 = v2 > 0.f ? v2 + 1.f : expf(v2);
                v3 = v3 > 0.f ? v3 + 1.f : expf(v3);
            }
            if (EPI == 4) {   // v/z + bias
                float b0 = auxN[c], b1 = auxN[c + 1];
                v0 = v0 * z0 + b0; v1 = v1 * z0 + b1;
                v2 = v2 * z1 + b0; v3 = v3 * z1 + b1;
            }
            if (sizeof(TC) == 2) {
                *reinterpret_cast<__half2*>((__half*)C + (long)r0 * ldc + c) =
                    __floats2half2_rn(v0, v1);
                *reinterpret_cast<__half2*>((__half*)C + (long)(r0 + 8) * ldc + c) =
                    __floats2half2_rn(v2, v3);
            } else {
                *reinterpret_cast<float2*>((float*)C + (long)r0       * ldc + c) = make_float2(v0, v1);
                *reinterpret_cast<float2*>((float*)C + (long)(r0 + 8) * ldc + c) = make_float2(v2, v3);
            }
        }
    }
}

// ---------------- f32 -> f16 convert (pre-pass) ----------------
__global__ void f2h_kernel(const float* __restrict__ src, __half* __restrict__ dst) {
    long i = (long)blockIdx.x * blockDim.x + threadIdx.x;     // one float4 each
    float4 v = reinterpret_cast<const float4*>(src)[i];
    reinterpret_cast<uint2*>(dst)[i] = make_uint2(f2h2(v.x, v.y), f2h2(v.z, v.w));
}

// ---------------- bvo[f] = sum_e bv[e] * Wo[f,e]  (f32 inputs) -------------
__global__ void bvo_kernel(const float* __restrict__ bv, const float* __restrict__ Wo) {
    int f = blockIdx.x * 8 + (threadIdx.x >> 5);
    int lane = threadIdx.x & 31;
    const float* w = Wo + (long)f * D_DIM;
    float s = 0.f;
    #pragma unroll
    for (int i = 0; i < 8; ++i) {
        int e = (lane + i * 32) * 4;
        float4 a = *reinterpret_cast<const float4*>(bv + e);
        float4 b = *reinterpret_cast<const float4*>(w + e);
        s += a.x * b.x + a.y * b.y + a.z * b.z + a.w * b.w;
    }
    #pragma unroll
    for (int o = 16; o > 0; o >>= 1) s += __shfl_xor_sync(0xFFFFFFFFu, s, o);
    if (lane == 0) g_bvo[f] = s;
}

// ---------------- unpack 8 halves -> 8 floats ----------------
__device__ __forceinline__ void h8f(const uint4& u, float* f) {
    const __half2* h = reinterpret_cast<const __half2*>(&u);
    #pragma unroll
    for (int i = 0; i < 4; ++i) {
        float2 t = __half22float2(h[i]);
        f[2 * i] = t.x; f[2 * i + 1] = t.y;
    }
}

// ---------------- K column-sum (+1e-6) ----------------
__global__ void ksum_init() {
    int i = blockIdx.x * 256 + threadIdx.x;
    g_Ksum[i] = 1e-6f;
}

__global__ void ksum_acc() {
    int b = blockIdx.y;
    int chunk = blockIdx.x;
    int c8 = threadIdx.x;
    float s[8];
    #pragma unroll
    for (int j = 0; j < 8; ++j) s[j] = 0.f;
    const __half* base = g_Kf + ((long)b * N_SEQ + chunk * 256) * D_DIM + c8 * 8;
    for (int n = 0; n < 256; ++n) {
        uint4 u = *reinterpret_cast<const uint4*>(base + (long)n * D_DIM);
        float f[8]; h8f(u, f);
        #pragma unroll
        for (int j = 0; j < 8; ++j) s[j] += f[j];
    }
    float* ks = g_Ksum + b * D_DIM + c8 * 8;
    #pragma unroll
    for (int j = 0; j < 8; ++j) atomicAdd(ks + j, s[j]);
}

// ---------------- Z[b,n] = Q[b,n,:] . Ksum[b,:] ----------------
__global__ void z_kernel() {
    int warp = threadIdx.x >> 5;
    int lane = threadIdx.x & 31;
    long row = (long)blockIdx.x * 8 + warp;
    int b = (int)(row >> 12);
    const __half* q  = g_Q + row * D_DIM;
    const float*  ks = g_Ksum + b * D_DIM;
    float s = 0.f;
    #pragma unroll
    for (int i = 0; i < 4; ++i) {
        int d = (lane + i * 32) * 8;
        uint4 u = *reinterpret_cast<const uint4*>(q + d);
        float f[8]; h8f(u, f);
        float4 k0 = *reinterpret_cast<const float4*>(&ks[d]);
        float4 k1 = *reinterpret_cast<const float4*>(&ks[d + 4]);
        s += f[0] * k0.x + f[1] * k0.y + f[2] * k0.z + f[3] * k0.w
           + f[4] * k1.x + f[5] * k1.y + f[6] * k1.z + f[7] * k1.w;
    }
    #pragma unroll
    for (int o = 16; o > 0; o >>= 1) s += __shfl_xor_sync(0xFFFFFFFFu, s, o);
    if (lane == 0) g_Z[row] = s;
}

// ---------------- launch ----------------
extern "C" void kernel_launch(void* const* d_in, const int* in_sizes, int n_in,
                              void* d_out, int out_size)
{
    const float* x  = (const float*)d_in[0];
    const float* Wq = (const float*)d_in[1];
    const float* bq = (const float*)d_in[2];
    const float* Wk = (const float*)d_in[3];
    const float* bk = (const float*)d_in[4];
    const float* Wv = (const float*)d_in[5];
    const float* bv = (const float*)d_in[6];
    const float* Wo = (const float*)d_in[7];
    const float* bo = (const float*)d_in[8];
    float* out = (float*)d_out;

    __half *pXh, *pWh, *pWvo, *pQ, *pK, *pVo, *pMV;
    float *pZ, *pBvo;
    cudaGetSymbolAddress((void**)&pXh,  g_Xh);
    cudaGetSymbolAddress((void**)&pWh,  g_Wh);
    cudaGetSymbolAddress((void**)&pWvo, g_Wvo);
    cudaGetSymbolAddress((void**)&pBvo, g_bvo);
    cudaGetSymbolAddress((void**)&pQ,   g_Q);
    cudaGetSymbolAddress((void**)&pK,   g_Kf);
    cudaGetSymbolAddress((void**)&pVo,  g_Vo);
    cudaGetSymbolAddress((void**)&pMV,  g_MV);
    cudaGetSymbolAddress((void**)&pZ,   g_Z);

    __half* pWqh = pWh;
    __half* pWkh = pWh + (size_t)D_DIM * D_DIM;
    __half* pWvh = pWh + (size_t)2 * D_DIM * D_DIM;
    __half* pWoh = pWh + (size_t)3 * D_DIM * D_DIM;

    static bool attr_done = false;
    if (!attr_done) {
        cudaFuncSetAttribute(gemm_h<0,0,2,__half>, cudaFuncAttributeMaxDynamicSharedMemorySize, SMEM_BYTES);
        cudaFuncSetAttribute(gemm_h<0,0,1,__half>, cudaFuncAttributeMaxDynamicSharedMemorySize, SMEM_BYTES);
        cudaFuncSetAttribute(gemm_h<0,1,0,__half>, cudaFuncAttributeMaxDynamicSharedMemorySize, SMEM_BYTES);
        cudaFuncSetAttribute(gemm_h<1,1,0,__half>, cudaFuncAttributeMaxDynamicSharedMemorySize, SMEM_BYTES);
        cudaFuncSetAttribute(gemm_h<0,1,4,float >, cudaFuncAttributeMaxDynamicSharedMemorySize, SMEM_BYTES);
        attr_done = true;
    }

    dim3 blk(256);

    // 0) convert x + weights to fp16 (rounding-equivalent)
    f2h_kernel<<<(M_FLAT / 256) * (D_DIM / 4), 256>>>(x, pXh);
    f2h_kernel<<<D_DIM * D_DIM / 1024, 256>>>(Wq, pWqh);
    f2h_kernel<<<D_DIM * D_DIM / 1024, 256>>>(Wk, pWkh);
    f2h_kernel<<<D_DIM * D_DIM / 1024, 256>>>(Wv, pWvh);
    f2h_kernel<<<D_DIM * D_DIM / 1024, 256>>>(Wo, pWoh);

    // 0b) compose Wvo[f,k] = sum_e Wo[f,e] * Wv[e,k]; bvo = Wo @ bv
    gemm_h<0,1,0,__half><<<dim3(D_DIM / 256, D_DIM / 128, 1), blk, SMEM_BYTES>>>(
        pWoh, pWvh, pWvo, pZ, pZ,
        D_DIM, D_DIM, D_DIM, D_DIM, D_DIM, D_DIM, 0, 0, 0, 0);
    bvo_kernel<<<D_DIM / 8, 256>>>(bv, Wo);

    dim3 gproj(D_DIM / 256, M_FLAT / 128, 1);        // (4, 256)

    // 1) projections: Q, K (elu+1), Vo = x@Wvo^T + bvo
    gemm_h<0,0,2,__half><<<gproj, blk, SMEM_BYTES>>>(pXh, pWqh, pQ, pZ, bq,
        M_FLAT, D_DIM, D_DIM, D_DIM, D_DIM, D_DIM, 0, 0, 0, 0);
    gemm_h<0,0,2,__half><<<gproj, blk, SMEM_BYTES>>>(pXh, pWkh, pK, pZ, bk,
        M_FLAT, D_DIM, D_DIM, D_DIM, D_DIM, D_DIM, 0, 0, 0, 0);
    gemm_h<0,0,1,__half><<<gproj, blk, SMEM_BYTES>>>(pXh, pWvo, pVo, pZ, pBvo,
        M_FLAT, D_DIM, D_DIM, D_DIM, D_DIM, D_DIM, 0, 0, 0, 0);

    // 2) Ksum (+eps) and Z
    ksum_init<<<(N_BATCH * D_DIM) / 256, 256>>>();
    ksum_acc<<<dim3(16, N_BATCH), 128>>>();
    z_kernel<<<M_FLAT / 8, 256>>>();

    // 3) MV[b][d,f] = sum_n K[b][n,d] * Vo[b][n,f]
    gemm_h<1,1,0,__half><<<dim3(D_DIM / 256, D_DIM / 128, N_BATCH), blk, SMEM_BYTES>>>(
        pK, pVo, pMV, pZ, pZ,
        D_DIM, D_DIM, N_SEQ, D_DIM, D_DIM, D_DIM,
        (long)N_SEQ * D_DIM, (long)N_SEQ * D_DIM, (long)D_DIM * D_DIM, 0);

    // 4) out[b][n,f] = (sum_d Q[b][n,d] * MV[b][d,f]) / Z[b,n] + bo[f]
    gemm_h<0,1,4,float><<<dim3(D_DIM / 256, N_SEQ / 128, N_BATCH), blk, SMEM_BYTES>>>(
        pQ, pMV, out, pZ, bo,
        N_SEQ, D_DIM, D_DIM, D_DIM, D_DIM, D_DIM,
        (long)N_SEQ * D_DIM, (long)D_DIM * D_DIM, (long)N_SEQ * D_DIM, N_SEQ);
}

// round 17
// speedup vs baseline: 3.6235x; 1.0105x over previous
#include <cuda_runtime.h>
#include <cuda_fp16.h>
#include <cstdint>
#include <math.h>

#define D_DIM   1024
#define N_BATCH 8
#define N_SEQ   4096
#define M_FLAT  (N_BATCH * N_SEQ)   // 32768

// GEMM tiles: block 128(M) x 256(N) x 32(K); 8 warps as 2(m) x 4(n), warp 64x64
#define ASZ 5120
#define BSZ 10240
#define NST 4
#define SMEM_BYTES (NST * (ASZ + BSZ) * 2)   // 122880 B

// ---------------- scratch (device globals: no allocation allowed) ----------
__device__ __half g_Xh [(size_t)M_FLAT * D_DIM];           // fp16 copy of x
__device__ __half g_Wh [(size_t)4 * D_DIM * D_DIM];        // Wq,Wk,Wv,Wo fp16
__device__ __half g_Wvo[(size_t)D_DIM * D_DIM];            // (Wo @ Wv) fp16 [f,k]
__device__ float  g_bvo[D_DIM];                            // Wo @ bv
__device__ __half g_Q  [(size_t)M_FLAT * D_DIM];
__device__ __half g_Kf [(size_t)M_FLAT * D_DIM];
__device__ __half g_Vo [(size_t)M_FLAT * D_DIM];           // x @ Wvo^T + bvo
__device__ __half g_MV [(size_t)N_BATCH * D_DIM * D_DIM];  // K^T Vo  [d,f]
__device__ float  g_Ksum[N_BATCH * D_DIM];
__device__ float  g_Z[M_FLAT];

// ---------------- helpers ----------------
__device__ __forceinline__ uint32_t f2h2(float lo, float hi) {
    __half2 h = __floats2half2_rn(lo, hi);
    return *reinterpret_cast<uint32_t*>(&h);
}

__device__ __forceinline__ uint32_t smem_u32(const void* p) {
    uint32_t a;
    asm("{ .reg .u64 t; cvta.to.shared.u64 t, %1; cvt.u32.u64 %0, t; }" : "=r"(a) : "l"(p));
    return a;
}

#define CP16(dst, src) \
    asm volatile("cp.async.cg.shared.global [%0], [%1], 16;" :: "r"(dst), "l"(src) : "memory")
#define CP_COMMIT() asm volatile("cp.async.commit_group;" ::: "memory")
#define CP_WAIT2()  asm volatile("cp.async.wait_group 2;" ::: "memory")

__device__ __forceinline__ void mma16(float c[4], const uint32_t a[4], const uint32_t b[2]) {
    asm volatile(
        "mma.sync.aligned.m16n8k16.row.col.f32.f16.f16.f32 "
        "{%0,%1,%2,%3}, {%4,%5,%6,%7}, {%8,%9}, {%0,%1,%2,%3};\n"
        : "+f"(c[0]), "+f"(c[1]), "+f"(c[2]), "+f"(c[3])
        : "r"(a[0]), "r"(a[1]), "r"(a[2]), "r"(a[3]), "r"(b[0]), "r"(b[1]));
}

__device__ __forceinline__ void ldmx4(uint32_t* r, uint32_t a) {
    asm volatile("ldmatrix.sync.aligned.m8n8.x4.shared.b16 {%0,%1,%2,%3}, [%4];"
                 : "=r"(r[0]), "=r"(r[1]), "=r"(r[2]), "=r"(r[3]) : "r"(a));
}
__device__ __forceinline__ void ldmx4t(uint32_t* r, uint32_t a) {
    asm volatile("ldmatrix.sync.aligned.m8n8.x4.trans.shared.b16 {%0,%1,%2,%3}, [%4];"
                 : "=r"(r[0]), "=r"(r[1]), "=r"(r[2]), "=r"(r[3]) : "r"(a));
}

// ---------------- generic fp16 GEMM (proven round-16 core) ----------------
// AT/BT/EPI semantics as before. Used for compose, MV, out steps.
template<int AT, int BT, int EPI, typename TC>
__global__ void __launch_bounds__(256, 1)
gemm_h(const __half* __restrict__ Ag, const __half* __restrict__ Bg,
       TC* __restrict__ Cg,
       const float* __restrict__ auxM, const float* __restrict__ auxN,
       int M, int N, int K, int lda, int ldb, int ldc,
       long sA, long sB, long sC, long sAuxM)
{
    extern __shared__ __align__(16) __half dsm[];

    const int bz = blockIdx.z;
    const __half* A = Ag + (long)bz * sA;
    const __half* B = Bg + (long)bz * sB;
    TC*           C = Cg + (long)bz * sC;
    const float* axm = auxM + (long)bz * sAuxM;

    const int tid  = threadIdx.x;
    const int lane = tid & 31;
    const int warp = tid >> 5;
    const int g    = lane >> 2;
    const int t    = lane & 3;
    const int wm   = warp & 1;
    const int wn   = warp >> 1;
    const int m0   = blockIdx.y * 128;
    const int n0   = blockIdx.x * 256;

    const uint32_t sb = smem_u32(dsm);
    auto Ast = [&](int s) -> uint32_t { return sb + (uint32_t)(s * (ASZ + BSZ) * 2); };
    auto Bst = [&](int s) -> uint32_t { return Ast(s) + ASZ * 2; };

    float acc[4][8][4];
    #pragma unroll
    for (int i = 0; i < 4; ++i)
        #pragma unroll
        for (int j = 0; j < 8; ++j)
            #pragma unroll
            for (int l = 0; l < 4; ++l) acc[i][j][l] = 0.f;

    auto loadA = [&](int s, int kt) {
        uint32_t d0 = Ast(s);
        int k0 = kt * 32;
        if (AT == 0) {
            #pragma unroll
            for (int i = 0; i < 2; ++i) {
                int id  = tid + 256 * i;
                int row = id >> 2, ch = id & 3;
                CP16(d0 + (uint32_t)(row * 80 + ch * 16),
                     A + (long)(m0 + row) * lda + k0 + ch * 8);
            }
        } else {
            #pragma unroll
            for (int i = 0; i < 2; ++i) {
                int id  = tid + 256 * i;
                int row = id >> 4, col = id & 15;
                CP16(d0 + (uint32_t)(row * 272 + col * 16),
                     A + (long)(k0 + row) * lda + m0 + col * 8);
            }
        }
    };
    auto loadB = [&](int s, int kt) {
        uint32_t d0 = Bst(s);
        int k0 = kt * 32;
        if (BT == 0) {
            #pragma unroll
            for (int i = 0; i < 4; ++i) {
                int id  = tid + 256 * i;
                int row = id >> 2, ch = id & 3;
                CP16(d0 + (uint32_t)(row * 80 + ch * 16),
                     B + (long)(n0 + row) * ldb + k0 + ch * 8);
            }
        } else {
            #pragma unroll
            for (int i = 0; i < 4; ++i) {
                int id  = tid + 256 * i;
                int row = id >> 5, col = id & 31;
                CP16(d0 + (uint32_t)(row * 528 + col * 16),
                     B + (long)(k0 + row) * ldb + n0 + col * 8);
            }
        }
    };

    const uint32_t aK = (uint32_t)((lane & 15) * 80 + (lane >> 4) * 16);
    const uint32_t aM = (uint32_t)(((lane & 7) + (lane >> 4) * 8) * 272
                                   + ((lane >> 3) & 1) * 16);
    const uint32_t bK = (uint32_t)(((lane & 7) + (lane >> 4) * 8) * 80
                                   + ((lane >> 3) & 1) * 16);
    const uint32_t bN = (uint32_t)(((lane & 7) + ((lane >> 3) & 1) * 8) * 528
                                   + (lane >> 4) * 16);

    auto compute = [&](int s) {
        uint32_t sA_ = Ast(s), sB_ = Bst(s);
        #pragma unroll
        for (int ks = 0; ks < 2; ++ks) {
            uint32_t af[4][4];
            uint32_t bf[8][2];
            #pragma unroll
            for (int mt = 0; mt < 4; ++mt) {
                int mr = wm * 64 + mt * 16;
                if (AT == 0) ldmx4(af[mt],  sA_ + (uint32_t)(mr * 80) + aK + (uint32_t)(ks * 32));
                else         ldmx4t(af[mt], sA_ + (uint32_t)(ks * 16 * 272) + aM + (uint32_t)(mr * 2));
            }
            #pragma unroll
            for (int jp = 0; jp < 4; ++jp) {
                int nb = wn * 64 + jp * 16;
                uint32_t r[4];
                if (BT == 0) ldmx4(r,  sB_ + (uint32_t)(nb * 80) + bK + (uint32_t)(ks * 32));
                else         ldmx4t(r, sB_ + (uint32_t)(ks * 16 * 528) + bN + (uint32_t)(nb * 2));
                bf[jp * 2 + 0][0] = r[0]; bf[jp * 2 + 0][1] = r[1];
                bf[jp * 2 + 1][0] = r[2]; bf[jp * 2 + 1][1] = r[3];
            }
            #pragma unroll
            for (int mt = 0; mt < 4; ++mt)
                #pragma unroll
                for (int nt = 0; nt < 8; ++nt)
                    mma16(acc[mt][nt], af[mt], bf[nt]);
        }
    };

    const int KT = K / 32;
    loadA(0, 0); loadB(0, 0); CP_COMMIT();
    loadA(1, 1); loadB(1, 1); CP_COMMIT();
    loadA(2, 2); loadB(2, 2); CP_COMMIT();
    for (int kt = 0; kt < KT; ++kt) {
        CP_WAIT2();
        __syncthreads();
        compute(kt & 3);
        if (kt + 3 < KT) { loadA((kt + 3) & 3, kt + 3); loadB((kt + 3) & 3, kt + 3); }
        CP_COMMIT();
    }

    #pragma unroll
    for (int mt = 0; mt < 4; ++mt) {
        int r0 = m0 + wm * 64 + mt * 16 + g;
        float z0 = 1.f, z1 = 1.f;
        if (EPI == 4) { z0 = 1.f / axm[r0]; z1 = 1.f / axm[r0 + 8]; }
        #pragma unroll
        for (int nt = 0; nt < 8; ++nt) {
            int c = n0 + wn * 64 + nt * 8 + t * 2;
            float v0 = acc[mt][nt][0], v1 = acc[mt][nt][1];
            float v2 = acc[mt][nt][2], v3 = acc[mt][nt][3];
            if (EPI == 1 || EPI == 2) {
                float b0 = auxN[c], b1 = auxN[c + 1];
                v0 += b0; v1 += b1; v2 += b0; v3 += b1;
            }
            if (EPI == 2) {
                v0 = v0 > 0.f ? v0 + 1.f : expf(v0);
                v1 = v1 > 0.f ? v1 + 1.f : expf(v1);
                v2 = v2 > 0.f ? v2 + 1.f : expf(v2);
                v3 = v3 > 0.f ? v3 + 1.f : expf(v3);
            }
            if (EPI == 4) {
                float b0 = auxN[c], b1 = auxN[c + 1];
                v0 = v0 * z0 + b0; v1 = v1 * z0 + b1;
                v2 = v2 * z1 + b0; v3 = v3 * z1 + b1;
            }
            if (sizeof(TC) == 2) {
                *reinterpret_cast<__half2*>((__half*)C + (long)r0 * ldc + c) =
                    __floats2half2_rn(v0, v1);
                *reinterpret_cast<__half2*>((__half*)C + (long)(r0 + 8) * ldc + c) =
                    __floats2half2_rn(v2, v3);
            } else {
                *reinterpret_cast<float2*>((float*)C + (long)r0       * ldc + c) = make_float2(v0, v1);
                *reinterpret_cast<float2*>((float*)C + (long)(r0 + 8) * ldc + c) = make_float2(v2, v3);
            }
        }
    }
}

// ---------------- fused Q/K/Vo projection GEMM ------------------------------
// Grid (12, 256). Section = blockIdx.x>>2: 0->Q(elu,bq) 1->K(elu,bk,+Ksum) 2->Vo(bvo)
// A = g_Xh [M,1024]; B = section weight [1024,1024] K-contig; C -> g_Q/g_Kf/g_Vo.
__global__ void __launch_bounds__(256, 1)
gemm_qkv(const float* __restrict__ bq, const float* __restrict__ bk)
{
    extern __shared__ __align__(16) __half dsm[];

    const int sec = blockIdx.x >> 2;
    const int n0l = (blockIdx.x & 3) * 256;           // column within section
    const __half* A = g_Xh;
    const __half* B = (sec == 0) ? g_Wh
                    : (sec == 1) ? g_Wh + (size_t)D_DIM * D_DIM
                                 : g_Wvo;
    __half* C = (sec == 0) ? g_Q : (sec == 1) ? g_Kf : g_Vo;
    const float* bias = (sec == 0) ? bq : (sec == 1) ? bk : g_bvo;

    const int tid  = threadIdx.x;
    const int lane = tid & 31;
    const int warp = tid >> 5;
    const int g    = lane >> 2;
    const int t    = lane & 3;
    const int wm   = warp & 1;
    const int wn   = warp >> 1;
    const int m0   = blockIdx.y * 128;
    const int bidx = blockIdx.y >> 5;                 // batch (128*32 = 4096 rows)

    const uint32_t sb = smem_u32(dsm);
    auto Ast = [&](int s) -> uint32_t { return sb + (uint32_t)(s * (ASZ + BSZ) * 2); };
    auto Bst = [&](int s) -> uint32_t { return Ast(s) + ASZ * 2; };

    float acc[4][8][4];
    #pragma unroll
    for (int i = 0; i < 4; ++i)
        #pragma unroll
        for (int j = 0; j < 8; ++j)
            #pragma unroll
            for (int l = 0; l < 4; ++l) acc[i][j][l] = 0.f;

    auto loadA = [&](int s, int kt) {
        uint32_t d0 = Ast(s);
        int k0 = kt * 32;
        #pragma unroll
        for (int i = 0; i < 2; ++i) {
            int id  = tid + 256 * i;
            int row = id >> 2, ch = id & 3;
            CP16(d0 + (uint32_t)(row * 80 + ch * 16),
                 A + (long)(m0 + row) * D_DIM + k0 + ch * 8);
        }
    };
    auto loadB = [&](int s, int kt) {
        uint32_t d0 = Bst(s);
        int k0 = kt * 32;
        #pragma unroll
        for (int i = 0; i < 4; ++i) {
            int id  = tid + 256 * i;
            int row = id >> 2, ch = id & 3;
            CP16(d0 + (uint32_t)(row * 80 + ch * 16),
                 B + (long)(n0l + row) * D_DIM + k0 + ch * 8);
        }
    };

    const uint32_t aK = (uint32_t)((lane & 15) * 80 + (lane >> 4) * 16);
    const uint32_t bK = (uint32_t)(((lane & 7) + (lane >> 4) * 8) * 80
                                   + ((lane >> 3) & 1) * 16);

    auto compute = [&](int s) {
        uint32_t sA_ = Ast(s), sB_ = Bst(s);
        #pragma unroll
        for (int ks = 0; ks < 2; ++ks) {
            uint32_t af[4][4];
            uint32_t bf[8][2];
            #pragma unroll
            for (int mt = 0; mt < 4; ++mt)
                ldmx4(af[mt], sA_ + (uint32_t)((wm * 64 + mt * 16) * 80) + aK + (uint32_t)(ks * 32));
            #pragma unroll
            for (int jp = 0; jp < 4; ++jp) {
                uint32_t r[4];
                ldmx4(r, sB_ + (uint32_t)((wn * 64 + jp * 16) * 80) + bK + (uint32_t)(ks * 32));
                bf[jp * 2 + 0][0] = r[0]; bf[jp * 2 + 0][1] = r[1];
                bf[jp * 2 + 1][0] = r[2]; bf[jp * 2 + 1][1] = r[3];
            }
            #pragma unroll
            for (int mt = 0; mt < 4; ++mt)
                #pragma unroll
                for (int nt = 0; nt < 8; ++nt)
                    mma16(acc[mt][nt], af[mt], bf[nt]);
        }
    };

    const int KT = D_DIM / 32;   // 32
    loadA(0, 0); loadB(0, 0); CP_COMMIT();
    loadA(1, 1); loadB(1, 1); CP_COMMIT();
    loadA(2, 2); loadB(2, 2); CP_COMMIT();
    for (int kt = 0; kt < KT; ++kt) {
        CP_WAIT2();
        __syncthreads();
        compute(kt & 3);
        if (kt + 3 < KT) { loadA((kt + 3) & 3, kt + 3); loadB((kt + 3) & 3, kt + 3); }
        CP_COMMIT();
    }

    // epilogue: bias (+elu for sec<2), fp16 store, fused Ksum atomics for sec==1
    float ks[8][2];
    #pragma unroll
    for (int j = 0; j < 8; ++j) { ks[j][0] = 0.f; ks[j][1] = 0.f; }

    #pragma unroll
    for (int mt = 0; mt < 4; ++mt) {
        int r0 = m0 + wm * 64 + mt * 16 + g;
        #pragma unroll
        for (int nt = 0; nt < 8; ++nt) {
            int cl = n0l + wn * 64 + nt * 8 + t * 2;
            float b0 = bias[cl], b1 = bias[cl + 1];
            float v0 = acc[mt][nt][0] + b0, v1 = acc[mt][nt][1] + b1;
            float v2 = acc[mt][nt][2] + b0, v3 = acc[mt][nt][3] + b1;
            if (sec < 2) {   // elu(x)+1
                v0 = v0 > 0.f ? v0 + 1.f : expf(v0);
                v1 = v1 > 0.f ? v1 + 1.f : expf(v1);
                v2 = v2 > 0.f ? v2 + 1.f : expf(v2);
                v3 = v3 > 0.f ? v3 + 1.f : expf(v3);
            }
            if (sec == 1) {
                ks[nt][0] += v0 + v2;
                ks[nt][1] += v1 + v3;
            }
            *reinterpret_cast<__half2*>(C + (long)r0 * D_DIM + cl) =
                __floats2half2_rn(v0, v1);
            *reinterpret_cast<__half2*>(C + (long)(r0 + 8) * D_DIM + cl) =
                __floats2half2_rn(v2, v3);
        }
    }
    if (sec == 1) {
        #pragma unroll
        for (int nt = 0; nt < 8; ++nt) {
            #pragma unroll
            for (int p = 0; p < 2; ++p) {
                float s = ks[nt][p];
                s += __shfl_xor_sync(0xFFFFFFFFu, s, 4);
                s += __shfl_xor_sync(0xFFFFFFFFu, s, 8);
                s += __shfl_xor_sync(0xFFFFFFFFu, s, 16);
                if (g == 0) {
                    int cl = n0l + wn * 64 + nt * 8 + t * 2 + p;
                    atomicAdd(&g_Ksum[bidx * D_DIM + cl], s);
                }
            }
        }
    }
}

// ---------------- batched f32 -> f16 convert --------------------------------
// blocks [0, 32768): x -> Xh ; [32768, 36864): weights -> Wh slots
__global__ void f2h_all(const float* __restrict__ x,
                        const float* __restrict__ Wq, const float* __restrict__ Wk,
                        const float* __restrict__ Wv, const float* __restrict__ Wo)
{
    const float* src;
    __half* dst;
    long off;
    int b = blockIdx.x;
    if (b < M_FLAT) {
        src = x; dst = g_Xh; off = (long)b * D_DIM;
    } else {
        int w = (b - M_FLAT) >> 10;
        int r = (b - M_FLAT) & 1023;
        src = (w == 0) ? Wq : (w == 1) ? Wk : (w == 2) ? Wv : Wo;
        dst = g_Wh + (size_t)w * D_DIM * D_DIM;
        off = (long)r * D_DIM;
    }
    long i = off + threadIdx.x * 4;
    float4 v = *reinterpret_cast<const float4*>(src + i);
    *reinterpret_cast<uint2*>(dst + i) = make_uint2(f2h2(v.x, v.y), f2h2(v.z, v.w));
}

// ---------------- bvo[f] = sum_e bv[e] * Wo[f,e] ----------------------------
__global__ void bvo_kernel(const float* __restrict__ bv, const float* __restrict__ Wo) {
    int f = blockIdx.x * 8 + (threadIdx.x >> 5);
    int lane = threadIdx.x & 31;
    const float* w = Wo + (long)f * D_DIM;
    float s = 0.f;
    #pragma unroll
    for (int i = 0; i < 8; ++i) {
        int e = (lane + i * 32) * 4;
        float4 a = *reinterpret_cast<const float4*>(bv + e);
        float4 b = *reinterpret_cast<const float4*>(w + e);
        s += a.x * b.x + a.y * b.y + a.z * b.z + a.w * b.w;
    }
    #pragma unroll
    for (int o = 16; o > 0; o >>= 1) s += __shfl_xor_sync(0xFFFFFFFFu, s, o);
    if (lane == 0) g_bvo[f] = s;
}

// ---------------- Ksum init (+1e-6) ----------------
__global__ void ksum_init() {
    int i = blockIdx.x * 256 + threadIdx.x;
    g_Ksum[i] = 1e-6f;
}

// ---------------- Z[b,n] = Q[b,n,:] . Ksum[b,:] ----------------
__device__ __forceinline__ void h8f(const uint4& u, float* f) {
    const __half2* h = reinterpret_cast<const __half2*>(&u);
    #pragma unroll
    for (int i = 0; i < 4; ++i) {
        float2 t = __half22float2(h[i]);
        f[2 * i] = t.x; f[2 * i + 1] = t.y;
    }
}

__global__ void z_kernel() {
    int warp = threadIdx.x >> 5;
    int lane = threadIdx.x & 31;
    long row = (long)blockIdx.x * 8 + warp;
    int b = (int)(row >> 12);
    const __half* q  = g_Q + row * D_DIM;
    const float*  ks = g_Ksum + b * D_DIM;
    float s = 0.f;
    #pragma unroll
    for (int i = 0; i < 4; ++i) {
        int d = (lane + i * 32) * 8;
        uint4 u = *reinterpret_cast<const uint4*>(q + d);
        float f[8]; h8f(u, f);
        float4 k0 = *reinterpret_cast<const float4*>(&ks[d]);
        float4 k1 = *reinterpret_cast<const float4*>(&ks[d + 4]);
        s += f[0] * k0.x + f[1] * k0.y + f[2] * k0.z + f[3] * k0.w
           + f[4] * k1.x + f[5] * k1.y + f[6] * k1.z + f[7] * k1.w;
    }
    #pragma unroll
    for (int o = 16; o > 0; o >>= 1) s += __shfl_xor_sync(0xFFFFFFFFu, s, o);
    if (lane == 0) g_Z[row] = s;
}

// ---------------- launch ----------------
extern "C" void kernel_launch(void* const* d_in, const int* in_sizes, int n_in,
                              void* d_out, int out_size)
{
    const float* x  = (const float*)d_in[0];
    const float* Wq = (const float*)d_in[1];
    const float* bq = (const float*)d_in[2];
    const float* Wk = (const float*)d_in[3];
    const float* bk = (const float*)d_in[4];
    const float* Wv = (const float*)d_in[5];
    const float* bv = (const float*)d_in[6];
    const float* Wo = (const float*)d_in[7];
    const float* bo = (const float*)d_in[8];
    float* out = (float*)d_out;

    __half *pWh, *pWvo, *pQ, *pK, *pVo, *pMV;
    float *pZ;
    cudaGetSymbolAddress((void**)&pWh,  g_Wh);
    cudaGetSymbolAddress((void**)&pWvo, g_Wvo);
    cudaGetSymbolAddress((void**)&pQ,   g_Q);
    cudaGetSymbolAddress((void**)&pK,   g_Kf);
    cudaGetSymbolAddress((void**)&pVo,  g_Vo);
    cudaGetSymbolAddress((void**)&pMV,  g_MV);
    cudaGetSymbolAddress((void**)&pZ,   g_Z);

    __half* pWoh = pWh + (size_t)3 * D_DIM * D_DIM;
    __half* pWvh = pWh + (size_t)2 * D_DIM * D_DIM;

    static bool attr_done = false;
    if (!attr_done) {
        cudaFuncSetAttribute(gemm_h<0,1,0,__half>, cudaFuncAttributeMaxDynamicSharedMemorySize, SMEM_BYTES);
        cudaFuncSetAttribute(gemm_h<1,1,0,__half>, cudaFuncAttributeMaxDynamicSharedMemorySize, SMEM_BYTES);
        cudaFuncSetAttribute(gemm_h<0,1,4,float >, cudaFuncAttributeMaxDynamicSharedMemorySize, SMEM_BYTES);
        cudaFuncSetAttribute(gemm_qkv, cudaFuncAttributeMaxDynamicSharedMemorySize, SMEM_BYTES);
        attr_done = true;
    }

    dim3 blk(256);

    // 0) fp16 conversions (one launch), bvo, ksum init
    f2h_all<<<M_FLAT + 4 * D_DIM, 256>>>(x, Wq, Wk, Wv, Wo);
    bvo_kernel<<<D_DIM / 8, 256>>>(bv, Wo);
    ksum_init<<<(N_BATCH * D_DIM) / 256, 256>>>();

    // 0b) compose Wvo[f,k] = sum_e Wo[f,e] * Wv[e,k]
    gemm_h<0,1,0,__half><<<dim3(D_DIM / 256, D_DIM / 128, 1), blk, SMEM_BYTES>>>(
        pWoh, pWvh, pWvo, pZ, pZ,
        D_DIM, D_DIM, D_DIM, D_DIM, D_DIM, D_DIM, 0, 0, 0, 0);

    // 1) fused Q/K/Vo projections (+ Ksum atomics from K section)
    gemm_qkv<<<dim3(12, M_FLAT / 128, 1), blk, SMEM_BYTES>>>(bq, bk);

    // 2) Z
    z_kernel<<<M_FLAT / 8, 256>>>();

    // 3) MV[b][d,f] = sum_n K[b][n,d] * Vo[b][n,f]
    gemm_h<1,1,0,__half><<<dim3(D_DIM / 256, D_DIM / 128, N_BATCH), blk, SMEM_BYTES>>>(
        pK, pVo, pMV, pZ, pZ,
        D_DIM, D_DIM, N_SEQ, D_DIM, D_DIM, D_DIM,
        (long)N_SEQ * D_DIM, (long)N_SEQ * D_DIM, (long)D_DIM * D_DIM, 0);

    // 4) out[b][n,f] = (sum_d Q[b][n,d] * MV[b][d,f]) / Z[b,n] + bo[f]
    gemm_h<0,1,4,float><<<dim3(D_DIM / 256, N_SEQ / 128, N_BATCH), blk, SMEM_BYTES>>>(
        pQ, pMV, out, pZ, bo,
        N_SEQ, D_DIM, D_DIM, D_DIM, D_DIM, D_DIM,
        (long)N_SEQ * D_DIM, (long)D_DIM * D_DIM, (long)N_SEQ * D_DIM, N_SEQ);
}